// round 10
// baseline (speedup 1.0000x reference)
#include <cuda_runtime.h>
#include <math.h>
#include <stdint.h>

__device__ float g_L [2u*4096u*1024u];
__device__ float g_G [2u*4096u*1024u];
__device__ float g_BC[2u*4096u*1024u];
__device__ float g_M [2u*4096u*1024u];
__device__ float g_COMP[2u*64u*1024u];
__device__ float g_W1[2048u*1024u];   // mix_w, tf32-RN
__device__ float g_W2[1024u*1024u];   // out_w, tf32-RN
__device__ float g_XC[128u*4096u];    // gathered conv input
__device__ float g_CP[4u*128u*1024u]; // conv split-K partials

__device__ __forceinline__ float f2tff(float x) {
    uint32_t u; asm("cvt.rn.tf32.f32 %0, %1;" : "=r"(u) : "f"(x));
    return __uint_as_float(u);
}
__device__ __forceinline__ void mma8(float* c, const uint32_t* a, const uint32_t* b) {
    asm volatile("mma.sync.aligned.m16n8k8.row.col.f32.tf32.tf32.f32 "
        "{%0,%1,%2,%3}, {%4,%5,%6,%7}, {%8,%9}, {%0,%1,%2,%3};"
        : "+f"(c[0]), "+f"(c[1]), "+f"(c[2]), "+f"(c[3])
        : "r"(a[0]), "r"(a[1]), "r"(a[2]), "r"(a[3]), "r"(b[0]), "r"(b[1]));
}
__device__ __forceinline__ uint32_t smem_u32(const void* p) {
    uint32_t a;
    asm("{ .reg .u64 t; cvta.to.shared.u64 t, %1; cvt.u32.u64 %0, t; }" : "=r"(a) : "l"(p));
    return a;
}
#define CP16(dst, src) asm volatile("cp.async.cg.shared.global [%0], [%1], 16;" :: "r"(dst), "l"(src))
#define CPCOMMIT()     asm volatile("cp.async.commit_group;" ::: "memory")
#define CPWAIT1()      asm volatile("cp.async.wait_group 1;" ::: "memory")

__device__ __forceinline__ float invden(int s) {
    int n1 = s >> 8, i1 = s & 255;
    float d = 0.f;
    if (n1 <= 14) d += 0.5f + (float)i1 * (1.0f / 511.0f);
    if (n1 >= 1)  d += 0.5f + (float)(i1 + 256) * (1.0f / 511.0f);
    return 1.0f / d;
}

// ============ 0) weight tf32-RN pre-rounding ============
__global__ void wround(const float* __restrict__ W, float* __restrict__ WR) {
    size_t i = ((size_t)blockIdx.x * blockDim.x + threadIdx.x) << 2;
    float4 v = *(const float4*)(W + i);
    v.x = f2tff(v.x); v.y = f2tff(v.y); v.z = f2tff(v.z); v.w = f2tff(v.w);
    *(float4*)(WR + i) = v;
}

// ============ 1) broadcast diffusion (conflict-free planes) ============
__global__ void bc_kernel(const float* __restrict__ x, float* __restrict__ bc) {
    extern __shared__ float sm[];
    const int tid = threadIdx.x, b = blockIdx.y, d0 = blockIdx.x << 2;
    float* bufA = sm; float* bufB = sm + 16384;
    const float* src = x + (size_t)b * 4194304u + d0;
    for (int s = tid; s < 4096; s += 512) {
        float4 v = *(const float4*)(src + (size_t)s * 1024u);
        bufA[s] = v.x; bufA[4096 + s] = v.y; bufA[8192 + s] = v.z; bufA[12288 + s] = v.w;
    }
    __syncthreads();
    float acc[32];
#pragma unroll
    for (int e = 0; e < 32; ++e) acc[e] = 0.f;
    float* cur = bufA; float* nxt = bufB;
    for (int st = 1; st < 4096; st <<= 1) {
#pragma unroll
        for (int q = 0; q < 8; ++q) {
            int s = tid + (q << 9);
            int sm1 = (s - st) & 4095, sp1 = (s + st) & 4095;
#pragma unroll
            for (int j = 0; j < 4; ++j) {
                const float* cj = cur + (j << 12);
                float v = cj[s] + 0.5f * (cj[sm1] + cj[sp1]);
                nxt[(j << 12) + s] = v;
                acc[(q << 2) + j] += v;
            }
        }
        __syncthreads();
        float* t = cur; cur = nxt; nxt = t;
    }
    const float inv = 1.0f / 13.0f;
    float* dst = bc + (size_t)b * 4194304u + d0;
#pragma unroll
    for (int q = 0; q < 8; ++q) {
        int s = tid + (q << 9);
        *(float4*)(dst + (size_t)s * 1024u) =
            make_float4(acc[q*4]*inv, acc[q*4+1]*inv, acc[q*4+2]*inv, acc[q*4+3]*inv);
    }
}

// ============ 2a) conv input gather ============
__global__ void xc_kernel(const float* __restrict__ x, float* __restrict__ Xc) {
    const int s = blockIdx.x;
    const int b = blockIdx.y;
    const int t = s >> 2, j = s & 3;
    const int m = (b << 6) + t;
    const float* src = x + (size_t)b * 4194304u + (size_t)s * 1024u;
    float* dst = Xc + (size_t)m * 4096u + j;
#pragma unroll
    for (int k = 0; k < 4; ++k) {
        int d = threadIdx.x + (k << 8);
        dst[d << 2] = src[d];
    }
}

// ============ 2b) conv GEMM (split-K x4) ============
__global__ void __launch_bounds__(256) conv_gemm(
        const float* __restrict__ Xc, const float* __restrict__ cwf,
        float* __restrict__ CP) {
    extern __shared__ float gsm[];
    const int tid = threadIdx.x;
    const int n0 = blockIdx.x << 7;
    const int kq = blockIdx.y;
    const int kbase = kq << 10;
    const int wid = tid >> 5, lane = tid & 31;
    const int quad = lane >> 2, tq = lane & 3;
    const int wm = wid >> 2, wn = wid & 3;
    const int am = tid >> 1, ak = (tid & 1) << 4;
    const uint32_t sbase = smem_u32(gsm);

    auto issue = [&](int kt, int slot) {
        uint32_t aoff = sbase + (uint32_t)(slot * 9216 + am * 36 + ak) * 4u;
        const float* asrc = Xc + (size_t)am * 4096u + kbase + kt + ak;
        CP16(aoff, asrc); CP16(aoff + 16, asrc + 4);
        CP16(aoff + 32, asrc + 8); CP16(aoff + 48, asrc + 12);
        uint32_t boff = aoff + 4608u * 4u;
        const float* bsrc = cwf + (size_t)(n0 + am) * 4096u + kbase + kt + ak;
        CP16(boff, bsrc); CP16(boff + 16, bsrc + 4);
        CP16(boff + 32, bsrc + 8); CP16(boff + 48, bsrc + 12);
        CPCOMMIT();
    };

    float acc[4][4][4];
#pragma unroll
    for (int i = 0; i < 4; ++i)
#pragma unroll
        for (int j = 0; j < 4; ++j)
#pragma unroll
            for (int e = 0; e < 4; ++e) acc[i][j][e] = 0.f;

    issue(0, 0);
    issue(32, 1);

    for (int kt = 0; kt < 1024; kt += 32) {
        CPWAIT1();
        __syncthreads();
        int nk = kt + 64;
        if (nk < 1024) issue(nk, ((kt >> 5) + 2) % 3);
        else           CPCOMMIT();

        const float* Asb = gsm + ((kt >> 5) % 3) * 9216;
        const float* Bsb = Asb + 4608;
#pragma unroll
        for (int ks = 0; ks < 4; ++ks) {
            const int k0 = ks << 3;
            uint32_t af[4][4], bf[4][2];
#pragma unroll
            for (int i = 0; i < 4; ++i) {
                int r = (wm << 6) + (i << 4) + quad;
                af[i][0] = __float_as_uint(Asb[r * 36 + k0 + tq]);
                af[i][1] = __float_as_uint(Asb[(r + 8) * 36 + k0 + tq]);
                af[i][2] = __float_as_uint(Asb[r * 36 + k0 + tq + 4]);
                af[i][3] = __float_as_uint(Asb[(r + 8) * 36 + k0 + tq + 4]);
            }
#pragma unroll
            for (int j = 0; j < 4; ++j) {
                int cidx = (wn << 5) + (j << 3) + quad;
                bf[j][0] = __float_as_uint(Bsb[cidx * 36 + k0 + tq]);
                bf[j][1] = __float_as_uint(Bsb[cidx * 36 + k0 + tq + 4]);
            }
#pragma unroll
            for (int i = 0; i < 4; ++i)
#pragma unroll
                for (int j = 0; j < 4; ++j) mma8(acc[i][j], af[i], bf[j]);
        }
    }
    float* cp = CP + (size_t)kq * 131072u;
#pragma unroll
    for (int i = 0; i < 4; ++i)
#pragma unroll
        for (int j = 0; j < 4; ++j) {
            int mr = (wm << 6) + (i << 4) + quad;
            int nc = n0 + (wn << 5) + (j << 3) + (tq << 1);
#pragma unroll
            for (int hf = 0; hf < 2; ++hf) {
                int m = mr + (hf << 3);
                *(float2*)(cp + (size_t)m * 1024u + nc) =
                    make_float2(acc[i][j][(hf << 1)], acc[i][j][(hf << 1) + 1]);
            }
        }
}

// ============ 2c) conv reduce ============
__global__ void conv_reduce(const float* __restrict__ CP, const float* __restrict__ cb,
                            float* __restrict__ comp) {
    int i = (blockIdx.x << 8) + threadIdx.x;
    int o4 = (i & 255) << 2;
    float4 a = *(const float4*)(CP + ((size_t)i << 2));
    float4 b = *(const float4*)(CP + 131072u + ((size_t)i << 2));
    float4 c = *(const float4*)(CP + 262144u + ((size_t)i << 2));
    float4 d = *(const float4*)(CP + 393216u + ((size_t)i << 2));
    float4 e = *(const float4*)(cb + o4);
    *(float4*)(comp + ((size_t)i << 2)) = make_float4(
        a.x + b.x + c.x + d.x + e.x, a.y + b.y + c.y + d.y + e.y,
        a.z + b.z + c.z + d.z + e.z, a.w + b.w + c.w + d.w + e.w);
}

// ============ 3) sliding-window attention (TC, fused normalization) ============
__global__ void __launch_bounds__(256) win_attn(
        const float* __restrict__ x, float* __restrict__ L, int parity) {
    extern __shared__ float sm[];
    float* Qs = sm;
    float* Ks = sm + 8448;
    float* Ss = sm + 16896;
    float* Al = sm + 21248;
    const int tid = threadIdx.x;
    const int lane = tid & 31, wid = tid >> 5;
    const int g = lane >> 2, tq = lane & 3;
    const int qt = blockIdx.x;
    const int n = (blockIdx.y << 1) + parity;
    const int b = blockIdx.z >> 3, h = blockIdx.z & 7;
    const int base = n << 8, q0 = base + (qt << 6);
    const float* xb = x + (size_t)b * 4194304u + (h << 7);

#pragma unroll
    for (int it = 0; it < 8; ++it) {
        int i = tid + (it << 8);
        int r = i >> 5, c4 = (i & 31) << 2;
        float4 v = *(const float4*)(xb + (size_t)(q0 + r) * 1024u + c4);
        float* q = &Qs[r * 132 + c4];
        q[0] = f2tff(v.x); q[1] = f2tff(v.y); q[2] = f2tff(v.z); q[3] = f2tff(v.w);
    }

    const int wm = wid >> 1, wn = wid & 1;
    const int m0 = wm << 4;
    const int sn0 = wn << 5;
    const int on0 = wn << 6;
    const int srow = tid >> 2, seg = tid & 3;
    const float scale = 0.08838834764831845f;

    float oacc[8][4];
#pragma unroll
    for (int nt = 0; nt < 8; ++nt)
#pragma unroll
        for (int e = 0; e < 4; ++e) oacc[nt][e] = 0.f;
    float m_i = -1e30f, l_i = 0.f;

    for (int kt = 0; kt < 8; ++kt) {
        __syncthreads();
        const int ktok = base + (kt << 6);
#pragma unroll
        for (int it = 0; it < 8; ++it) {
            int i = tid + (it << 8);
            int r = i >> 5, c4 = (i & 31) << 2;
            float4 v = *(const float4*)(xb + (size_t)(ktok + r) * 1024u + c4);
            float* k = &Ks[r * 132 + c4];
            k[0] = f2tff(v.x); k[1] = f2tff(v.y); k[2] = f2tff(v.z); k[3] = f2tff(v.w);
        }
        __syncthreads();

        float sacc[4][4];
#pragma unroll
        for (int nt = 0; nt < 4; ++nt)
#pragma unroll
            for (int e = 0; e < 4; ++e) sacc[nt][e] = 0.f;
#pragma unroll
        for (int kd = 0; kd < 128; kd += 8) {
            uint32_t a[4];
            a[0] = __float_as_uint(Qs[(m0 + g) * 132 + kd + tq]);
            a[1] = __float_as_uint(Qs[(m0 + g + 8) * 132 + kd + tq]);
            a[2] = __float_as_uint(Qs[(m0 + g) * 132 + kd + tq + 4]);
            a[3] = __float_as_uint(Qs[(m0 + g + 8) * 132 + kd + tq + 4]);
#pragma unroll
            for (int nt = 0; nt < 4; ++nt) {
                int tcol = sn0 + (nt << 3) + g;
                uint32_t bb[2];
                bb[0] = __float_as_uint(Ks[tcol * 132 + kd + tq]);
                bb[1] = __float_as_uint(Ks[tcol * 132 + kd + tq + 4]);
                mma8(sacc[nt], a, bb);
            }
        }
#pragma unroll
        for (int nt = 0; nt < 4; ++nt) {
            int nc = sn0 + (nt << 3) + (tq << 1);
            *(float2*)&Ss[(m0 + g) * 68 + nc] =
                make_float2(sacc[nt][0] * scale, sacc[nt][1] * scale);
            *(float2*)&Ss[(m0 + g + 8) * 68 + nc] =
                make_float2(sacc[nt][2] * scale, sacc[nt][3] * scale);
        }
        __syncthreads();

        {
            float* sr = &Ss[srow * 68 + (seg << 4)];
            float mt = -1e30f;
#pragma unroll
            for (int jj = 0; jj < 16; ++jj) mt = fmaxf(mt, sr[jj]);
            mt = fmaxf(mt, __shfl_xor_sync(0xffffffffu, mt, 1));
            mt = fmaxf(mt, __shfl_xor_sync(0xffffffffu, mt, 2));
            float m_new = fmaxf(m_i, mt);
            float alpha = __expf(m_i - m_new);
            float ls = 0.f;
#pragma unroll
            for (int jj = 0; jj < 16; ++jj) {
                float p = __expf(sr[jj] - m_new);
                ls += p;
                sr[jj] = f2tff(p);
            }
            ls += __shfl_xor_sync(0xffffffffu, ls, 1);
            ls += __shfl_xor_sync(0xffffffffu, ls, 2);
            l_i = l_i * alpha + ls;
            m_i = m_new;
            if (seg == 0) Al[srow] = alpha;
        }
        __syncthreads();

        float aLo = Al[m0 + g], aHi = Al[m0 + g + 8];
#pragma unroll
        for (int nt = 0; nt < 8; ++nt) {
            oacc[nt][0] *= aLo; oacc[nt][1] *= aLo;
            oacc[nt][2] *= aHi; oacc[nt][3] *= aHi;
        }
#pragma unroll
        for (int kd = 0; kd < 64; kd += 8) {
            uint32_t a[4];
            a[0] = __float_as_uint(Ss[(m0 + g) * 68 + kd + tq]);
            a[1] = __float_as_uint(Ss[(m0 + g + 8) * 68 + kd + tq]);
            a[2] = __float_as_uint(Ss[(m0 + g) * 68 + kd + tq + 4]);
            a[3] = __float_as_uint(Ss[(m0 + g + 8) * 68 + kd + tq + 4]);
#pragma unroll
            for (int nt = 0; nt < 8; ++nt) {
                int dcol = on0 + (nt << 3) + g;
                uint32_t bb[2];
                bb[0] = __float_as_uint(Ks[(kd + tq) * 132 + dcol]);
                bb[1] = __float_as_uint(Ks[(kd + tq + 4) * 132 + dcol]);
                mma8(oacc[nt], a, bb);
            }
        }
    }
    __syncthreads();
    if (seg == 0) Al[srow] = 1.0f / l_i;
    __syncthreads();

    const int iwLo = (qt << 6) + m0 + g;
    const int iwHi = iwLo + 8;
    const int sLo = base + iwLo, sHi = base + iwHi;
    const float triLo = 0.5f + (float)iwLo * (1.0f / 511.0f);
    const float triHi = 0.5f + (float)iwHi * (1.0f / 511.0f);
    float* dLo = L + ((size_t)b * 4096u + sLo) * 1024u + (h << 7);
    float* dHi = dLo + (size_t)8 * 1024u;
    if (parity == 0) {
        const bool snLo = (sLo < 256) || (sLo >= 3840);
        const bool snHi = (sHi < 256) || (sHi >= 3840);
        const float twLo = (snLo ? 1.0f : triLo) * Al[m0 + g];
        const float twHi = (snHi ? 1.0f : triHi) * Al[m0 + g + 8];
#pragma unroll
        for (int nt = 0; nt < 8; ++nt) {
            int dc = on0 + (nt << 3) + (tq << 1);
            *(float2*)(dLo + dc) = make_float2(oacc[nt][0] * twLo, oacc[nt][1] * twLo);
            *(float2*)(dHi + dc) = make_float2(oacc[nt][2] * twHi, oacc[nt][3] * twHi);
        }
    } else {
        const float twLo = triLo * Al[m0 + g];
        const float twHi = triHi * Al[m0 + g + 8];
        const float ivLo = invden(sLo), ivHi = invden(sHi);
#pragma unroll
        for (int nt = 0; nt < 8; ++nt) {
            int dc = on0 + (nt << 3) + (tq << 1);
            float2 o = *(float2*)(dLo + dc);
            o.x = (o.x + oacc[nt][0] * twLo) * ivLo;
            o.y = (o.y + oacc[nt][1] * twLo) * ivLo;
            *(float2*)(dLo + dc) = o;
            float2 p = *(float2*)(dHi + dc);
            p.x = (p.x + oacc[nt][2] * twHi) * ivHi;
            p.y = (p.y + oacc[nt][3] * twHi) * ivHi;
            *(float2*)(dHi + dc) = p;
        }
    }
}

// ============ 4) compressed-global attention (TC) ============
__global__ void __launch_bounds__(256) gattn(
        const float* __restrict__ x, const float* __restrict__ gmem,
        const float* __restrict__ comp, float* __restrict__ G) {
    extern __shared__ float sm[];
    float* KVs = sm;
    float* Qs  = sm + 16896;
    float* Ps  = sm + 21120;
    const int tid = threadIdx.x;
    const int lane = tid & 31, wid = tid >> 5;
    const int g = lane >> 2, tq = lane & 3;
    const int s0 = blockIdx.x << 5, h = blockIdx.y, b = blockIdx.z;

#pragma unroll
    for (int it = 0; it < 16; ++it) {
        int i = tid + (it << 8);
        int r = i >> 5, c4 = (i & 31) << 2;
        float4 v;
        if (r < 64) v = *(const float4*)(comp + (size_t)((b << 6) + r) * 1024u + (h << 7) + c4);
        else        v = *(const float4*)(gmem + (size_t)((h << 6) + (r - 64)) * 128u + c4);
        float* kv = &KVs[r * 132 + c4];
        kv[0] = f2tff(v.x); kv[1] = f2tff(v.y); kv[2] = f2tff(v.z); kv[3] = f2tff(v.w);
    }
#pragma unroll
    for (int it = 0; it < 4; ++it) {
        int i = tid + (it << 8);
        int r = i >> 5, c4 = (i & 31) << 2;
        float4 v = *(const float4*)(x + (size_t)b * 4194304u + (size_t)(s0 + r) * 1024u + (h << 7) + c4);
        float* q = &Qs[r * 132 + c4];
        q[0] = f2tff(v.x); q[1] = f2tff(v.y); q[2] = f2tff(v.z); q[3] = f2tff(v.w);
    }
    __syncthreads();

    const int wm = wid & 1, wn = wid >> 1;
    const int m0 = wm << 4;
    const int tn0 = wn << 5;
    const float scale = 0.08838834764831845f;

    {
        float sacc[4][4];
#pragma unroll
        for (int nt = 0; nt < 4; ++nt)
#pragma unroll
            for (int e = 0; e < 4; ++e) sacc[nt][e] = 0.f;
#pragma unroll
        for (int kd = 0; kd < 128; kd += 8) {
            uint32_t a[4];
            a[0] = __float_as_uint(Qs[(m0 + g) * 132 + kd + tq]);
            a[1] = __float_as_uint(Qs[(m0 + g + 8) * 132 + kd + tq]);
            a[2] = __float_as_uint(Qs[(m0 + g) * 132 + kd + tq + 4]);
            a[3] = __float_as_uint(Qs[(m0 + g + 8) * 132 + kd + tq + 4]);
#pragma unroll
            for (int nt = 0; nt < 4; ++nt) {
                int tcol = tn0 + (nt << 3) + g;
                uint32_t bb[2];
                bb[0] = __float_as_uint(KVs[tcol * 132 + kd + tq]);
                bb[1] = __float_as_uint(KVs[tcol * 132 + kd + tq + 4]);
                mma8(sacc[nt], a, bb);
            }
        }
#pragma unroll
        for (int nt = 0; nt < 4; ++nt) {
            int nc = tn0 + (nt << 3) + (tq << 1);
            *(float2*)&Ps[(m0 + g) * 132 + nc] =
                make_float2(sacc[nt][0] * scale, sacc[nt][1] * scale);
            *(float2*)&Ps[(m0 + g + 8) * 132 + nc] =
                make_float2(sacc[nt][2] * scale, sacc[nt][3] * scale);
        }
    }
    __syncthreads();

    {
        int row = tid >> 3, seg8 = tid & 7;
        float* pr = &Ps[row * 132 + (seg8 << 4)];
        float mt = -1e30f;
        float pv[16];
#pragma unroll
        for (int jj = 0; jj < 16; ++jj) mt = fmaxf(mt, pr[jj]);
        mt = fmaxf(mt, __shfl_xor_sync(0xffffffffu, mt, 1));
        mt = fmaxf(mt, __shfl_xor_sync(0xffffffffu, mt, 2));
        mt = fmaxf(mt, __shfl_xor_sync(0xffffffffu, mt, 4));
        float ssum = 0.f;
#pragma unroll
        for (int jj = 0; jj < 16; ++jj) { pv[jj] = __expf(pr[jj] - mt); ssum += pv[jj]; }
        ssum += __shfl_xor_sync(0xffffffffu, ssum, 1);
        ssum += __shfl_xor_sync(0xffffffffu, ssum, 2);
        ssum += __shfl_xor_sync(0xffffffffu, ssum, 4);
        float invs = 1.0f / ssum;
#pragma unroll
        for (int jj = 0; jj < 16; ++jj) pr[jj] = f2tff(pv[jj] * invs);
    }
    __syncthreads();

    {
        float oacc[4][4];
#pragma unroll
        for (int nt = 0; nt < 4; ++nt)
#pragma unroll
            for (int e = 0; e < 4; ++e) oacc[nt][e] = 0.f;
#pragma unroll
        for (int kd = 0; kd < 128; kd += 8) {
            uint32_t a[4];
            a[0] = __float_as_uint(Ps[(m0 + g) * 132 + kd + tq]);
            a[1] = __float_as_uint(Ps[(m0 + g + 8) * 132 + kd + tq]);
            a[2] = __float_as_uint(Ps[(m0 + g) * 132 + kd + tq + 4]);
            a[3] = __float_as_uint(Ps[(m0 + g + 8) * 132 + kd + tq + 4]);
#pragma unroll
            for (int nt = 0; nt < 4; ++nt) {
                int dcol = tn0 + (nt << 3) + g;
                uint32_t bb[2];
                bb[0] = __float_as_uint(KVs[(kd + tq) * 132 + dcol]);
                bb[1] = __float_as_uint(KVs[(kd + tq + 4) * 132 + dcol]);
                mma8(oacc[nt], a, bb);
            }
        }
        float* gLo = G + ((size_t)b * 4096u + s0 + m0 + g) * 1024u + (h << 7);
        float* gHi = gLo + (size_t)8 * 1024u;
#pragma unroll
        for (int nt = 0; nt < 4; ++nt) {
            int nc = tn0 + (nt << 3) + (tq << 1);
            *(float2*)(gLo + nc) = make_float2(oacc[nt][0], oacc[nt][1]);
            *(float2*)(gHi + nc) = make_float2(oacc[nt][2], oacc[nt][3]);
        }
    }
}

// ============ 5+6) cp.async-pipelined tf32 GEMM (mma.sync) ============
__global__ void __launch_bounds__(256) gemm_tc(
        int mode, const float* __restrict__ A0, const float* __restrict__ A1,
        const float* __restrict__ BCp, const float* __restrict__ W,
        const float* __restrict__ bias, float* __restrict__ C, int K) {
    extern __shared__ float gsm[];
    const int tid = threadIdx.x;
    const int m0 = blockIdx.x << 7, n0 = blockIdx.y << 7;
    const int wid = tid >> 5, lane = tid & 31;
    const int quad = lane >> 2, tq = lane & 3;
    const int wm = wid >> 2, wn = wid & 3;
    const int am = tid >> 1, ak = (tid & 1) << 4;
    const int bk = tid >> 3, bn = (tid & 7) << 4;
    const uint32_t sbase = smem_u32(gsm);

    auto issue = [&](int kt, int slot) {
        uint32_t aoff = sbase + (uint32_t)(slot * 8960 + am * 36 + ak) * 4u;
        const float* asrc = (mode == 1 && kt >= 1024)
            ? (A1 + (size_t)(m0 + am) * 1024u + (kt - 1024) + ak)
            : (A0 + (size_t)(m0 + am) * 1024u + kt + ak);
        CP16(aoff, asrc); CP16(aoff + 16, asrc + 4);
        CP16(aoff + 32, asrc + 8); CP16(aoff + 48, asrc + 12);
        uint32_t boff = sbase + (uint32_t)(slot * 8960 + 4608 + bk * 136 + bn) * 4u;
        const float* bsrc = W + (size_t)(kt + bk) * 1024u + n0 + bn;
        CP16(boff, bsrc); CP16(boff + 16, bsrc + 4);
        CP16(boff + 32, bsrc + 8); CP16(boff + 48, bsrc + 12);
        CPCOMMIT();
    };

    float acc[4][4][4];
#pragma unroll
    for (int i = 0; i < 4; ++i)
#pragma unroll
        for (int j = 0; j < 4; ++j)
#pragma unroll
            for (int e = 0; e < 4; ++e) acc[i][j][e] = 0.f;

    issue(0, 0);
    issue(32, 1);

    for (int kt = 0; kt < K; kt += 32) {
        CPWAIT1();
        __syncthreads();
        int nk = kt + 64;
        if (nk < K) issue(nk, ((kt >> 5) + 2) % 3);
        else        CPCOMMIT();

        const float* Asb = gsm + ((kt >> 5) % 3) * 8960;
        const float* Bsb = Asb + 4608;
#pragma unroll
        for (int ks = 0; ks < 4; ++ks) {
            const int k0 = ks << 3;
            uint32_t af[4][4], bf[4][2];
#pragma unroll
            for (int i = 0; i < 4; ++i) {
                int r = (wm << 6) + (i << 4) + quad;
                af[i][0] = __float_as_uint(Asb[r * 36 + k0 + tq]);
                af[i][1] = __float_as_uint(Asb[(r + 8) * 36 + k0 + tq]);
                af[i][2] = __float_as_uint(Asb[r * 36 + k0 + tq + 4]);
                af[i][3] = __float_as_uint(Asb[(r + 8) * 36 + k0 + tq + 4]);
            }
#pragma unroll
            for (int j = 0; j < 4; ++j) {
                int cidx = (wn << 5) + (j << 3) + quad;
                bf[j][0] = __float_as_uint(Bsb[(k0 + tq) * 136 + cidx]);
                bf[j][1] = __float_as_uint(Bsb[(k0 + tq + 4) * 136 + cidx]);
            }
#pragma unroll
            for (int i = 0; i < 4; ++i)
#pragma unroll
                for (int j = 0; j < 4; ++j) mma8(acc[i][j], af[i], bf[j]);
        }
    }

#pragma unroll
    for (int i = 0; i < 4; ++i)
#pragma unroll
        for (int j = 0; j < 4; ++j) {
            int mr = m0 + (wm << 6) + (i << 4) + quad;
            int nc = n0 + (wn << 5) + (j << 3) + (tq << 1);
#pragma unroll
            for (int hf = 0; hf < 2; ++hf) {
                int m = mr + (hf << 3);
                size_t bix = (size_t)m * 1024u + nc;
#pragma unroll
                for (int e = 0; e < 2; ++e) {
                    float z = acc[i][j][(hf << 1) + e] + bias[nc + e];
                    if (mode == 1) {
                        float gg = 1.0f / (1.0f + __expf(-z));
                        C[bix + e] = gg * A0[bix + e] + (1.0f - gg) * A1[bix + e] + BCp[bix + e];
                    } else {
                        C[bix + e] = z;
                    }
                }
            }
        }
}

// =====================================================================
extern "C" void kernel_launch(void* const* d_in, const int* in_sizes, int n_in,
                              void* d_out, int out_size) {
    const float* x    = (const float*)d_in[0];
    const float* gmem = (const float*)d_in[1];
    const float* cw   = (const float*)d_in[2];
    const float* cb   = (const float*)d_in[3];
    const float* mw   = (const float*)d_in[4];
    const float* mb   = (const float*)d_in[5];
    const float* ow   = (const float*)d_in[6];
    const float* ob   = (const float*)d_in[7];
    float* out = (float*)d_out;

    float *pL, *pG, *pBC, *pM, *pCOMP, *pW1, *pW2, *pXC, *pCP;
    cudaGetSymbolAddress((void**)&pL,    g_L);
    cudaGetSymbolAddress((void**)&pG,    g_G);
    cudaGetSymbolAddress((void**)&pBC,   g_BC);
    cudaGetSymbolAddress((void**)&pM,    g_M);
    cudaGetSymbolAddress((void**)&pCOMP, g_COMP);
    cudaGetSymbolAddress((void**)&pW1,   g_W1);
    cudaGetSymbolAddress((void**)&pW2,   g_W2);
    cudaGetSymbolAddress((void**)&pXC,   g_XC);
    cudaGetSymbolAddress((void**)&pCP,   g_CP);

    static cudaStream_t s1 = nullptr, s2 = nullptr, s3 = nullptr;
    static cudaEvent_t evR = nullptr, ev1 = nullptr, ev2 = nullptr, ev3 = nullptr;
    static cudaEvent_t evQ[4] = {nullptr, nullptr, nullptr, nullptr};
    static cudaEvent_t evF = nullptr;
    if (s1 == nullptr) {
        cudaStreamCreateWithFlags(&s1, cudaStreamNonBlocking);
        cudaStreamCreateWithFlags(&s2, cudaStreamNonBlocking);
        cudaStreamCreateWithFlags(&s3, cudaStreamNonBlocking);
        cudaEventCreateWithFlags(&evR, cudaEventDisableTiming);
        cudaEventCreateWithFlags(&ev1, cudaEventDisableTiming);
        cudaEventCreateWithFlags(&ev2, cudaEventDisableTiming);
        cudaEventCreateWithFlags(&ev3, cudaEventDisableTiming);
        for (int q = 0; q < 4; ++q) cudaEventCreateWithFlags(&evQ[q], cudaEventDisableTiming);
        cudaEventCreateWithFlags(&evF, cudaEventDisableTiming);
    }

    const int BC_SMEM = 2 * 16384 * 4;
    const int WA_SMEM = 21312 * 4;
    const int GA_SMEM = 25344 * 4;
    const int GE_SMEM = 3 * 8960 * 4;
    const int CV_SMEM = 3 * 9216 * 4;
    cudaFuncSetAttribute(bc_kernel, cudaFuncAttributeMaxDynamicSharedMemorySize, BC_SMEM);
    cudaFuncSetAttribute(win_attn,  cudaFuncAttributeMaxDynamicSharedMemorySize, WA_SMEM);
    cudaFuncSetAttribute(gattn,     cudaFuncAttributeMaxDynamicSharedMemorySize, GA_SMEM);
    cudaFuncSetAttribute(gemm_tc,   cudaFuncAttributeMaxDynamicSharedMemorySize, GE_SMEM);
    cudaFuncSetAttribute(conv_gemm, cudaFuncAttributeMaxDynamicSharedMemorySize, CV_SMEM);

    cudaEventRecord(evR, 0);
    cudaStreamWaitEvent(s1, evR, 0);
    cudaStreamWaitEvent(s2, evR, 0);
    cudaStreamWaitEvent(s3, evR, 0);

    wround     <<<2048, 256, 0, s1>>>(mw, pW1);
    wround     <<<1024, 256, 0, s1>>>(ow, pW2);
    bc_kernel  <<<dim3(256, 2), 512, BC_SMEM, s1>>>(x, pBC);

    xc_kernel  <<<dim3(256, 2), 256, 0, s2>>>(x, pXC);
    conv_gemm  <<<dim3(8, 4), 256, CV_SMEM, s2>>>(pXC, cw, pCP);
    conv_reduce<<<128, 256, 0, s2>>>(pCP, cb, pCOMP);
    gattn      <<<dim3(128, 8, 2), 256, GA_SMEM, s2>>>(x, gmem, pCOMP, pG);

    win_attn   <<<dim3(8, 8, 16), 256, WA_SMEM, s3>>>(x, pL, 0);
    win_attn   <<<dim3(8, 7, 16), 256, WA_SMEM, s3>>>(x, pL, 1);

    cudaEventRecord(ev1, s1);
    cudaEventRecord(ev2, s2);
    cudaEventRecord(ev3, s3);
    cudaStreamWaitEvent(0, ev1, 0);
    cudaStreamWaitEvent(0, ev2, 0);
    cudaStreamWaitEvent(0, ev3, 0);
    // s2 will run gemm2 quarters; it must also respect the join
    cudaStreamWaitEvent(s2, ev1, 0);
    cudaStreamWaitEvent(s2, ev3, 0);

    // m-split pipelined GEMMs: gemm1 quarter q on stream 0, gemm2 quarter q on s2
    const size_t QOFF = (size_t)2048u * 1024u;   // 2048 rows per quarter
    for (int q = 0; q < 4; ++q) {
        size_t o = (size_t)q * QOFF;
        gemm_tc<<<dim3(16, 8), 256, GE_SMEM, 0>>>(
            1, pL + o, pG + o, pBC + o, pW1, mb, pM + o, 2048);
        cudaEventRecord(evQ[q], 0);
        cudaStreamWaitEvent(s2, evQ[q], 0);
        gemm_tc<<<dim3(16, 8), 256, GE_SMEM, s2>>>(
            0, pM + o, pM + o, pBC + o, pW2, ob, out + o, 1024);
    }
    cudaEventRecord(evF, s2);
    cudaStreamWaitEvent(0, evF, 0);
}

// round 11
// speedup vs baseline: 1.0341x; 1.0341x over previous
#include <cuda_runtime.h>
#include <math.h>
#include <stdint.h>

__device__ float g_L [2u*4096u*1024u];
__device__ float g_G [2u*4096u*1024u];
__device__ float g_BC[2u*4096u*1024u];
__device__ float g_M [2u*4096u*1024u];
__device__ float g_COMP[2u*64u*1024u];
__device__ float g_W1[2048u*1024u];   // mix_w, tf32-RN
__device__ float g_W2[1024u*1024u];   // out_w, tf32-RN
__device__ float g_XC[128u*4096u];    // gathered conv input
__device__ float g_CP[4u*128u*1024u]; // conv split-K partials

__device__ __forceinline__ float f2tff(float x) {
    uint32_t u; asm("cvt.rn.tf32.f32 %0, %1;" : "=r"(u) : "f"(x));
    return __uint_as_float(u);
}
__device__ __forceinline__ void mma8(float* c, const uint32_t* a, const uint32_t* b) {
    asm volatile("mma.sync.aligned.m16n8k8.row.col.f32.tf32.tf32.f32 "
        "{%0,%1,%2,%3}, {%4,%5,%6,%7}, {%8,%9}, {%0,%1,%2,%3};"
        : "+f"(c[0]), "+f"(c[1]), "+f"(c[2]), "+f"(c[3])
        : "r"(a[0]), "r"(a[1]), "r"(a[2]), "r"(a[3]), "r"(b[0]), "r"(b[1]));
}
__device__ __forceinline__ uint32_t smem_u32(const void* p) {
    uint32_t a;
    asm("{ .reg .u64 t; cvta.to.shared.u64 t, %1; cvt.u32.u64 %0, t; }" : "=r"(a) : "l"(p));
    return a;
}
#define CP16(dst, src) asm volatile("cp.async.cg.shared.global [%0], [%1], 16;" :: "r"(dst), "l"(src))
#define CPCOMMIT()     asm volatile("cp.async.commit_group;" ::: "memory")
#define CPWAIT1()      asm volatile("cp.async.wait_group 1;" ::: "memory")
#define CPWAIT0()      asm volatile("cp.async.wait_group 0;" ::: "memory")

__device__ __forceinline__ float invden(int s) {
    int n1 = s >> 8, i1 = s & 255;
    float d = 0.f;
    if (n1 <= 14) d += 0.5f + (float)i1 * (1.0f / 511.0f);
    if (n1 >= 1)  d += 0.5f + (float)(i1 + 256) * (1.0f / 511.0f);
    return 1.0f / d;
}

// ============ 0) weight tf32-RN pre-rounding ============
__global__ void wround(const float* __restrict__ W, float* __restrict__ WR) {
    size_t i = ((size_t)blockIdx.x * blockDim.x + threadIdx.x) << 2;
    float4 v = *(const float4*)(W + i);
    v.x = f2tff(v.x); v.y = f2tff(v.y); v.z = f2tff(v.z); v.w = f2tff(v.w);
    *(float4*)(WR + i) = v;
}

// ============ 1) broadcast diffusion (conflict-free planes) ============
__global__ void bc_kernel(const float* __restrict__ x, float* __restrict__ bc) {
    extern __shared__ float sm[];
    const int tid = threadIdx.x, b = blockIdx.y, d0 = blockIdx.x << 2;
    float* bufA = sm; float* bufB = sm + 16384;
    const float* src = x + (size_t)b * 4194304u + d0;
    for (int s = tid; s < 4096; s += 512) {
        float4 v = *(const float4*)(src + (size_t)s * 1024u);
        bufA[s] = v.x; bufA[4096 + s] = v.y; bufA[8192 + s] = v.z; bufA[12288 + s] = v.w;
    }
    __syncthreads();
    float acc[32];
#pragma unroll
    for (int e = 0; e < 32; ++e) acc[e] = 0.f;
    float* cur = bufA; float* nxt = bufB;
    for (int st = 1; st < 4096; st <<= 1) {
#pragma unroll
        for (int q = 0; q < 8; ++q) {
            int s = tid + (q << 9);
            int sm1 = (s - st) & 4095, sp1 = (s + st) & 4095;
#pragma unroll
            for (int j = 0; j < 4; ++j) {
                const float* cj = cur + (j << 12);
                float v = cj[s] + 0.5f * (cj[sm1] + cj[sp1]);
                nxt[(j << 12) + s] = v;
                acc[(q << 2) + j] += v;
            }
        }
        __syncthreads();
        float* t = cur; cur = nxt; nxt = t;
    }
    const float inv = 1.0f / 13.0f;
    float* dst = bc + (size_t)b * 4194304u + d0;
#pragma unroll
    for (int q = 0; q < 8; ++q) {
        int s = tid + (q << 9);
        *(float4*)(dst + (size_t)s * 1024u) =
            make_float4(acc[q*4]*inv, acc[q*4+1]*inv, acc[q*4+2]*inv, acc[q*4+3]*inv);
    }
}

// ============ 2a) conv input gather ============
__global__ void xc_kernel(const float* __restrict__ x, float* __restrict__ Xc) {
    const int s = blockIdx.x;
    const int b = blockIdx.y;
    const int t = s >> 2, j = s & 3;
    const int m = (b << 6) + t;
    const float* src = x + (size_t)b * 4194304u + (size_t)s * 1024u;
    float* dst = Xc + (size_t)m * 4096u + j;
#pragma unroll
    for (int k = 0; k < 4; ++k) {
        int d = threadIdx.x + (k << 8);
        dst[d << 2] = src[d];
    }
}

// ============ 2b) conv GEMM (split-K x4) ============
__global__ void __launch_bounds__(256) conv_gemm(
        const float* __restrict__ Xc, const float* __restrict__ cwf,
        float* __restrict__ CP) {
    extern __shared__ float gsm[];
    const int tid = threadIdx.x;
    const int n0 = blockIdx.x << 7;
    const int kq = blockIdx.y;
    const int kbase = kq << 10;
    const int wid = tid >> 5, lane = tid & 31;
    const int quad = lane >> 2, tq = lane & 3;
    const int wm = wid >> 2, wn = wid & 3;
    const int am = tid >> 1, ak = (tid & 1) << 4;
    const uint32_t sbase = smem_u32(gsm);

    auto issue = [&](int kt, int slot) {
        uint32_t aoff = sbase + (uint32_t)(slot * 9216 + am * 36 + ak) * 4u;
        const float* asrc = Xc + (size_t)am * 4096u + kbase + kt + ak;
        CP16(aoff, asrc); CP16(aoff + 16, asrc + 4);
        CP16(aoff + 32, asrc + 8); CP16(aoff + 48, asrc + 12);
        uint32_t boff = aoff + 4608u * 4u;
        const float* bsrc = cwf + (size_t)(n0 + am) * 4096u + kbase + kt + ak;
        CP16(boff, bsrc); CP16(boff + 16, bsrc + 4);
        CP16(boff + 32, bsrc + 8); CP16(boff + 48, bsrc + 12);
        CPCOMMIT();
    };

    float acc[4][4][4];
#pragma unroll
    for (int i = 0; i < 4; ++i)
#pragma unroll
        for (int j = 0; j < 4; ++j)
#pragma unroll
            for (int e = 0; e < 4; ++e) acc[i][j][e] = 0.f;

    issue(0, 0);
    issue(32, 1);

    for (int kt = 0; kt < 1024; kt += 32) {
        CPWAIT1();
        __syncthreads();
        int nk = kt + 64;
        if (nk < 1024) issue(nk, ((kt >> 5) + 2) % 3);
        else           CPCOMMIT();

        const float* Asb = gsm + ((kt >> 5) % 3) * 9216;
        const float* Bsb = Asb + 4608;
#pragma unroll
        for (int ks = 0; ks < 4; ++ks) {
            const int k0 = ks << 3;
            uint32_t af[4][4], bf[4][2];
#pragma unroll
            for (int i = 0; i < 4; ++i) {
                int r = (wm << 6) + (i << 4) + quad;
                af[i][0] = __float_as_uint(Asb[r * 36 + k0 + tq]);
                af[i][1] = __float_as_uint(Asb[(r + 8) * 36 + k0 + tq]);
                af[i][2] = __float_as_uint(Asb[r * 36 + k0 + tq + 4]);
                af[i][3] = __float_as_uint(Asb[(r + 8) * 36 + k0 + tq + 4]);
            }
#pragma unroll
            for (int j = 0; j < 4; ++j) {
                int cidx = (wn << 5) + (j << 3) + quad;
                bf[j][0] = __float_as_uint(Bsb[cidx * 36 + k0 + tq]);
                bf[j][1] = __float_as_uint(Bsb[cidx * 36 + k0 + tq + 4]);
            }
#pragma unroll
            for (int i = 0; i < 4; ++i)
#pragma unroll
                for (int j = 0; j < 4; ++j) mma8(acc[i][j], af[i], bf[j]);
        }
    }
    float* cp = CP + (size_t)kq * 131072u;
#pragma unroll
    for (int i = 0; i < 4; ++i)
#pragma unroll
        for (int j = 0; j < 4; ++j) {
            int mr = (wm << 6) + (i << 4) + quad;
            int nc = n0 + (wn << 5) + (j << 3) + (tq << 1);
#pragma unroll
            for (int hf = 0; hf < 2; ++hf) {
                int m = mr + (hf << 3);
                *(float2*)(cp + (size_t)m * 1024u + nc) =
                    make_float2(acc[i][j][(hf << 1)], acc[i][j][(hf << 1) + 1]);
            }
        }
}

// ============ 2c) conv reduce ============
__global__ void conv_reduce(const float* __restrict__ CP, const float* __restrict__ cb,
                            float* __restrict__ comp) {
    int i = (blockIdx.x << 8) + threadIdx.x;
    int o4 = (i & 255) << 2;
    float4 a = *(const float4*)(CP + ((size_t)i << 2));
    float4 b = *(const float4*)(CP + 131072u + ((size_t)i << 2));
    float4 c = *(const float4*)(CP + 262144u + ((size_t)i << 2));
    float4 d = *(const float4*)(CP + 393216u + ((size_t)i << 2));
    float4 e = *(const float4*)(cb + o4);
    *(float4*)(comp + ((size_t)i << 2)) = make_float4(
        a.x + b.x + c.x + d.x + e.x, a.y + b.y + c.y + d.y + e.y,
        a.z + b.z + c.z + d.z + e.z, a.w + b.w + c.w + d.w + e.w);
}

// ============ 3) sliding-window attention (TC, fused normalization) ============
__global__ void __launch_bounds__(256) win_attn(
        const float* __restrict__ x, float* __restrict__ L, int parity) {
    extern __shared__ float sm[];
    float* Qs = sm;
    float* Ks = sm + 8448;
    float* Ss = sm + 16896;
    float* Al = sm + 21248;
    const int tid = threadIdx.x;
    const int lane = tid & 31, wid = tid >> 5;
    const int g = lane >> 2, tq = lane & 3;
    const int qt = blockIdx.x;
    const int n = (blockIdx.y << 1) + parity;
    const int b = blockIdx.z >> 3, h = blockIdx.z & 7;
    const int base = n << 8, q0 = base + (qt << 6);
    const float* xb = x + (size_t)b * 4194304u + (h << 7);

#pragma unroll
    for (int it = 0; it < 8; ++it) {
        int i = tid + (it << 8);
        int r = i >> 5, c4 = (i & 31) << 2;
        float4 v = *(const float4*)(xb + (size_t)(q0 + r) * 1024u + c4);
        float* q = &Qs[r * 132 + c4];
        q[0] = f2tff(v.x); q[1] = f2tff(v.y); q[2] = f2tff(v.z); q[3] = f2tff(v.w);
    }

    const int wm = wid >> 1, wn = wid & 1;
    const int m0 = wm << 4;
    const int sn0 = wn << 5;
    const int on0 = wn << 6;
    const int srow = tid >> 2, seg = tid & 3;
    const float scale = 0.08838834764831845f;

    float oacc[8][4];
#pragma unroll
    for (int nt = 0; nt < 8; ++nt)
#pragma unroll
        for (int e = 0; e < 4; ++e) oacc[nt][e] = 0.f;
    float m_i = -1e30f, l_i = 0.f;

    for (int kt = 0; kt < 8; ++kt) {
        __syncthreads();
        const int ktok = base + (kt << 6);
#pragma unroll
        for (int it = 0; it < 8; ++it) {
            int i = tid + (it << 8);
            int r = i >> 5, c4 = (i & 31) << 2;
            float4 v = *(const float4*)(xb + (size_t)(ktok + r) * 1024u + c4);
            float* k = &Ks[r * 132 + c4];
            k[0] = f2tff(v.x); k[1] = f2tff(v.y); k[2] = f2tff(v.z); k[3] = f2tff(v.w);
        }
        __syncthreads();

        float sacc[4][4];
#pragma unroll
        for (int nt = 0; nt < 4; ++nt)
#pragma unroll
            for (int e = 0; e < 4; ++e) sacc[nt][e] = 0.f;
#pragma unroll
        for (int kd = 0; kd < 128; kd += 8) {
            uint32_t a[4];
            a[0] = __float_as_uint(Qs[(m0 + g) * 132 + kd + tq]);
            a[1] = __float_as_uint(Qs[(m0 + g + 8) * 132 + kd + tq]);
            a[2] = __float_as_uint(Qs[(m0 + g) * 132 + kd + tq + 4]);
            a[3] = __float_as_uint(Qs[(m0 + g + 8) * 132 + kd + tq + 4]);
#pragma unroll
            for (int nt = 0; nt < 4; ++nt) {
                int tcol = sn0 + (nt << 3) + g;
                uint32_t bb[2];
                bb[0] = __float_as_uint(Ks[tcol * 132 + kd + tq]);
                bb[1] = __float_as_uint(Ks[tcol * 132 + kd + tq + 4]);
                mma8(sacc[nt], a, bb);
            }
        }
#pragma unroll
        for (int nt = 0; nt < 4; ++nt) {
            int nc = sn0 + (nt << 3) + (tq << 1);
            *(float2*)&Ss[(m0 + g) * 68 + nc] =
                make_float2(sacc[nt][0] * scale, sacc[nt][1] * scale);
            *(float2*)&Ss[(m0 + g + 8) * 68 + nc] =
                make_float2(sacc[nt][2] * scale, sacc[nt][3] * scale);
        }
        __syncthreads();

        {
            float* sr = &Ss[srow * 68 + (seg << 4)];
            float mt = -1e30f;
#pragma unroll
            for (int jj = 0; jj < 16; ++jj) mt = fmaxf(mt, sr[jj]);
            mt = fmaxf(mt, __shfl_xor_sync(0xffffffffu, mt, 1));
            mt = fmaxf(mt, __shfl_xor_sync(0xffffffffu, mt, 2));
            float m_new = fmaxf(m_i, mt);
            float alpha = __expf(m_i - m_new);
            float ls = 0.f;
#pragma unroll
            for (int jj = 0; jj < 16; ++jj) {
                float p = __expf(sr[jj] - m_new);
                ls += p;
                sr[jj] = f2tff(p);
            }
            ls += __shfl_xor_sync(0xffffffffu, ls, 1);
            ls += __shfl_xor_sync(0xffffffffu, ls, 2);
            l_i = l_i * alpha + ls;
            m_i = m_new;
            if (seg == 0) Al[srow] = alpha;
        }
        __syncthreads();

        float aLo = Al[m0 + g], aHi = Al[m0 + g + 8];
#pragma unroll
        for (int nt = 0; nt < 8; ++nt) {
            oacc[nt][0] *= aLo; oacc[nt][1] *= aLo;
            oacc[nt][2] *= aHi; oacc[nt][3] *= aHi;
        }
#pragma unroll
        for (int kd = 0; kd < 64; kd += 8) {
            uint32_t a[4];
            a[0] = __float_as_uint(Ss[(m0 + g) * 68 + kd + tq]);
            a[1] = __float_as_uint(Ss[(m0 + g + 8) * 68 + kd + tq]);
            a[2] = __float_as_uint(Ss[(m0 + g) * 68 + kd + tq + 4]);
            a[3] = __float_as_uint(Ss[(m0 + g + 8) * 68 + kd + tq + 4]);
#pragma unroll
            for (int nt = 0; nt < 8; ++nt) {
                int dcol = on0 + (nt << 3) + g;
                uint32_t bb[2];
                bb[0] = __float_as_uint(Ks[(kd + tq) * 132 + dcol]);
                bb[1] = __float_as_uint(Ks[(kd + tq + 4) * 132 + dcol]);
                mma8(oacc[nt], a, bb);
            }
        }
    }
    __syncthreads();
    if (seg == 0) Al[srow] = 1.0f / l_i;
    __syncthreads();

    const int iwLo = (qt << 6) + m0 + g;
    const int iwHi = iwLo + 8;
    const int sLo = base + iwLo, sHi = base + iwHi;
    const float triLo = 0.5f + (float)iwLo * (1.0f / 511.0f);
    const float triHi = 0.5f + (float)iwHi * (1.0f / 511.0f);
    float* dLo = L + ((size_t)b * 4096u + sLo) * 1024u + (h << 7);
    float* dHi = dLo + (size_t)8 * 1024u;
    if (parity == 0) {
        const bool snLo = (sLo < 256) || (sLo >= 3840);
        const bool snHi = (sHi < 256) || (sHi >= 3840);
        const float twLo = (snLo ? 1.0f : triLo) * Al[m0 + g];
        const float twHi = (snHi ? 1.0f : triHi) * Al[m0 + g + 8];
#pragma unroll
        for (int nt = 0; nt < 8; ++nt) {
            int dc = on0 + (nt << 3) + (tq << 1);
            *(float2*)(dLo + dc) = make_float2(oacc[nt][0] * twLo, oacc[nt][1] * twLo);
            *(float2*)(dHi + dc) = make_float2(oacc[nt][2] * twHi, oacc[nt][3] * twHi);
        }
    } else {
        const float twLo = triLo * Al[m0 + g];
        const float twHi = triHi * Al[m0 + g + 8];
        const float ivLo = invden(sLo), ivHi = invden(sHi);
#pragma unroll
        for (int nt = 0; nt < 8; ++nt) {
            int dc = on0 + (nt << 3) + (tq << 1);
            float2 o = *(float2*)(dLo + dc);
            o.x = (o.x + oacc[nt][0] * twLo) * ivLo;
            o.y = (o.y + oacc[nt][1] * twLo) * ivLo;
            *(float2*)(dLo + dc) = o;
            float2 p = *(float2*)(dHi + dc);
            p.x = (p.x + oacc[nt][2] * twHi) * ivHi;
            p.y = (p.y + oacc[nt][3] * twHi) * ivHi;
            *(float2*)(dHi + dc) = p;
        }
    }
}

// ============ 4) compressed-global attention (TC) ============
__global__ void __launch_bounds__(256) gattn(
        const float* __restrict__ x, const float* __restrict__ gmem,
        const float* __restrict__ comp, float* __restrict__ G) {
    extern __shared__ float sm[];
    float* KVs = sm;
    float* Qs  = sm + 16896;
    float* Ps  = sm + 21120;
    const int tid = threadIdx.x;
    const int lane = tid & 31, wid = tid >> 5;
    const int g = lane >> 2, tq = lane & 3;
    const int s0 = blockIdx.x << 5, h = blockIdx.y, b = blockIdx.z;

#pragma unroll
    for (int it = 0; it < 16; ++it) {
        int i = tid + (it << 8);
        int r = i >> 5, c4 = (i & 31) << 2;
        float4 v;
        if (r < 64) v = *(const float4*)(comp + (size_t)((b << 6) + r) * 1024u + (h << 7) + c4);
        else        v = *(const float4*)(gmem + (size_t)((h << 6) + (r - 64)) * 128u + c4);
        float* kv = &KVs[r * 132 + c4];
        kv[0] = f2tff(v.x); kv[1] = f2tff(v.y); kv[2] = f2tff(v.z); kv[3] = f2tff(v.w);
    }
#pragma unroll
    for (int it = 0; it < 4; ++it) {
        int i = tid + (it << 8);
        int r = i >> 5, c4 = (i & 31) << 2;
        float4 v = *(const float4*)(x + (size_t)b * 4194304u + (size_t)(s0 + r) * 1024u + (h << 7) + c4);
        float* q = &Qs[r * 132 + c4];
        q[0] = f2tff(v.x); q[1] = f2tff(v.y); q[2] = f2tff(v.z); q[3] = f2tff(v.w);
    }
    __syncthreads();

    const int wm = wid & 1, wn = wid >> 1;
    const int m0 = wm << 4;
    const int tn0 = wn << 5;
    const float scale = 0.08838834764831845f;

    {
        float sacc[4][4];
#pragma unroll
        for (int nt = 0; nt < 4; ++nt)
#pragma unroll
            for (int e = 0; e < 4; ++e) sacc[nt][e] = 0.f;
#pragma unroll
        for (int kd = 0; kd < 128; kd += 8) {
            uint32_t a[4];
            a[0] = __float_as_uint(Qs[(m0 + g) * 132 + kd + tq]);
            a[1] = __float_as_uint(Qs[(m0 + g + 8) * 132 + kd + tq]);
            a[2] = __float_as_uint(Qs[(m0 + g) * 132 + kd + tq + 4]);
            a[3] = __float_as_uint(Qs[(m0 + g + 8) * 132 + kd + tq + 4]);
#pragma unroll
            for (int nt = 0; nt < 4; ++nt) {
                int tcol = tn0 + (nt << 3) + g;
                uint32_t bb[2];
                bb[0] = __float_as_uint(KVs[tcol * 132 + kd + tq]);
                bb[1] = __float_as_uint(KVs[tcol * 132 + kd + tq + 4]);
                mma8(sacc[nt], a, bb);
            }
        }
#pragma unroll
        for (int nt = 0; nt < 4; ++nt) {
            int nc = tn0 + (nt << 3) + (tq << 1);
            *(float2*)&Ps[(m0 + g) * 132 + nc] =
                make_float2(sacc[nt][0] * scale, sacc[nt][1] * scale);
            *(float2*)&Ps[(m0 + g + 8) * 132 + nc] =
                make_float2(sacc[nt][2] * scale, sacc[nt][3] * scale);
        }
    }
    __syncthreads();

    {
        int row = tid >> 3, seg8 = tid & 7;
        float* pr = &Ps[row * 132 + (seg8 << 4)];
        float mt = -1e30f;
        float pv[16];
#pragma unroll
        for (int jj = 0; jj < 16; ++jj) mt = fmaxf(mt, pr[jj]);
        mt = fmaxf(mt, __shfl_xor_sync(0xffffffffu, mt, 1));
        mt = fmaxf(mt, __shfl_xor_sync(0xffffffffu, mt, 2));
        mt = fmaxf(mt, __shfl_xor_sync(0xffffffffu, mt, 4));
        float ssum = 0.f;
#pragma unroll
        for (int jj = 0; jj < 16; ++jj) { pv[jj] = __expf(pr[jj] - mt); ssum += pv[jj]; }
        ssum += __shfl_xor_sync(0xffffffffu, ssum, 1);
        ssum += __shfl_xor_sync(0xffffffffu, ssum, 2);
        ssum += __shfl_xor_sync(0xffffffffu, ssum, 4);
        float invs = 1.0f / ssum;
#pragma unroll
        for (int jj = 0; jj < 16; ++jj) pr[jj] = f2tff(pv[jj] * invs);
    }
    __syncthreads();

    {
        float oacc[4][4];
#pragma unroll
        for (int nt = 0; nt < 4; ++nt)
#pragma unroll
            for (int e = 0; e < 4; ++e) oacc[nt][e] = 0.f;
#pragma unroll
        for (int kd = 0; kd < 128; kd += 8) {
            uint32_t a[4];
            a[0] = __float_as_uint(Ps[(m0 + g) * 132 + kd + tq]);
            a[1] = __float_as_uint(Ps[(m0 + g + 8) * 132 + kd + tq]);
            a[2] = __float_as_uint(Ps[(m0 + g) * 132 + kd + tq + 4]);
            a[3] = __float_as_uint(Ps[(m0 + g + 8) * 132 + kd + tq + 4]);
#pragma unroll
            for (int nt = 0; nt < 4; ++nt) {
                int dcol = tn0 + (nt << 3) + g;
                uint32_t bb[2];
                bb[0] = __float_as_uint(KVs[(kd + tq) * 132 + dcol]);
                bb[1] = __float_as_uint(KVs[(kd + tq + 4) * 132 + dcol]);
                mma8(oacc[nt], a, bb);
            }
        }
        float* gLo = G + ((size_t)b * 4096u + s0 + m0 + g) * 1024u + (h << 7);
        float* gHi = gLo + (size_t)8 * 1024u;
#pragma unroll
        for (int nt = 0; nt < 4; ++nt) {
            int nc = tn0 + (nt << 3) + (tq << 1);
            *(float2*)(gLo + nc) = make_float2(oacc[nt][0], oacc[nt][1]);
            *(float2*)(gHi + nc) = make_float2(oacc[nt][2], oacc[nt][3]);
        }
    }
}

// ============ 5+6) tf32 GEMM v2: 128x256 tile, 64x64 warp, 2-stage, 2 CTA/SM ============
// stage: A[128][36] (4608) + B[32][264] (8448) = 13056 floats
__global__ void __launch_bounds__(256) gemm_tc2(
        int mode, const float* __restrict__ A0, const float* __restrict__ A1,
        const float* __restrict__ BCp, const float* __restrict__ W,
        const float* __restrict__ bias, float* __restrict__ C, int K) {
    extern __shared__ float gsm[];
    const int tid = threadIdx.x;
    const int m0 = blockIdx.x << 7, n0 = blockIdx.y << 8;
    const int wid = tid >> 5, lane = tid & 31;
    const int quad = lane >> 2, tq = lane & 3;
    const int wm = wid >> 2, wn = wid & 3;           // 2 x 4 warps, 64x64 tiles
    const int am = tid >> 1, ak = (tid & 1) << 4;    // A loader
    const int bk = tid >> 3, bn = (tid & 7) << 5;    // B loader: 32 floats each
    const uint32_t sbase = smem_u32(gsm);

    auto issue = [&](int kt, int slot) {
        uint32_t aoff = sbase + (uint32_t)(slot * 13056 + am * 36 + ak) * 4u;
        const float* asrc = (mode == 1 && kt >= 1024)
            ? (A1 + (size_t)(m0 + am) * 1024u + (kt - 1024) + ak)
            : (A0 + (size_t)(m0 + am) * 1024u + kt + ak);
        CP16(aoff, asrc); CP16(aoff + 16, asrc + 4);
        CP16(aoff + 32, asrc + 8); CP16(aoff + 48, asrc + 12);
        uint32_t boff = sbase + (uint32_t)(slot * 13056 + 4608 + bk * 264 + bn) * 4u;
        const float* bsrc = W + (size_t)(kt + bk) * 1024u + n0 + bn;
#pragma unroll
        for (int q = 0; q < 8; ++q)
            CP16(boff + (q << 4), bsrc + (q << 2));
        CPCOMMIT();
    };

    float acc[4][8][4];
#pragma unroll
    for (int i = 0; i < 4; ++i)
#pragma unroll
        for (int j = 0; j < 8; ++j)
#pragma unroll
            for (int e = 0; e < 4; ++e) acc[i][j][e] = 0.f;

    issue(0, 0);
    const int NC = K >> 5;
    for (int kc = 0; kc < NC; ++kc) {
        if (kc + 1 < NC) { issue((kc + 1) << 5, (kc + 1) & 1); CPWAIT1(); }
        else             { CPWAIT0(); }
        __syncthreads();

        const float* Asb = gsm + (kc & 1) * 13056;
        const float* Bsb = Asb + 4608;
#pragma unroll
        for (int ks = 0; ks < 4; ++ks) {
            const int k0 = ks << 3;
            uint32_t af[4][4], bf[8][2];
#pragma unroll
            for (int i = 0; i < 4; ++i) {
                int r = (wm << 6) + (i << 4) + quad;
                af[i][0] = __float_as_uint(Asb[r * 36 + k0 + tq]);
                af[i][1] = __float_as_uint(Asb[(r + 8) * 36 + k0 + tq]);
                af[i][2] = __float_as_uint(Asb[r * 36 + k0 + tq + 4]);
                af[i][3] = __float_as_uint(Asb[(r + 8) * 36 + k0 + tq + 4]);
            }
#pragma unroll
            for (int j = 0; j < 8; ++j) {
                int cidx = (wn << 6) + (j << 3) + quad;
                bf[j][0] = __float_as_uint(Bsb[(k0 + tq) * 264 + cidx]);
                bf[j][1] = __float_as_uint(Bsb[(k0 + tq + 4) * 264 + cidx]);
            }
#pragma unroll
            for (int i = 0; i < 4; ++i)
#pragma unroll
                for (int j = 0; j < 8; ++j) mma8(acc[i][j], af[i], bf[j]);
        }
        __syncthreads();
    }

#pragma unroll
    for (int i = 0; i < 4; ++i)
#pragma unroll
        for (int j = 0; j < 8; ++j) {
            int mr = m0 + (wm << 6) + (i << 4) + quad;
            int nc = n0 + (wn << 6) + (j << 3) + (tq << 1);
#pragma unroll
            for (int hf = 0; hf < 2; ++hf) {
                int m = mr + (hf << 3);
                size_t bix = (size_t)m * 1024u + nc;
#pragma unroll
                for (int e = 0; e < 2; ++e) {
                    float z = acc[i][j][(hf << 1) + e] + bias[nc + e];
                    if (mode == 1) {
                        float gg = 1.0f / (1.0f + __expf(-z));
                        C[bix + e] = gg * A0[bix + e] + (1.0f - gg) * A1[bix + e] + BCp[bix + e];
                    } else {
                        C[bix + e] = z;
                    }
                }
            }
        }
}

// =====================================================================
extern "C" void kernel_launch(void* const* d_in, const int* in_sizes, int n_in,
                              void* d_out, int out_size) {
    const float* x    = (const float*)d_in[0];
    const float* gmem = (const float*)d_in[1];
    const float* cw   = (const float*)d_in[2];
    const float* cb   = (const float*)d_in[3];
    const float* mw   = (const float*)d_in[4];
    const float* mb   = (const float*)d_in[5];
    const float* ow   = (const float*)d_in[6];
    const float* ob   = (const float*)d_in[7];
    float* out = (float*)d_out;

    float *pL, *pG, *pBC, *pM, *pCOMP, *pW1, *pW2, *pXC, *pCP;
    cudaGetSymbolAddress((void**)&pL,    g_L);
    cudaGetSymbolAddress((void**)&pG,    g_G);
    cudaGetSymbolAddress((void**)&pBC,   g_BC);
    cudaGetSymbolAddress((void**)&pM,    g_M);
    cudaGetSymbolAddress((void**)&pCOMP, g_COMP);
    cudaGetSymbolAddress((void**)&pW1,   g_W1);
    cudaGetSymbolAddress((void**)&pW2,   g_W2);
    cudaGetSymbolAddress((void**)&pXC,   g_XC);
    cudaGetSymbolAddress((void**)&pCP,   g_CP);

    static cudaStream_t s1 = nullptr, s2 = nullptr, s3 = nullptr;
    static cudaEvent_t evR = nullptr, ev1 = nullptr, ev2 = nullptr, ev3 = nullptr;
    if (s1 == nullptr) {
        cudaStreamCreateWithFlags(&s1, cudaStreamNonBlocking);
        cudaStreamCreateWithFlags(&s2, cudaStreamNonBlocking);
        cudaStreamCreateWithFlags(&s3, cudaStreamNonBlocking);
        cudaEventCreateWithFlags(&evR, cudaEventDisableTiming);
        cudaEventCreateWithFlags(&ev1, cudaEventDisableTiming);
        cudaEventCreateWithFlags(&ev2, cudaEventDisableTiming);
        cudaEventCreateWithFlags(&ev3, cudaEventDisableTiming);
    }

    const int BC_SMEM = 2 * 16384 * 4;
    const int WA_SMEM = 21312 * 4;
    const int GA_SMEM = 25344 * 4;
    const int G2_SMEM = 2 * 13056 * 4;     // 104448 B (2 CTA/SM)
    const int CV_SMEM = 3 * 9216 * 4;
    cudaFuncSetAttribute(bc_kernel, cudaFuncAttributeMaxDynamicSharedMemorySize, BC_SMEM);
    cudaFuncSetAttribute(win_attn,  cudaFuncAttributeMaxDynamicSharedMemorySize, WA_SMEM);
    cudaFuncSetAttribute(gattn,     cudaFuncAttributeMaxDynamicSharedMemorySize, GA_SMEM);
    cudaFuncSetAttribute(gemm_tc2,  cudaFuncAttributeMaxDynamicSharedMemorySize, G2_SMEM);
    cudaFuncSetAttribute(conv_gemm, cudaFuncAttributeMaxDynamicSharedMemorySize, CV_SMEM);

    cudaEventRecord(evR, 0);
    cudaStreamWaitEvent(s1, evR, 0);
    cudaStreamWaitEvent(s2, evR, 0);
    cudaStreamWaitEvent(s3, evR, 0);

    wround     <<<2048, 256, 0, s1>>>(mw, pW1);
    wround     <<<1024, 256, 0, s1>>>(ow, pW2);
    bc_kernel  <<<dim3(256, 2), 512, BC_SMEM, s1>>>(x, pBC);

    xc_kernel  <<<dim3(256, 2), 256, 0, s2>>>(x, pXC);
    conv_gemm  <<<dim3(8, 4), 256, CV_SMEM, s2>>>(pXC, cw, pCP);
    conv_reduce<<<128, 256, 0, s2>>>(pCP, cb, pCOMP);
    gattn      <<<dim3(128, 8, 2), 256, GA_SMEM, s2>>>(x, gmem, pCOMP, pG);

    win_attn   <<<dim3(8, 8, 16), 256, WA_SMEM, s3>>>(x, pL, 0);
    win_attn   <<<dim3(8, 7, 16), 256, WA_SMEM, s3>>>(x, pL, 1);

    cudaEventRecord(ev1, s1);
    cudaEventRecord(ev2, s2);
    cudaEventRecord(ev3, s3);
    cudaStreamWaitEvent(0, ev1, 0);
    cudaStreamWaitEvent(0, ev2, 0);
    cudaStreamWaitEvent(0, ev3, 0);

    gemm_tc2<<<dim3(64, 4), 256, G2_SMEM>>>(1, pL, pG, pBC, pW1, mb, pM, 2048);
    gemm_tc2<<<dim3(64, 4), 256, G2_SMEM>>>(0, pM, pM, pBC, pW2, ob, out, 1024);
}

// round 13
// speedup vs baseline: 1.4164x; 1.3697x over previous
#include <cuda_runtime.h>
#include <cuda_fp16.h>
#include <math.h>
#include <stdint.h>

__device__ float g_L [2u*4096u*1024u];
__device__ float g_G [2u*4096u*1024u];
__device__ float g_BC[2u*4096u*1024u];
__device__ float g_COMP[2u*64u*1024u];
__device__ float g_XC[128u*4096u];
__device__ float g_CP[4u*128u*1024u];
__device__ __half g_Lh[2u*4096u*1024u];
__device__ __half g_Gh[2u*4096u*1024u];
__device__ __half g_Mh[2u*4096u*1024u];
__device__ __half g_W1h[1024u*2048u];   // mix_w^T [n][k]
__device__ __half g_W2h[1024u*1024u];   // out_w^T [n][k]

__device__ __forceinline__ float f2tff(float x) {
    uint32_t u; asm("cvt.rn.tf32.f32 %0, %1;" : "=r"(u) : "f"(x));
    return __uint_as_float(u);
}
__device__ __forceinline__ void mma8(float* c, const uint32_t* a, const uint32_t* b) {
    asm volatile("mma.sync.aligned.m16n8k8.row.col.f32.tf32.tf32.f32 "
        "{%0,%1,%2,%3}, {%4,%5,%6,%7}, {%8,%9}, {%0,%1,%2,%3};"
        : "+f"(c[0]), "+f"(c[1]), "+f"(c[2]), "+f"(c[3])
        : "r"(a[0]), "r"(a[1]), "r"(a[2]), "r"(a[3]), "r"(b[0]), "r"(b[1]));
}
__device__ __forceinline__ void mma16h(float* c, const uint32_t* a, const uint32_t* b) {
    asm volatile("mma.sync.aligned.m16n8k16.row.col.f32.f16.f16.f32 "
        "{%0,%1,%2,%3}, {%4,%5,%6,%7}, {%8,%9}, {%0,%1,%2,%3};"
        : "+f"(c[0]), "+f"(c[1]), "+f"(c[2]), "+f"(c[3])
        : "r"(a[0]), "r"(a[1]), "r"(a[2]), "r"(a[3]), "r"(b[0]), "r"(b[1]));
}
__device__ __forceinline__ uint32_t smem_u32(const void* p) {
    uint32_t a;
    asm("{ .reg .u64 t; cvta.to.shared.u64 t, %1; cvt.u32.u64 %0, t; }" : "=r"(a) : "l"(p));
    return a;
}
#define CP16(dst, src) asm volatile("cp.async.cg.shared.global [%0], [%1], 16;" :: "r"(dst), "l"(src))
#define CPCOMMIT()     asm volatile("cp.async.commit_group;" ::: "memory")
#define CPWAIT1()      asm volatile("cp.async.wait_group 1;" ::: "memory")

__device__ __forceinline__ float invden(int s) {
    int n1 = s >> 8, i1 = s & 255;
    float d = 0.f;
    if (n1 <= 14) d += 0.5f + (float)i1 * (1.0f / 511.0f);
    if (n1 >= 1)  d += 0.5f + (float)(i1 + 256) * (1.0f / 511.0f);
    return 1.0f / d;
}

// ============ 0a) weight transpose -> half, [n][k] K-major ============
__global__ void wthalf(const float* __restrict__ W, __half* __restrict__ WT, int K) {
    __shared__ float tile[32][33];
    const int k0 = blockIdx.x << 5, n0 = blockIdx.y << 5;
    const int tx = threadIdx.x & 31, ty = threadIdx.x >> 5;
#pragma unroll
    for (int i = ty; i < 32; i += 8)
        tile[i][tx] = W[(size_t)(k0 + i) * 1024u + n0 + tx];
    __syncthreads();
#pragma unroll
    for (int i = ty; i < 32; i += 8)
        WT[(size_t)(n0 + i) * (size_t)K + k0 + tx] = __float2half_rn(tile[tx][i]);
}

// ============ 0b) fp32 -> fp16 convert ============
__global__ void tohalf(const float* __restrict__ S, __half* __restrict__ D) {
    size_t i = ((size_t)blockIdx.x * blockDim.x + threadIdx.x) << 3;
    float4 a = *(const float4*)(S + i);
    float4 b = *(const float4*)(S + i + 4);
    __half2 h0 = __floats2half2_rn(a.x, a.y);
    __half2 h1 = __floats2half2_rn(a.z, a.w);
    __half2 h2 = __floats2half2_rn(b.x, b.y);
    __half2 h3 = __floats2half2_rn(b.z, b.w);
    uint4 o;
    o.x = *(uint32_t*)&h0; o.y = *(uint32_t*)&h1;
    o.z = *(uint32_t*)&h2; o.w = *(uint32_t*)&h3;
    *(uint4*)(D + i) = o;
}

// ============ 1) broadcast diffusion (conflict-free planes) ============
__global__ void bc_kernel(const float* __restrict__ x, float* __restrict__ bc) {
    extern __shared__ float sm[];
    const int tid = threadIdx.x, b = blockIdx.y, d0 = blockIdx.x << 2;
    float* bufA = sm; float* bufB = sm + 16384;
    const float* src = x + (size_t)b * 4194304u + d0;
    for (int s = tid; s < 4096; s += 512) {
        float4 v = *(const float4*)(src + (size_t)s * 1024u);
        bufA[s] = v.x; bufA[4096 + s] = v.y; bufA[8192 + s] = v.z; bufA[12288 + s] = v.w;
    }
    __syncthreads();
    float acc[32];
#pragma unroll
    for (int e = 0; e < 32; ++e) acc[e] = 0.f;
    float* cur = bufA; float* nxt = bufB;
    for (int st = 1; st < 4096; st <<= 1) {
#pragma unroll
        for (int q = 0; q < 8; ++q) {
            int s = tid + (q << 9);
            int sm1 = (s - st) & 4095, sp1 = (s + st) & 4095;
#pragma unroll
            for (int j = 0; j < 4; ++j) {
                const float* cj = cur + (j << 12);
                float v = cj[s] + 0.5f * (cj[sm1] + cj[sp1]);
                nxt[(j << 12) + s] = v;
                acc[(q << 2) + j] += v;
            }
        }
        __syncthreads();
        float* t = cur; cur = nxt; nxt = t;
    }
    const float inv = 1.0f / 13.0f;
    float* dst = bc + (size_t)b * 4194304u + d0;
#pragma unroll
    for (int q = 0; q < 8; ++q) {
        int s = tid + (q << 9);
        *(float4*)(dst + (size_t)s * 1024u) =
            make_float4(acc[q*4]*inv, acc[q*4+1]*inv, acc[q*4+2]*inv, acc[q*4+3]*inv);
    }
}

// ============ 2a) conv input gather ============
__global__ void xc_kernel(const float* __restrict__ x, float* __restrict__ Xc) {
    const int s = blockIdx.x;
    const int b = blockIdx.y;
    const int t = s >> 2, j = s & 3;
    const int m = (b << 6) + t;
    const float* src = x + (size_t)b * 4194304u + (size_t)s * 1024u;
    float* dst = Xc + (size_t)m * 4096u + j;
#pragma unroll
    for (int k = 0; k < 4; ++k) {
        int d = threadIdx.x + (k << 8);
        dst[d << 2] = src[d];
    }
}

// ============ 2b) conv GEMM (split-K x4, tf32) ============
__global__ void __launch_bounds__(256) conv_gemm(
        const float* __restrict__ Xc, const float* __restrict__ cwf,
        float* __restrict__ CP) {
    extern __shared__ float gsm[];
    const int tid = threadIdx.x;
    const int n0 = blockIdx.x << 7;
    const int kq = blockIdx.y;
    const int kbase = kq << 10;
    const int wid = tid >> 5, lane = tid & 31;
    const int quad = lane >> 2, tq = lane & 3;
    const int wm = wid >> 2, wn = wid & 3;
    const int am = tid >> 1, ak = (tid & 1) << 4;
    const uint32_t sbase = smem_u32(gsm);

    auto issue = [&](int kt, int slot) {
        uint32_t aoff = sbase + (uint32_t)(slot * 9216 + am * 36 + ak) * 4u;
        const float* asrc = Xc + (size_t)am * 4096u + kbase + kt + ak;
        CP16(aoff, asrc); CP16(aoff + 16, asrc + 4);
        CP16(aoff + 32, asrc + 8); CP16(aoff + 48, asrc + 12);
        uint32_t boff = aoff + 4608u * 4u;
        const float* bsrc = cwf + (size_t)(n0 + am) * 4096u + kbase + kt + ak;
        CP16(boff, bsrc); CP16(boff + 16, bsrc + 4);
        CP16(boff + 32, bsrc + 8); CP16(boff + 48, bsrc + 12);
        CPCOMMIT();
    };

    float acc[4][4][4];
#pragma unroll
    for (int i = 0; i < 4; ++i)
#pragma unroll
        for (int j = 0; j < 4; ++j)
#pragma unroll
            for (int e = 0; e < 4; ++e) acc[i][j][e] = 0.f;

    issue(0, 0);
    issue(32, 1);

    for (int kt = 0; kt < 1024; kt += 32) {
        CPWAIT1();
        __syncthreads();
        int nk = kt + 64;
        if (nk < 1024) issue(nk, ((kt >> 5) + 2) % 3);
        else           CPCOMMIT();

        const float* Asb = gsm + ((kt >> 5) % 3) * 9216;
        const float* Bsb = Asb + 4608;
#pragma unroll
        for (int ks = 0; ks < 4; ++ks) {
            const int k0 = ks << 3;
            uint32_t af[4][4], bf[4][2];
#pragma unroll
            for (int i = 0; i < 4; ++i) {
                int r = (wm << 6) + (i << 4) + quad;
                af[i][0] = __float_as_uint(Asb[r * 36 + k0 + tq]);
                af[i][1] = __float_as_uint(Asb[(r + 8) * 36 + k0 + tq]);
                af[i][2] = __float_as_uint(Asb[r * 36 + k0 + tq + 4]);
                af[i][3] = __float_as_uint(Asb[(r + 8) * 36 + k0 + tq + 4]);
            }
#pragma unroll
            for (int j = 0; j < 4; ++j) {
                int cidx = (wn << 5) + (j << 3) + quad;
                bf[j][0] = __float_as_uint(Bsb[cidx * 36 + k0 + tq]);
                bf[j][1] = __float_as_uint(Bsb[cidx * 36 + k0 + tq + 4]);
            }
#pragma unroll
            for (int i = 0; i < 4; ++i)
#pragma unroll
                for (int j = 0; j < 4; ++j) mma8(acc[i][j], af[i], bf[j]);
        }
    }
    float* cp = CP + (size_t)kq * 131072u;
#pragma unroll
    for (int i = 0; i < 4; ++i)
#pragma unroll
        for (int j = 0; j < 4; ++j) {
            int mr = (wm << 6) + (i << 4) + quad;
            int nc = n0 + (wn << 5) + (j << 3) + (tq << 1);
#pragma unroll
            for (int hf = 0; hf < 2; ++hf) {
                int m = mr + (hf << 3);
                *(float2*)(cp + (size_t)m * 1024u + nc) =
                    make_float2(acc[i][j][(hf << 1)], acc[i][j][(hf << 1) + 1]);
            }
        }
}

// ============ 2c) conv reduce ============
__global__ void conv_reduce(const float* __restrict__ CP, const float* __restrict__ cb,
                            float* __restrict__ comp) {
    int i = (blockIdx.x << 8) + threadIdx.x;
    int o4 = (i & 255) << 2;
    float4 a = *(const float4*)(CP + ((size_t)i << 2));
    float4 b = *(const float4*)(CP + 131072u + ((size_t)i << 2));
    float4 c = *(const float4*)(CP + 262144u + ((size_t)i << 2));
    float4 d = *(const float4*)(CP + 393216u + ((size_t)i << 2));
    float4 e = *(const float4*)(cb + o4);
    *(float4*)(comp + ((size_t)i << 2)) = make_float4(
        a.x + b.x + c.x + d.x + e.x, a.y + b.y + c.y + d.y + e.y,
        a.z + b.z + c.z + d.z + e.z, a.w + b.w + c.w + d.w + e.w);
}

// ============ 3) sliding-window attention (TC, fused normalization) ============
__global__ void __launch_bounds__(256) win_attn(
        const float* __restrict__ x, float* __restrict__ L, int parity) {
    extern __shared__ float sm[];
    float* Qs = sm;
    float* Ks = sm + 8448;
    float* Ss = sm + 16896;
    float* Al = sm + 21248;
    const int tid = threadIdx.x;
    const int lane = tid & 31, wid = tid >> 5;
    const int g = lane >> 2, tq = lane & 3;
    const int qt = blockIdx.x;
    const int n = (blockIdx.y << 1) + parity;
    const int b = blockIdx.z >> 3, h = blockIdx.z & 7;
    const int base = n << 8, q0 = base + (qt << 6);
    const float* xb = x + (size_t)b * 4194304u + (h << 7);

#pragma unroll
    for (int it = 0; it < 8; ++it) {
        int i = tid + (it << 8);
        int r = i >> 5, c4 = (i & 31) << 2;
        float4 v = *(const float4*)(xb + (size_t)(q0 + r) * 1024u + c4);
        float* q = &Qs[r * 132 + c4];
        q[0] = f2tff(v.x); q[1] = f2tff(v.y); q[2] = f2tff(v.z); q[3] = f2tff(v.w);
    }

    const int wm = wid >> 1, wn = wid & 1;
    const int m0 = wm << 4;
    const int sn0 = wn << 5;
    const int on0 = wn << 6;
    const int srow = tid >> 2, seg = tid & 3;
    const float scale = 0.08838834764831845f;

    float oacc[8][4];
#pragma unroll
    for (int nt = 0; nt < 8; ++nt)
#pragma unroll
        for (int e = 0; e < 4; ++e) oacc[nt][e] = 0.f;
    float m_i = -1e30f, l_i = 0.f;

    for (int kt = 0; kt < 8; ++kt) {
        __syncthreads();
        const int ktok = base + (kt << 6);
#pragma unroll
        for (int it = 0; it < 8; ++it) {
            int i = tid + (it << 8);
            int r = i >> 5, c4 = (i & 31) << 2;
            float4 v = *(const float4*)(xb + (size_t)(ktok + r) * 1024u + c4);
            float* k = &Ks[r * 132 + c4];
            k[0] = f2tff(v.x); k[1] = f2tff(v.y); k[2] = f2tff(v.z); k[3] = f2tff(v.w);
        }
        __syncthreads();

        float sacc[4][4];
#pragma unroll
        for (int nt = 0; nt < 4; ++nt)
#pragma unroll
            for (int e = 0; e < 4; ++e) sacc[nt][e] = 0.f;
#pragma unroll
        for (int kd = 0; kd < 128; kd += 8) {
            uint32_t a[4];
            a[0] = __float_as_uint(Qs[(m0 + g) * 132 + kd + tq]);
            a[1] = __float_as_uint(Qs[(m0 + g + 8) * 132 + kd + tq]);
            a[2] = __float_as_uint(Qs[(m0 + g) * 132 + kd + tq + 4]);
            a[3] = __float_as_uint(Qs[(m0 + g + 8) * 132 + kd + tq + 4]);
#pragma unroll
            for (int nt = 0; nt < 4; ++nt) {
                int tcol = sn0 + (nt << 3) + g;
                uint32_t bb[2];
                bb[0] = __float_as_uint(Ks[tcol * 132 + kd + tq]);
                bb[1] = __float_as_uint(Ks[tcol * 132 + kd + tq + 4]);
                mma8(sacc[nt], a, bb);
            }
        }
#pragma unroll
        for (int nt = 0; nt < 4; ++nt) {
            int nc = sn0 + (nt << 3) + (tq << 1);
            *(float2*)&Ss[(m0 + g) * 68 + nc] =
                make_float2(sacc[nt][0] * scale, sacc[nt][1] * scale);
            *(float2*)&Ss[(m0 + g + 8) * 68 + nc] =
                make_float2(sacc[nt][2] * scale, sacc[nt][3] * scale);
        }
        __syncthreads();

        {
            float* sr = &Ss[srow * 68 + (seg << 4)];
            float mt = -1e30f;
#pragma unroll
            for (int jj = 0; jj < 16; ++jj) mt = fmaxf(mt, sr[jj]);
            mt = fmaxf(mt, __shfl_xor_sync(0xffffffffu, mt, 1));
            mt = fmaxf(mt, __shfl_xor_sync(0xffffffffu, mt, 2));
            float m_new = fmaxf(m_i, mt);
            float alpha = __expf(m_i - m_new);
            float ls = 0.f;
#pragma unroll
            for (int jj = 0; jj < 16; ++jj) {
                float p = __expf(sr[jj] - m_new);
                ls += p;
                sr[jj] = f2tff(p);
            }
            ls += __shfl_xor_sync(0xffffffffu, ls, 1);
            ls += __shfl_xor_sync(0xffffffffu, ls, 2);
            l_i = l_i * alpha + ls;
            m_i = m_new;
            if (seg == 0) Al[srow] = alpha;
        }
        __syncthreads();

        float aLo = Al[m0 + g], aHi = Al[m0 + g + 8];
#pragma unroll
        for (int nt = 0; nt < 8; ++nt) {
            oacc[nt][0] *= aLo; oacc[nt][1] *= aLo;
            oacc[nt][2] *= aHi; oacc[nt][3] *= aHi;
        }
#pragma unroll
        for (int kd = 0; kd < 64; kd += 8) {
            uint32_t a[4];
            a[0] = __float_as_uint(Ss[(m0 + g) * 68 + kd + tq]);
            a[1] = __float_as_uint(Ss[(m0 + g + 8) * 68 + kd + tq]);
            a[2] = __float_as_uint(Ss[(m0 + g) * 68 + kd + tq + 4]);
            a[3] = __float_as_uint(Ss[(m0 + g + 8) * 68 + kd + tq + 4]);
#pragma unroll
            for (int nt = 0; nt < 8; ++nt) {
                int dcol = on0 + (nt << 3) + g;
                uint32_t bb[2];
                bb[0] = __float_as_uint(Ks[(kd + tq) * 132 + dcol]);
                bb[1] = __float_as_uint(Ks[(kd + tq + 4) * 132 + dcol]);
                mma8(oacc[nt], a, bb);
            }
        }
    }
    __syncthreads();
    if (seg == 0) Al[srow] = 1.0f / l_i;
    __syncthreads();

    const int iwLo = (qt << 6) + m0 + g;
    const int iwHi = iwLo + 8;
    const int sLo = base + iwLo, sHi = base + iwHi;
    const float triLo = 0.5f + (float)iwLo * (1.0f / 511.0f);
    const float triHi = 0.5f + (float)iwHi * (1.0f / 511.0f);
    float* dLo = L + ((size_t)b * 4096u + sLo) * 1024u + (h << 7);
    float* dHi = dLo + (size_t)8 * 1024u;
    if (parity == 0) {
        const bool snLo = (sLo < 256) || (sLo >= 3840);
        const bool snHi = (sHi < 256) || (sHi >= 3840);
        const float twLo = (snLo ? 1.0f : triLo) * Al[m0 + g];
        const float twHi = (snHi ? 1.0f : triHi) * Al[m0 + g + 8];
#pragma unroll
        for (int nt = 0; nt < 8; ++nt) {
            int dc = on0 + (nt << 3) + (tq << 1);
            *(float2*)(dLo + dc) = make_float2(oacc[nt][0] * twLo, oacc[nt][1] * twLo);
            *(float2*)(dHi + dc) = make_float2(oacc[nt][2] * twHi, oacc[nt][3] * twHi);
        }
    } else {
        const float twLo = triLo * Al[m0 + g];
        const float twHi = triHi * Al[m0 + g + 8];
        const float ivLo = invden(sLo), ivHi = invden(sHi);
#pragma unroll
        for (int nt = 0; nt < 8; ++nt) {
            int dc = on0 + (nt << 3) + (tq << 1);
            float2 o = *(float2*)(dLo + dc);
            o.x = (o.x + oacc[nt][0] * twLo) * ivLo;
            o.y = (o.y + oacc[nt][1] * twLo) * ivLo;
            *(float2*)(dLo + dc) = o;
            float2 p = *(float2*)(dHi + dc);
            p.x = (p.x + oacc[nt][2] * twHi) * ivHi;
            p.y = (p.y + oacc[nt][3] * twHi) * ivHi;
            *(float2*)(dHi + dc) = p;
        }
    }
}

// ============ 4) compressed-global attention (TC) ============
__global__ void __launch_bounds__(256) gattn(
        const float* __restrict__ x, const float* __restrict__ gmem,
        const float* __restrict__ comp, float* __restrict__ G) {
    extern __shared__ float sm[];
    float* KVs = sm;
    float* Qs  = sm + 16896;
    float* Ps  = sm + 21120;
    const int tid = threadIdx.x;
    const int lane = tid & 31, wid = tid >> 5;
    const int g = lane >> 2, tq = lane & 3;
    const int s0 = blockIdx.x << 5, h = blockIdx.y, b = blockIdx.z;

#pragma unroll
    for (int it = 0; it < 16; ++it) {
        int i = tid + (it << 8);
        int r = i >> 5, c4 = (i & 31) << 2;
        float4 v;
        if (r < 64) v = *(const float4*)(comp + (size_t)((b << 6) + r) * 1024u + (h << 7) + c4);
        else        v = *(const float4*)(gmem + (size_t)((h << 6) + (r - 64)) * 128u + c4);
        float* kv = &KVs[r * 132 + c4];
        kv[0] = f2tff(v.x); kv[1] = f2tff(v.y); kv[2] = f2tff(v.z); kv[3] = f2tff(v.w);
    }
#pragma unroll
    for (int it = 0; it < 4; ++it) {
        int i = tid + (it << 8);
        int r = i >> 5, c4 = (i & 31) << 2;
        float4 v = *(const float4*)(x + (size_t)b * 4194304u + (size_t)(s0 + r) * 1024u + (h << 7) + c4);
        float* q = &Qs[r * 132 + c4];
        q[0] = f2tff(v.x); q[1] = f2tff(v.y); q[2] = f2tff(v.z); q[3] = f2tff(v.w);
    }
    __syncthreads();

    const int wm = wid & 1, wn = wid >> 1;
    const int m0 = wm << 4;
    const int tn0 = wn << 5;
    const float scale = 0.08838834764831845f;

    {
        float sacc[4][4];
#pragma unroll
        for (int nt = 0; nt < 4; ++nt)
#pragma unroll
            for (int e = 0; e < 4; ++e) sacc[nt][e] = 0.f;
#pragma unroll
        for (int kd = 0; kd < 128; kd += 8) {
            uint32_t a[4];
            a[0] = __float_as_uint(Qs[(m0 + g) * 132 + kd + tq]);
            a[1] = __float_as_uint(Qs[(m0 + g + 8) * 132 + kd + tq]);
            a[2] = __float_as_uint(Qs[(m0 + g) * 132 + kd + tq + 4]);
            a[3] = __float_as_uint(Qs[(m0 + g + 8) * 132 + kd + tq + 4]);
#pragma unroll
            for (int nt = 0; nt < 4; ++nt) {
                int tcol = tn0 + (nt << 3) + g;
                uint32_t bb[2];
                bb[0] = __float_as_uint(KVs[tcol * 132 + kd + tq]);
                bb[1] = __float_as_uint(KVs[tcol * 132 + kd + tq + 4]);
                mma8(sacc[nt], a, bb);
            }
        }
#pragma unroll
        for (int nt = 0; nt < 4; ++nt) {
            int nc = tn0 + (nt << 3) + (tq << 1);
            *(float2*)&Ps[(m0 + g) * 132 + nc] =
                make_float2(sacc[nt][0] * scale, sacc[nt][1] * scale);
            *(float2*)&Ps[(m0 + g + 8) * 132 + nc] =
                make_float2(sacc[nt][2] * scale, sacc[nt][3] * scale);
        }
    }
    __syncthreads();

    {
        int row = tid >> 3, seg8 = tid & 7;
        float* pr = &Ps[row * 132 + (seg8 << 4)];
        float mt = -1e30f;
        float pv[16];
#pragma unroll
        for (int jj = 0; jj < 16; ++jj) mt = fmaxf(mt, pr[jj]);
        mt = fmaxf(mt, __shfl_xor_sync(0xffffffffu, mt, 1));
        mt = fmaxf(mt, __shfl_xor_sync(0xffffffffu, mt, 2));
        mt = fmaxf(mt, __shfl_xor_sync(0xffffffffu, mt, 4));
        float ssum = 0.f;
#pragma unroll
        for (int jj = 0; jj < 16; ++jj) { pv[jj] = __expf(pr[jj] - mt); ssum += pv[jj]; }
        ssum += __shfl_xor_sync(0xffffffffu, ssum, 1);
        ssum += __shfl_xor_sync(0xffffffffu, ssum, 2);
        ssum += __shfl_xor_sync(0xffffffffu, ssum, 4);
        float invs = 1.0f / ssum;
#pragma unroll
        for (int jj = 0; jj < 16; ++jj) pr[jj] = f2tff(pv[jj] * invs);
    }
    __syncthreads();

    {
        float oacc[4][4];
#pragma unroll
        for (int nt = 0; nt < 4; ++nt)
#pragma unroll
            for (int e = 0; e < 4; ++e) oacc[nt][e] = 0.f;
#pragma unroll
        for (int kd = 0; kd < 128; kd += 8) {
            uint32_t a[4];
            a[0] = __float_as_uint(Ps[(m0 + g) * 132 + kd + tq]);
            a[1] = __float_as_uint(Ps[(m0 + g + 8) * 132 + kd + tq]);
            a[2] = __float_as_uint(Ps[(m0 + g) * 132 + kd + tq + 4]);
            a[3] = __float_as_uint(Ps[(m0 + g + 8) * 132 + kd + tq + 4]);
#pragma unroll
            for (int nt = 0; nt < 4; ++nt) {
                int dcol = tn0 + (nt << 3) + g;
                uint32_t bb[2];
                bb[0] = __float_as_uint(KVs[(kd + tq) * 132 + dcol]);
                bb[1] = __float_as_uint(KVs[(kd + tq + 4) * 132 + dcol]);
                mma8(oacc[nt], a, bb);
            }
        }
        float* gLo = G + ((size_t)b * 4096u + s0 + m0 + g) * 1024u + (h << 7);
        float* gHi = gLo + (size_t)8 * 1024u;
#pragma unroll
        for (int nt = 0; nt < 4; ++nt) {
            int nc = tn0 + (nt << 3) + (tq << 1);
            *(float2*)(gLo + nc) = make_float2(oacc[nt][0], oacc[nt][1]);
            *(float2*)(gHi + nc) = make_float2(oacc[nt][2], oacc[nt][3]);
        }
    }
}

// ============ 5+6) fp16 GEMM: 128x128 tile, m16n8k16, 3-stage cp.async ============
// stage: A[128][40]h (5120) + B[128][40]h (5120) = 10240 halves = 20480 B
__global__ void __launch_bounds__(256) gemm_fp16(
        int mode, const __half* __restrict__ Ah0, const __half* __restrict__ Ah1,
        const float* __restrict__ Lf, const float* __restrict__ Gf,
        const float* __restrict__ BCp, const __half* __restrict__ WT,
        const float* __restrict__ bias, float* __restrict__ Cf,
        __half* __restrict__ Ch, int K) {
    extern __shared__ __half hsm[];
    const int tid = threadIdx.x;
    const int m0 = blockIdx.x << 7, n0 = blockIdx.y << 7;
    const int wid = tid >> 5, lane = tid & 31;
    const int quad = lane >> 2, tq = lane & 3;
    const int wm = wid >> 2, wn = wid & 3;
    const int arow = tid >> 1, aseg = (tid & 1) << 4;
    const uint32_t sbase = smem_u32(hsm);

    auto issue = [&](int kt, int slot) {
        uint32_t aoff = sbase + (uint32_t)(slot * 10240 + arow * 40 + aseg) * 2u;
        const __half* asrc = (mode == 1 && kt >= 1024)
            ? (Ah1 + (size_t)(m0 + arow) * 1024u + (kt - 1024) + aseg)
            : (Ah0 + (size_t)(m0 + arow) * 1024u + kt + aseg);
        CP16(aoff, asrc); CP16(aoff + 16, asrc + 8);
        uint32_t boff = sbase + (uint32_t)(slot * 10240 + 5120 + arow * 40 + aseg) * 2u;
        const __half* bsrc = WT + (size_t)(n0 + arow) * (size_t)K + kt + aseg;
        CP16(boff, bsrc); CP16(boff + 16, bsrc + 8);
        CPCOMMIT();
    };

    float acc[4][4][4];
#pragma unroll
    for (int i = 0; i < 4; ++i)
#pragma unroll
        for (int j = 0; j < 4; ++j)
#pragma unroll
            for (int e = 0; e < 4; ++e) acc[i][j][e] = 0.f;

    issue(0, 0);
    issue(32, 1);

    for (int kt = 0; kt < K; kt += 32) {
        CPWAIT1();
        __syncthreads();
        int nk = kt + 64;
        if (nk < K) issue(nk, ((kt >> 5) + 2) % 3);
        else        CPCOMMIT();

        const __half* Asb = hsm + ((kt >> 5) % 3) * 10240;
        const __half* Bsb = Asb + 5120;
#pragma unroll
        for (int ks = 0; ks < 2; ++ks) {
            const int k0 = ks << 4;
            uint32_t af[4][4], bf[4][2];
#pragma unroll
            for (int i = 0; i < 4; ++i) {
                int r = (wm << 6) + (i << 4) + quad;
                af[i][0] = *(const uint32_t*)&Asb[r * 40 + k0 + (tq << 1)];
                af[i][1] = *(const uint32_t*)&Asb[(r + 8) * 40 + k0 + (tq << 1)];
                af[i][2] = *(const uint32_t*)&Asb[r * 40 + k0 + (tq << 1) + 8];
                af[i][3] = *(const uint32_t*)&Asb[(r + 8) * 40 + k0 + (tq << 1) + 8];
            }
#pragma unroll
            for (int j = 0; j < 4; ++j) {
                int cidx = (wn << 5) + (j << 3) + quad;
                bf[j][0] = *(const uint32_t*)&Bsb[cidx * 40 + k0 + (tq << 1)];
                bf[j][1] = *(const uint32_t*)&Bsb[cidx * 40 + k0 + (tq << 1) + 8];
            }
#pragma unroll
            for (int i = 0; i < 4; ++i)
#pragma unroll
                for (int j = 0; j < 4; ++j) mma16h(acc[i][j], af[i], bf[j]);
        }
    }

#pragma unroll
    for (int i = 0; i < 4; ++i)
#pragma unroll
        for (int j = 0; j < 4; ++j) {
            int mr = m0 + (wm << 6) + (i << 4) + quad;
            int nc = n0 + (wn << 5) + (j << 3) + (tq << 1);
#pragma unroll
            for (int hf = 0; hf < 2; ++hf) {
                int m = mr + (hf << 3);
                size_t bix = (size_t)m * 1024u + nc;
#pragma unroll
                for (int e = 0; e < 2; ++e) {
                    float z = acc[i][j][(hf << 1) + e] + bias[nc + e];
                    if (mode == 1) {
                        float gg = 1.0f / (1.0f + __expf(-z));
                        float mval = gg * Lf[bix + e] + (1.0f - gg) * Gf[bix + e] + BCp[bix + e];
                        Ch[bix + e] = __float2half_rn(mval);
                    } else {
                        Cf[bix + e] = z;
                    }
                }
            }
        }
}

// =====================================================================
extern "C" void kernel_launch(void* const* d_in, const int* in_sizes, int n_in,
                              void* d_out, int out_size) {
    const float* x    = (const float*)d_in[0];
    const float* gmem = (const float*)d_in[1];
    const float* cw   = (const float*)d_in[2];
    const float* cb   = (const float*)d_in[3];
    const float* mw   = (const float*)d_in[4];
    const float* mb   = (const float*)d_in[5];
    const float* ow   = (const float*)d_in[6];
    const float* ob   = (const float*)d_in[7];
    float* out = (float*)d_out;

    float *pL, *pG, *pBC, *pCOMP, *pXC, *pCP;
    __half *pLh, *pGh, *pMh, *pW1h, *pW2h;
    cudaGetSymbolAddress((void**)&pL,    g_L);
    cudaGetSymbolAddress((void**)&pG,    g_G);
    cudaGetSymbolAddress((void**)&pBC,   g_BC);
    cudaGetSymbolAddress((void**)&pCOMP, g_COMP);
    cudaGetSymbolAddress((void**)&pXC,   g_XC);
    cudaGetSymbolAddress((void**)&pCP,   g_CP);
    cudaGetSymbolAddress((void**)&pLh,   g_Lh);
    cudaGetSymbolAddress((void**)&pGh,   g_Gh);
    cudaGetSymbolAddress((void**)&pMh,   g_Mh);
    cudaGetSymbolAddress((void**)&pW1h,  g_W1h);
    cudaGetSymbolAddress((void**)&pW2h,  g_W2h);

    static cudaStream_t s1 = nullptr, s2 = nullptr, s3 = nullptr;
    static cudaEvent_t evR = nullptr, ev1 = nullptr, ev2 = nullptr, ev3 = nullptr;
    if (s1 == nullptr) {
        cudaStreamCreateWithFlags(&s1, cudaStreamNonBlocking);
        cudaStreamCreateWithFlags(&s2, cudaStreamNonBlocking);
        cudaStreamCreateWithFlags(&s3, cudaStreamNonBlocking);
        cudaEventCreateWithFlags(&evR, cudaEventDisableTiming);
        cudaEventCreateWithFlags(&ev1, cudaEventDisableTiming);
        cudaEventCreateWithFlags(&ev2, cudaEventDisableTiming);
        cudaEventCreateWithFlags(&ev3, cudaEventDisableTiming);
    }

    const int BC_SMEM = 2 * 16384 * 4;
    const int WA_SMEM = 21312 * 4;
    const int GA_SMEM = 25344 * 4;
    const int GH_SMEM = 3 * 10240 * 2;     // 61440 B
    const int CV_SMEM = 3 * 9216 * 4;
    cudaFuncSetAttribute(bc_kernel, cudaFuncAttributeMaxDynamicSharedMemorySize, BC_SMEM);
    cudaFuncSetAttribute(win_attn,  cudaFuncAttributeMaxDynamicSharedMemorySize, WA_SMEM);
    cudaFuncSetAttribute(gattn,     cudaFuncAttributeMaxDynamicSharedMemorySize, GA_SMEM);
    cudaFuncSetAttribute(gemm_fp16, cudaFuncAttributeMaxDynamicSharedMemorySize, GH_SMEM);
    cudaFuncSetAttribute(conv_gemm, cudaFuncAttributeMaxDynamicSharedMemorySize, CV_SMEM);

    cudaEventRecord(evR, 0);
    cudaStreamWaitEvent(s1, evR, 0);
    cudaStreamWaitEvent(s2, evR, 0);
    cudaStreamWaitEvent(s3, evR, 0);

    wthalf     <<<dim3(64, 32), 256, 0, s1>>>(mw, pW1h, 2048);
    wthalf     <<<dim3(32, 32), 256, 0, s1>>>(ow, pW2h, 1024);
    bc_kernel  <<<dim3(256, 2), 512, BC_SMEM, s1>>>(x, pBC);

    xc_kernel  <<<dim3(256, 2), 256, 0, s2>>>(x, pXC);
    conv_gemm  <<<dim3(8, 4), 256, CV_SMEM, s2>>>(pXC, cw, pCP);
    conv_reduce<<<128, 256, 0, s2>>>(pCP, cb, pCOMP);
    gattn      <<<dim3(128, 8, 2), 256, GA_SMEM, s2>>>(x, gmem, pCOMP, pG);
    tohalf     <<<4096, 256, 0, s2>>>(pG, pGh);

    win_attn   <<<dim3(8, 8, 16), 256, WA_SMEM, s3>>>(x, pL, 0);
    win_attn   <<<dim3(8, 7, 16), 256, WA_SMEM, s3>>>(x, pL, 1);
    tohalf     <<<4096, 256, 0, s3>>>(pL, pLh);

    cudaEventRecord(ev1, s1);
    cudaEventRecord(ev2, s2);
    cudaEventRecord(ev3, s3);
    cudaStreamWaitEvent(0, ev1, 0);
    cudaStreamWaitEvent(0, ev2, 0);
    cudaStreamWaitEvent(0, ev3, 0);

    gemm_fp16<<<dim3(64, 8), 256, GH_SMEM>>>(
        1, pLh, pGh, pL, pG, pBC, pW1h, mb, out, pMh, 2048);
    gemm_fp16<<<dim3(64, 8), 256, GH_SMEM>>>(
        0, pMh, pMh, pL, pG, pBC, pW2h, ob, out, pMh, 1024);
}

// round 14
// speedup vs baseline: 1.7495x; 1.2352x over previous
#include <cuda_runtime.h>
#include <cuda_fp16.h>
#include <math.h>
#include <stdint.h>

__device__ float g_L [2u*4096u*1024u];
__device__ float g_G [2u*4096u*1024u];
__device__ float g_BC[2u*4096u*1024u];
__device__ float g_COMP[2u*64u*1024u];
__device__ float g_XC[128u*4096u];
__device__ float g_CP[4u*128u*1024u];
__device__ __half g_Lh[2u*4096u*1024u];
__device__ __half g_Gh[2u*4096u*1024u];
__device__ __half g_Mh[2u*4096u*1024u];
__device__ __half g_W1h[1024u*2048u];   // mix_w^T [n][k]
__device__ __half g_W2h[1024u*1024u];   // out_w^T [n][k]

__device__ __forceinline__ float f2tff(float x) {
    uint32_t u; asm("cvt.rn.tf32.f32 %0, %1;" : "=r"(u) : "f"(x));
    return __uint_as_float(u);
}
__device__ __forceinline__ void mma8(float* c, const uint32_t* a, const uint32_t* b) {
    asm volatile("mma.sync.aligned.m16n8k8.row.col.f32.tf32.tf32.f32 "
        "{%0,%1,%2,%3}, {%4,%5,%6,%7}, {%8,%9}, {%0,%1,%2,%3};"
        : "+f"(c[0]), "+f"(c[1]), "+f"(c[2]), "+f"(c[3])
        : "r"(a[0]), "r"(a[1]), "r"(a[2]), "r"(a[3]), "r"(b[0]), "r"(b[1]));
}
__device__ __forceinline__ void mma16h(float* c, const uint32_t* a, const uint32_t* b) {
    asm volatile("mma.sync.aligned.m16n8k16.row.col.f32.f16.f16.f32 "
        "{%0,%1,%2,%3}, {%4,%5,%6,%7}, {%8,%9}, {%0,%1,%2,%3};"
        : "+f"(c[0]), "+f"(c[1]), "+f"(c[2]), "+f"(c[3])
        : "r"(a[0]), "r"(a[1]), "r"(a[2]), "r"(a[3]), "r"(b[0]), "r"(b[1]));
}
#define LDSM_X2_TRANS(r0, r1, addr) \
    asm volatile("ldmatrix.sync.aligned.m8n8.x2.trans.shared.b16 {%0,%1}, [%2];" \
        : "=r"(r0), "=r"(r1) : "r"(addr))
__device__ __forceinline__ uint32_t smem_u32(const void* p) {
    uint32_t a;
    asm("{ .reg .u64 t; cvta.to.shared.u64 t, %1; cvt.u32.u64 %0, t; }" : "=r"(a) : "l"(p));
    return a;
}
#define CP16(dst, src) asm volatile("cp.async.cg.shared.global [%0], [%1], 16;" :: "r"(dst), "l"(src))
#define CPCOMMIT()     asm volatile("cp.async.commit_group;" ::: "memory")
#define CPWAIT1()      asm volatile("cp.async.wait_group 1;" ::: "memory")

__device__ __forceinline__ float invden(int s) {
    int n1 = s >> 8, i1 = s & 255;
    float d = 0.f;
    if (n1 <= 14) d += 0.5f + (float)i1 * (1.0f / 511.0f);
    if (n1 >= 1)  d += 0.5f + (float)(i1 + 256) * (1.0f / 511.0f);
    return 1.0f / d;
}

// ============ 0a) weight transpose -> half, [n][k] K-major ============
__global__ void wthalf(const float* __restrict__ W, __half* __restrict__ WT, int K) {
    __shared__ float tile[32][33];
    const int k0 = blockIdx.x << 5, n0 = blockIdx.y << 5;
    const int tx = threadIdx.x & 31, ty = threadIdx.x >> 5;
#pragma unroll
    for (int i = ty; i < 32; i += 8)
        tile[i][tx] = W[(size_t)(k0 + i) * 1024u + n0 + tx];
    __syncthreads();
#pragma unroll
    for (int i = ty; i < 32; i += 8)
        WT[(size_t)(n0 + i) * (size_t)K + k0 + tx] = __float2half_rn(tile[tx][i]);
}

// ============ 0b) fp32 -> fp16 convert ============
__global__ void tohalf(const float* __restrict__ S, __half* __restrict__ D) {
    size_t i = ((size_t)blockIdx.x * blockDim.x + threadIdx.x) << 3;
    float4 a = *(const float4*)(S + i);
    float4 b = *(const float4*)(S + i + 4);
    __half2 h0 = __floats2half2_rn(a.x, a.y);
    __half2 h1 = __floats2half2_rn(a.z, a.w);
    __half2 h2 = __floats2half2_rn(b.x, b.y);
    __half2 h3 = __floats2half2_rn(b.z, b.w);
    uint4 o;
    o.x = *(uint32_t*)&h0; o.y = *(uint32_t*)&h1;
    o.z = *(uint32_t*)&h2; o.w = *(uint32_t*)&h3;
    *(uint4*)(D + i) = o;
}

// ============ 1) broadcast diffusion (conflict-free planes) ============
__global__ void bc_kernel(const float* __restrict__ x, float* __restrict__ bc) {
    extern __shared__ float sm[];
    const int tid = threadIdx.x, b = blockIdx.y, d0 = blockIdx.x << 2;
    float* bufA = sm; float* bufB = sm + 16384;
    const float* src = x + (size_t)b * 4194304u + d0;
    for (int s = tid; s < 4096; s += 512) {
        float4 v = *(const float4*)(src + (size_t)s * 1024u);
        bufA[s] = v.x; bufA[4096 + s] = v.y; bufA[8192 + s] = v.z; bufA[12288 + s] = v.w;
    }
    __syncthreads();
    float acc[32];
#pragma unroll
    for (int e = 0; e < 32; ++e) acc[e] = 0.f;
    float* cur = bufA; float* nxt = bufB;
    for (int st = 1; st < 4096; st <<= 1) {
#pragma unroll
        for (int q = 0; q < 8; ++q) {
            int s = tid + (q << 9);
            int sm1 = (s - st) & 4095, sp1 = (s + st) & 4095;
#pragma unroll
            for (int j = 0; j < 4; ++j) {
                const float* cj = cur + (j << 12);
                float v = cj[s] + 0.5f * (cj[sm1] + cj[sp1]);
                nxt[(j << 12) + s] = v;
                acc[(q << 2) + j] += v;
            }
        }
        __syncthreads();
        float* t = cur; cur = nxt; nxt = t;
    }
    const float inv = 1.0f / 13.0f;
    float* dst = bc + (size_t)b * 4194304u + d0;
#pragma unroll
    for (int q = 0; q < 8; ++q) {
        int s = tid + (q << 9);
        *(float4*)(dst + (size_t)s * 1024u) =
            make_float4(acc[q*4]*inv, acc[q*4+1]*inv, acc[q*4+2]*inv, acc[q*4+3]*inv);
    }
}

// ============ 2a) conv input gather ============
__global__ void xc_kernel(const float* __restrict__ x, float* __restrict__ Xc) {
    const int s = blockIdx.x;
    const int b = blockIdx.y;
    const int t = s >> 2, j = s & 3;
    const int m = (b << 6) + t;
    const float* src = x + (size_t)b * 4194304u + (size_t)s * 1024u;
    float* dst = Xc + (size_t)m * 4096u + j;
#pragma unroll
    for (int k = 0; k < 4; ++k) {
        int d = threadIdx.x + (k << 8);
        dst[d << 2] = src[d];
    }
}

// ============ 2b) conv GEMM (split-K x4, tf32) ============
__global__ void __launch_bounds__(256) conv_gemm(
        const float* __restrict__ Xc, const float* __restrict__ cwf,
        float* __restrict__ CP) {
    extern __shared__ float gsm[];
    const int tid = threadIdx.x;
    const int n0 = blockIdx.x << 7;
    const int kq = blockIdx.y;
    const int kbase = kq << 10;
    const int wid = tid >> 5, lane = tid & 31;
    const int quad = lane >> 2, tq = lane & 3;
    const int wm = wid >> 2, wn = wid & 3;
    const int am = tid >> 1, ak = (tid & 1) << 4;
    const uint32_t sbase = smem_u32(gsm);

    auto issue = [&](int kt, int slot) {
        uint32_t aoff = sbase + (uint32_t)(slot * 9216 + am * 36 + ak) * 4u;
        const float* asrc = Xc + (size_t)am * 4096u + kbase + kt + ak;
        CP16(aoff, asrc); CP16(aoff + 16, asrc + 4);
        CP16(aoff + 32, asrc + 8); CP16(aoff + 48, asrc + 12);
        uint32_t boff = aoff + 4608u * 4u;
        const float* bsrc = cwf + (size_t)(n0 + am) * 4096u + kbase + kt + ak;
        CP16(boff, bsrc); CP16(boff + 16, bsrc + 4);
        CP16(boff + 32, bsrc + 8); CP16(boff + 48, bsrc + 12);
        CPCOMMIT();
    };

    float acc[4][4][4];
#pragma unroll
    for (int i = 0; i < 4; ++i)
#pragma unroll
        for (int j = 0; j < 4; ++j)
#pragma unroll
            for (int e = 0; e < 4; ++e) acc[i][j][e] = 0.f;

    issue(0, 0);
    issue(32, 1);

    for (int kt = 0; kt < 1024; kt += 32) {
        CPWAIT1();
        __syncthreads();
        int nk = kt + 64;
        if (nk < 1024) issue(nk, ((kt >> 5) + 2) % 3);
        else           CPCOMMIT();

        const float* Asb = gsm + ((kt >> 5) % 3) * 9216;
        const float* Bsb = Asb + 4608;
#pragma unroll
        for (int ks = 0; ks < 4; ++ks) {
            const int k0 = ks << 3;
            uint32_t af[4][4], bf[4][2];
#pragma unroll
            for (int i = 0; i < 4; ++i) {
                int r = (wm << 6) + (i << 4) + quad;
                af[i][0] = __float_as_uint(Asb[r * 36 + k0 + tq]);
                af[i][1] = __float_as_uint(Asb[(r + 8) * 36 + k0 + tq]);
                af[i][2] = __float_as_uint(Asb[r * 36 + k0 + tq + 4]);
                af[i][3] = __float_as_uint(Asb[(r + 8) * 36 + k0 + tq + 4]);
            }
#pragma unroll
            for (int j = 0; j < 4; ++j) {
                int cidx = (wn << 5) + (j << 3) + quad;
                bf[j][0] = __float_as_uint(Bsb[cidx * 36 + k0 + tq]);
                bf[j][1] = __float_as_uint(Bsb[cidx * 36 + k0 + tq + 4]);
            }
#pragma unroll
            for (int i = 0; i < 4; ++i)
#pragma unroll
                for (int j = 0; j < 4; ++j) mma8(acc[i][j], af[i], bf[j]);
        }
    }
    float* cp = CP + (size_t)kq * 131072u;
#pragma unroll
    for (int i = 0; i < 4; ++i)
#pragma unroll
        for (int j = 0; j < 4; ++j) {
            int mr = (wm << 6) + (i << 4) + quad;
            int nc = n0 + (wn << 5) + (j << 3) + (tq << 1);
#pragma unroll
            for (int hf = 0; hf < 2; ++hf) {
                int m = mr + (hf << 3);
                *(float2*)(cp + (size_t)m * 1024u + nc) =
                    make_float2(acc[i][j][(hf << 1)], acc[i][j][(hf << 1) + 1]);
            }
        }
}

// ============ 2c) conv reduce ============
__global__ void conv_reduce(const float* __restrict__ CP, const float* __restrict__ cb,
                            float* __restrict__ comp) {
    int i = (blockIdx.x << 8) + threadIdx.x;
    int o4 = (i & 255) << 2;
    float4 a = *(const float4*)(CP + ((size_t)i << 2));
    float4 b = *(const float4*)(CP + 131072u + ((size_t)i << 2));
    float4 c = *(const float4*)(CP + 262144u + ((size_t)i << 2));
    float4 d = *(const float4*)(CP + 393216u + ((size_t)i << 2));
    float4 e = *(const float4*)(cb + o4);
    *(float4*)(comp + ((size_t)i << 2)) = make_float4(
        a.x + b.x + c.x + d.x + e.x, a.y + b.y + c.y + d.y + e.y,
        a.z + b.z + c.z + d.z + e.z, a.w + b.w + c.w + d.w + e.w);
}

// ============ 3) sliding-window attention v5: fp16 MMA + ldmatrix ============
// smem: Ss float[64*68] (4352) | Al[64] | Qh half[64*136] | Ksh half[64*136] | Ph half[64*72]
__global__ void __launch_bounds__(256) win_attn(
        const float* __restrict__ x, float* __restrict__ L, int parity) {
    extern __shared__ float sm[];
    float* Ss = sm;                       // 4352 floats
    float* Al = sm + 4352;                // 64
    __half* Qh  = (__half*)(sm + 4416);   // 8704 halves
    __half* Ksh = Qh + 8704;              // 8704 halves
    __half* Ph  = Ksh + 8704;             // 4608 halves
    const uint32_t ksh_u32 = smem_u32(Ksh);

    const int tid = threadIdx.x;
    const int lane = tid & 31, wid = tid >> 5;
    const int g = lane >> 2, tq = lane & 3;
    const int qt = blockIdx.x;
    const int n = (blockIdx.y << 1) + parity;
    const int b = blockIdx.z >> 3, h = blockIdx.z & 7;
    const int base = n << 8, q0 = base + (qt << 6);
    const float* xb = x + (size_t)b * 4194304u + (h << 7);

    // load Q -> half
#pragma unroll
    for (int it = 0; it < 8; ++it) {
        int i = tid + (it << 8);
        int r = i >> 5, c4 = (i & 31) << 2;
        float4 v = *(const float4*)(xb + (size_t)(q0 + r) * 1024u + c4);
        __half2 h0 = __floats2half2_rn(v.x, v.y);
        __half2 h1 = __floats2half2_rn(v.z, v.w);
        uint2 w; w.x = *(uint32_t*)&h0; w.y = *(uint32_t*)&h1;
        *(uint2*)&Qh[r * 136 + c4] = w;
    }

    const int wm = wid >> 1, wn = wid & 1;
    const int m0 = wm << 4;
    const int sn0 = wn << 5;
    const int on0 = wn << 6;
    const int srow = tid >> 2, seg = tid & 3;
    const int lrow = (lane & 15) * 136;    // ldmatrix row offset (halves)
    const float scale = 0.08838834764831845f;

    float oacc[8][4];
#pragma unroll
    for (int nt = 0; nt < 8; ++nt)
#pragma unroll
        for (int e = 0; e < 4; ++e) oacc[nt][e] = 0.f;
    float m_i = -1e30f, l_i = 0.f;

    for (int kt = 0; kt < 8; ++kt) {
        __syncthreads();
        const int ktok = base + (kt << 6);
        // K tile -> half, natural [token][d]
#pragma unroll
        for (int it = 0; it < 8; ++it) {
            int i = tid + (it << 8);
            int r = i >> 5, c4 = (i & 31) << 2;
            float4 v = *(const float4*)(xb + (size_t)(ktok + r) * 1024u + c4);
            __half2 h0 = __floats2half2_rn(v.x, v.y);
            __half2 h1 = __floats2half2_rn(v.z, v.w);
            uint2 w; w.x = *(uint32_t*)&h0; w.y = *(uint32_t*)&h1;
            *(uint2*)&Ksh[r * 136 + c4] = w;
        }
        __syncthreads();

        // ---- scores: S(64x64) = Q @ K^T, fp16 m16n8k16 ----
        float sacc[4][4];
#pragma unroll
        for (int nt = 0; nt < 4; ++nt)
#pragma unroll
            for (int e = 0; e < 4; ++e) sacc[nt][e] = 0.f;
#pragma unroll
        for (int kd = 0; kd < 128; kd += 16) {
            uint32_t a[4];
            a[0] = *(const uint32_t*)&Qh[(m0 + g) * 136 + kd + (tq << 1)];
            a[1] = *(const uint32_t*)&Qh[(m0 + g + 8) * 136 + kd + (tq << 1)];
            a[2] = *(const uint32_t*)&Qh[(m0 + g) * 136 + kd + (tq << 1) + 8];
            a[3] = *(const uint32_t*)&Qh[(m0 + g + 8) * 136 + kd + (tq << 1) + 8];
#pragma unroll
            for (int nt = 0; nt < 4; ++nt) {
                int tcol = sn0 + (nt << 3) + g;
                uint32_t bb[2];
                bb[0] = *(const uint32_t*)&Ksh[tcol * 136 + kd + (tq << 1)];
                bb[1] = *(const uint32_t*)&Ksh[tcol * 136 + kd + (tq << 1) + 8];
                mma16h(sacc[nt], a, bb);
            }
        }
#pragma unroll
        for (int nt = 0; nt < 4; ++nt) {
            int nc = sn0 + (nt << 3) + (tq << 1);
            *(float2*)&Ss[(m0 + g) * 68 + nc] =
                make_float2(sacc[nt][0] * scale, sacc[nt][1] * scale);
            *(float2*)&Ss[(m0 + g + 8) * 68 + nc] =
                make_float2(sacc[nt][2] * scale, sacc[nt][3] * scale);
        }
        __syncthreads();

        // ---- online softmax (float); P -> half into Ph ----
        {
            float* sr = &Ss[srow * 68 + (seg << 4)];
            float mt = -1e30f;
            float pv[16];
#pragma unroll
            for (int jj = 0; jj < 16; ++jj) { pv[jj] = sr[jj]; mt = fmaxf(mt, pv[jj]); }
            mt = fmaxf(mt, __shfl_xor_sync(0xffffffffu, mt, 1));
            mt = fmaxf(mt, __shfl_xor_sync(0xffffffffu, mt, 2));
            float m_new = fmaxf(m_i, mt);
            float alpha = __expf(m_i - m_new);
            float ls = 0.f;
#pragma unroll
            for (int jj = 0; jj < 16; ++jj) {
                pv[jj] = __expf(pv[jj] - m_new);
                ls += pv[jj];
            }
            __half* pr = &Ph[srow * 72 + (seg << 4)];
#pragma unroll
            for (int j2 = 0; j2 < 8; ++j2) {
                __half2 hp = __floats2half2_rn(pv[j2 << 1], pv[(j2 << 1) + 1]);
                *(__half2*)&pr[j2 << 1] = hp;
            }
            ls += __shfl_xor_sync(0xffffffffu, ls, 1);
            ls += __shfl_xor_sync(0xffffffffu, ls, 2);
            l_i = l_i * alpha + ls;
            m_i = m_new;
            if (seg == 0) Al[srow] = alpha;
        }
        __syncthreads();

        // ---- AV: O(64x128) += P @ V  (A from Ph, B via ldmatrix.trans on Ksh) ----
        float aLo = Al[m0 + g], aHi = Al[m0 + g + 8];
#pragma unroll
        for (int nt = 0; nt < 8; ++nt) {
            oacc[nt][0] *= aLo; oacc[nt][1] *= aLo;
            oacc[nt][2] *= aHi; oacc[nt][3] *= aHi;
        }
#pragma unroll
        for (int kd = 0; kd < 64; kd += 16) {
            uint32_t a[4];
            a[0] = *(const uint32_t*)&Ph[(m0 + g) * 72 + kd + (tq << 1)];
            a[1] = *(const uint32_t*)&Ph[(m0 + g + 8) * 72 + kd + (tq << 1)];
            a[2] = *(const uint32_t*)&Ph[(m0 + g) * 72 + kd + (tq << 1) + 8];
            a[3] = *(const uint32_t*)&Ph[(m0 + g + 8) * 72 + kd + (tq << 1) + 8];
            uint32_t rowa = ksh_u32 + (uint32_t)(((kd * 136) + lrow) << 1);
#pragma unroll
            for (int nt = 0; nt < 8; ++nt) {
                uint32_t bb[2];
                uint32_t addr = rowa + (uint32_t)((on0 + (nt << 3)) << 1);
                LDSM_X2_TRANS(bb[0], bb[1], addr);
                mma16h(oacc[nt], a, bb);
            }
        }
    }
    __syncthreads();
    if (seg == 0) Al[srow] = 1.0f / l_i;
    __syncthreads();

    const int iwLo = (qt << 6) + m0 + g;
    const int iwHi = iwLo + 8;
    const int sLo = base + iwLo, sHi = base + iwHi;
    const float triLo = 0.5f + (float)iwLo * (1.0f / 511.0f);
    const float triHi = 0.5f + (float)iwHi * (1.0f / 511.0f);
    float* dLo = L + ((size_t)b * 4096u + sLo) * 1024u + (h << 7);
    float* dHi = dLo + (size_t)8 * 1024u;
    if (parity == 0) {
        const bool snLo = (sLo < 256) || (sLo >= 3840);
        const bool snHi = (sHi < 256) || (sHi >= 3840);
        const float twLo = (snLo ? 1.0f : triLo) * Al[m0 + g];
        const float twHi = (snHi ? 1.0f : triHi) * Al[m0 + g + 8];
#pragma unroll
        for (int nt = 0; nt < 8; ++nt) {
            int dc = on0 + (nt << 3) + (tq << 1);
            *(float2*)(dLo + dc) = make_float2(oacc[nt][0] * twLo, oacc[nt][1] * twLo);
            *(float2*)(dHi + dc) = make_float2(oacc[nt][2] * twHi, oacc[nt][3] * twHi);
        }
    } else {
        const float twLo = triLo * Al[m0 + g];
        const float twHi = triHi * Al[m0 + g + 8];
        const float ivLo = invden(sLo), ivHi = invden(sHi);
#pragma unroll
        for (int nt = 0; nt < 8; ++nt) {
            int dc = on0 + (nt << 3) + (tq << 1);
            float2 o = *(float2*)(dLo + dc);
            o.x = (o.x + oacc[nt][0] * twLo) * ivLo;
            o.y = (o.y + oacc[nt][1] * twLo) * ivLo;
            *(float2*)(dLo + dc) = o;
            float2 p = *(float2*)(dHi + dc);
            p.x = (p.x + oacc[nt][2] * twHi) * ivHi;
            p.y = (p.y + oacc[nt][3] * twHi) * ivHi;
            *(float2*)(dHi + dc) = p;
        }
    }
}

// ============ 4) compressed-global attention (TC tf32) ============
__global__ void __launch_bounds__(256) gattn(
        const float* __restrict__ x, const float* __restrict__ gmem,
        const float* __restrict__ comp, float* __restrict__ G) {
    extern __shared__ float sm[];
    float* KVs = sm;
    float* Qs  = sm + 16896;
    float* Ps  = sm + 21120;
    const int tid = threadIdx.x;
    const int lane = tid & 31, wid = tid >> 5;
    const int g = lane >> 2, tq = lane & 3;
    const int s0 = blockIdx.x << 5, h = blockIdx.y, b = blockIdx.z;

#pragma unroll
    for (int it = 0; it < 16; ++it) {
        int i = tid + (it << 8);
        int r = i >> 5, c4 = (i & 31) << 2;
        float4 v;
        if (r < 64) v = *(const float4*)(comp + (size_t)((b << 6) + r) * 1024u + (h << 7) + c4);
        else        v = *(const float4*)(gmem + (size_t)((h << 6) + (r - 64)) * 128u + c4);
        float* kv = &KVs[r * 132 + c4];
        kv[0] = f2tff(v.x); kv[1] = f2tff(v.y); kv[2] = f2tff(v.z); kv[3] = f2tff(v.w);
    }
#pragma unroll
    for (int it = 0; it < 4; ++it) {
        int i = tid + (it << 8);
        int r = i >> 5, c4 = (i & 31) << 2;
        float4 v = *(const float4*)(x + (size_t)b * 4194304u + (size_t)(s0 + r) * 1024u + (h << 7) + c4);
        float* q = &Qs[r * 132 + c4];
        q[0] = f2tff(v.x); q[1] = f2tff(v.y); q[2] = f2tff(v.z); q[3] = f2tff(v.w);
    }
    __syncthreads();

    const int wm = wid & 1, wn = wid >> 1;
    const int m0 = wm << 4;
    const int tn0 = wn << 5;
    const float scale = 0.08838834764831845f;

    {
        float sacc[4][4];
#pragma unroll
        for (int nt = 0; nt < 4; ++nt)
#pragma unroll
            for (int e = 0; e < 4; ++e) sacc[nt][e] = 0.f;
#pragma unroll
        for (int kd = 0; kd < 128; kd += 8) {
            uint32_t a[4];
            a[0] = __float_as_uint(Qs[(m0 + g) * 132 + kd + tq]);
            a[1] = __float_as_uint(Qs[(m0 + g + 8) * 132 + kd + tq]);
            a[2] = __float_as_uint(Qs[(m0 + g) * 132 + kd + tq + 4]);
            a[3] = __float_as_uint(Qs[(m0 + g + 8) * 132 + kd + tq + 4]);
#pragma unroll
            for (int nt = 0; nt < 4; ++nt) {
                int tcol = tn0 + (nt << 3) + g;
                uint32_t bb[2];
                bb[0] = __float_as_uint(KVs[tcol * 132 + kd + tq]);
                bb[1] = __float_as_uint(KVs[tcol * 132 + kd + tq + 4]);
                mma8(sacc[nt], a, bb);
            }
        }
#pragma unroll
        for (int nt = 0; nt < 4; ++nt) {
            int nc = tn0 + (nt << 3) + (tq << 1);
            *(float2*)&Ps[(m0 + g) * 132 + nc] =
                make_float2(sacc[nt][0] * scale, sacc[nt][1] * scale);
            *(float2*)&Ps[(m0 + g + 8) * 132 + nc] =
                make_float2(sacc[nt][2] * scale, sacc[nt][3] * scale);
        }
    }
    __syncthreads();

    {
        int row = tid >> 3, seg8 = tid & 7;
        float* pr = &Ps[row * 132 + (seg8 << 4)];
        float mt = -1e30f;
        float pv[16];
#pragma unroll
        for (int jj = 0; jj < 16; ++jj) mt = fmaxf(mt, pr[jj]);
        mt = fmaxf(mt, __shfl_xor_sync(0xffffffffu, mt, 1));
        mt = fmaxf(mt, __shfl_xor_sync(0xffffffffu, mt, 2));
        mt = fmaxf(mt, __shfl_xor_sync(0xffffffffu, mt, 4));
        float ssum = 0.f;
#pragma unroll
        for (int jj = 0; jj < 16; ++jj) { pv[jj] = __expf(pr[jj] - mt); ssum += pv[jj]; }
        ssum += __shfl_xor_sync(0xffffffffu, ssum, 1);
        ssum += __shfl_xor_sync(0xffffffffu, ssum, 2);
        ssum += __shfl_xor_sync(0xffffffffu, ssum, 4);
        float invs = 1.0f / ssum;
#pragma unroll
        for (int jj = 0; jj < 16; ++jj) pr[jj] = f2tff(pv[jj] * invs);
    }
    __syncthreads();

    {
        float oacc[4][4];
#pragma unroll
        for (int nt = 0; nt < 4; ++nt)
#pragma unroll
            for (int e = 0; e < 4; ++e) oacc[nt][e] = 0.f;
#pragma unroll
        for (int kd = 0; kd < 128; kd += 8) {
            uint32_t a[4];
            a[0] = __float_as_uint(Ps[(m0 + g) * 132 + kd + tq]);
            a[1] = __float_as_uint(Ps[(m0 + g + 8) * 132 + kd + tq]);
            a[2] = __float_as_uint(Ps[(m0 + g) * 132 + kd + tq + 4]);
            a[3] = __float_as_uint(Ps[(m0 + g + 8) * 132 + kd + tq + 4]);
#pragma unroll
            for (int nt = 0; nt < 4; ++nt) {
                int dcol = tn0 + (nt << 3) + g;
                uint32_t bb[2];
                bb[0] = __float_as_uint(KVs[(kd + tq) * 132 + dcol]);
                bb[1] = __float_as_uint(KVs[(kd + tq + 4) * 132 + dcol]);
                mma8(oacc[nt], a, bb);
            }
        }
        float* gLo = G + ((size_t)b * 4096u + s0 + m0 + g) * 1024u + (h << 7);
        float* gHi = gLo + (size_t)8 * 1024u;
#pragma unroll
        for (int nt = 0; nt < 4; ++nt) {
            int nc = tn0 + (nt << 3) + (tq << 1);
            *(float2*)(gLo + nc) = make_float2(oacc[nt][0], oacc[nt][1]);
            *(float2*)(gHi + nc) = make_float2(oacc[nt][2], oacc[nt][3]);
        }
    }
}

// ============ 5+6) fp16 GEMM: 128x128 tile, m16n8k16, 3-stage cp.async ============
__global__ void __launch_bounds__(256) gemm_fp16(
        int mode, const __half* __restrict__ Ah0, const __half* __restrict__ Ah1,
        const float* __restrict__ Lf, const float* __restrict__ Gf,
        const float* __restrict__ BCp, const __half* __restrict__ WT,
        const float* __restrict__ bias, float* __restrict__ Cf,
        __half* __restrict__ Ch, int K) {
    extern __shared__ __half hsm[];
    const int tid = threadIdx.x;
    const int m0 = blockIdx.x << 7, n0 = blockIdx.y << 7;
    const int wid = tid >> 5, lane = tid & 31;
    const int quad = lane >> 2, tq = lane & 3;
    const int wm = wid >> 2, wn = wid & 3;
    const int arow = tid >> 1, aseg = (tid & 1) << 4;
    const uint32_t sbase = smem_u32(hsm);

    auto issue = [&](int kt, int slot) {
        uint32_t aoff = sbase + (uint32_t)(slot * 10240 + arow * 40 + aseg) * 2u;
        const __half* asrc = (mode == 1 && kt >= 1024)
            ? (Ah1 + (size_t)(m0 + arow) * 1024u + (kt - 1024) + aseg)
            : (Ah0 + (size_t)(m0 + arow) * 1024u + kt + aseg);
        CP16(aoff, asrc); CP16(aoff + 16, asrc + 8);
        uint32_t boff = sbase + (uint32_t)(slot * 10240 + 5120 + arow * 40 + aseg) * 2u;
        const __half* bsrc = WT + (size_t)(n0 + arow) * (size_t)K + kt + aseg;
        CP16(boff, bsrc); CP16(boff + 16, bsrc + 8);
        CPCOMMIT();
    };

    float acc[4][4][4];
#pragma unroll
    for (int i = 0; i < 4; ++i)
#pragma unroll
        for (int j = 0; j < 4; ++j)
#pragma unroll
            for (int e = 0; e < 4; ++e) acc[i][j][e] = 0.f;

    issue(0, 0);
    issue(32, 1);

    for (int kt = 0; kt < K; kt += 32) {
        CPWAIT1();
        __syncthreads();
        int nk = kt + 64;
        if (nk < K) issue(nk, ((kt >> 5) + 2) % 3);
        else        CPCOMMIT();

        const __half* Asb = hsm + ((kt >> 5) % 3) * 10240;
        const __half* Bsb = Asb + 5120;
#pragma unroll
        for (int ks = 0; ks < 2; ++ks) {
            const int k0 = ks << 4;
            uint32_t af[4][4], bf[4][2];
#pragma unroll
            for (int i = 0; i < 4; ++i) {
                int r = (wm << 6) + (i << 4) + quad;
                af[i][0] = *(const uint32_t*)&Asb[r * 40 + k0 + (tq << 1)];
                af[i][1] = *(const uint32_t*)&Asb[(r + 8) * 40 + k0 + (tq << 1)];
                af[i][2] = *(const uint32_t*)&Asb[r * 40 + k0 + (tq << 1) + 8];
                af[i][3] = *(const uint32_t*)&Asb[(r + 8) * 40 + k0 + (tq << 1) + 8];
            }
#pragma unroll
            for (int j = 0; j < 4; ++j) {
                int cidx = (wn << 5) + (j << 3) + quad;
                bf[j][0] = *(const uint32_t*)&Bsb[cidx * 40 + k0 + (tq << 1)];
                bf[j][1] = *(const uint32_t*)&Bsb[cidx * 40 + k0 + (tq << 1) + 8];
            }
#pragma unroll
            for (int i = 0; i < 4; ++i)
#pragma unroll
                for (int j = 0; j < 4; ++j) mma16h(acc[i][j], af[i], bf[j]);
        }
    }

#pragma unroll
    for (int i = 0; i < 4; ++i)
#pragma unroll
        for (int j = 0; j < 4; ++j) {
            int mr = m0 + (wm << 6) + (i << 4) + quad;
            int nc = n0 + (wn << 5) + (j << 3) + (tq << 1);
#pragma unroll
            for (int hf = 0; hf < 2; ++hf) {
                int m = mr + (hf << 3);
                size_t bix = (size_t)m * 1024u + nc;
#pragma unroll
                for (int e = 0; e < 2; ++e) {
                    float z = acc[i][j][(hf << 1) + e] + bias[nc + e];
                    if (mode == 1) {
                        float gg = 1.0f / (1.0f + __expf(-z));
                        float mval = gg * Lf[bix + e] + (1.0f - gg) * Gf[bix + e] + BCp[bix + e];
                        Ch[bix + e] = __float2half_rn(mval);
                    } else {
                        Cf[bix + e] = z;
                    }
                }
            }
        }
}

// =====================================================================
extern "C" void kernel_launch(void* const* d_in, const int* in_sizes, int n_in,
                              void* d_out, int out_size) {
    const float* x    = (const float*)d_in[0];
    const float* gmem = (const float*)d_in[1];
    const float* cw   = (const float*)d_in[2];
    const float* cb   = (const float*)d_in[3];
    const float* mw   = (const float*)d_in[4];
    const float* mb   = (const float*)d_in[5];
    const float* ow   = (const float*)d_in[6];
    const float* ob   = (const float*)d_in[7];
    float* out = (float*)d_out;

    float *pL, *pG, *pBC, *pCOMP, *pXC, *pCP;
    __half *pLh, *pGh, *pMh, *pW1h, *pW2h;
    cudaGetSymbolAddress((void**)&pL,    g_L);
    cudaGetSymbolAddress((void**)&pG,    g_G);
    cudaGetSymbolAddress((void**)&pBC,   g_BC);
    cudaGetSymbolAddress((void**)&pCOMP, g_COMP);
    cudaGetSymbolAddress((void**)&pXC,   g_XC);
    cudaGetSymbolAddress((void**)&pCP,   g_CP);
    cudaGetSymbolAddress((void**)&pLh,   g_Lh);
    cudaGetSymbolAddress((void**)&pGh,   g_Gh);
    cudaGetSymbolAddress((void**)&pMh,   g_Mh);
    cudaGetSymbolAddress((void**)&pW1h,  g_W1h);
    cudaGetSymbolAddress((void**)&pW2h,  g_W2h);

    static cudaStream_t s1 = nullptr, s2 = nullptr, s3 = nullptr;
    static cudaEvent_t evR = nullptr, ev1 = nullptr, ev2 = nullptr, ev3 = nullptr;
    if (s1 == nullptr) {
        cudaStreamCreateWithFlags(&s1, cudaStreamNonBlocking);
        cudaStreamCreateWithFlags(&s2, cudaStreamNonBlocking);
        cudaStreamCreateWithFlags(&s3, cudaStreamNonBlocking);
        cudaEventCreateWithFlags(&evR, cudaEventDisableTiming);
        cudaEventCreateWithFlags(&ev1, cudaEventDisableTiming);
        cudaEventCreateWithFlags(&ev2, cudaEventDisableTiming);
        cudaEventCreateWithFlags(&ev3, cudaEventDisableTiming);
    }

    const int BC_SMEM = 2 * 16384 * 4;
    const int WA_SMEM = 61696;             // new fp16 win_attn layout
    const int GA_SMEM = 25344 * 4;
    const int GH_SMEM = 3 * 10240 * 2;
    const int CV_SMEM = 3 * 9216 * 4;
    cudaFuncSetAttribute(bc_kernel, cudaFuncAttributeMaxDynamicSharedMemorySize, BC_SMEM);
    cudaFuncSetAttribute(win_attn,  cudaFuncAttributeMaxDynamicSharedMemorySize, WA_SMEM);
    cudaFuncSetAttribute(gattn,     cudaFuncAttributeMaxDynamicSharedMemorySize, GA_SMEM);
    cudaFuncSetAttribute(gemm_fp16, cudaFuncAttributeMaxDynamicSharedMemorySize, GH_SMEM);
    cudaFuncSetAttribute(conv_gemm, cudaFuncAttributeMaxDynamicSharedMemorySize, CV_SMEM);

    cudaEventRecord(evR, 0);
    cudaStreamWaitEvent(s1, evR, 0);
    cudaStreamWaitEvent(s2, evR, 0);
    cudaStreamWaitEvent(s3, evR, 0);

    wthalf     <<<dim3(64, 32), 256, 0, s1>>>(mw, pW1h, 2048);
    wthalf     <<<dim3(32, 32), 256, 0, s1>>>(ow, pW2h, 1024);
    bc_kernel  <<<dim3(256, 2), 512, BC_SMEM, s1>>>(x, pBC);

    xc_kernel  <<<dim3(256, 2), 256, 0, s2>>>(x, pXC);
    conv_gemm  <<<dim3(8, 4), 256, CV_SMEM, s2>>>(pXC, cw, pCP);
    conv_reduce<<<128, 256, 0, s2>>>(pCP, cb, pCOMP);
    gattn      <<<dim3(128, 8, 2), 256, GA_SMEM, s2>>>(x, gmem, pCOMP, pG);
    tohalf     <<<4096, 256, 0, s2>>>(pG, pGh);

    win_attn   <<<dim3(8, 8, 16), 256, WA_SMEM, s3>>>(x, pL, 0);
    win_attn   <<<dim3(8, 7, 16), 256, WA_SMEM, s3>>>(x, pL, 1);
    tohalf     <<<4096, 256, 0, s3>>>(pL, pLh);

    cudaEventRecord(ev1, s1);
    cudaEventRecord(ev2, s2);
    cudaEventRecord(ev3, s3);
    cudaStreamWaitEvent(0, ev1, 0);
    cudaStreamWaitEvent(0, ev2, 0);
    cudaStreamWaitEvent(0, ev3, 0);

    gemm_fp16<<<dim3(64, 8), 256, GH_SMEM>>>(
        1, pLh, pGh, pL, pG, pBC, pW1h, mb, out, pMh, 2048);
    gemm_fp16<<<dim3(64, 8), 256, GH_SMEM>>>(
        0, pMh, pMh, pL, pG, pBC, pW2h, ob, out, pMh, 1024);
}

// round 15
// speedup vs baseline: 1.8140x; 1.0369x over previous
#include <cuda_runtime.h>
#include <cuda_fp16.h>
#include <math.h>
#include <stdint.h>

__device__ float g_L [2u*4096u*1024u];
__device__ float g_G [2u*4096u*1024u];
__device__ float g_BC[2u*4096u*1024u];
__device__ float g_COMP[2u*64u*1024u];
__device__ float g_XC[128u*4096u];
__device__ float g_CP[4u*128u*1024u];
__device__ __half g_Lh[2u*4096u*1024u];
__device__ __half g_Gh[2u*4096u*1024u];
__device__ __half g_Mh[2u*4096u*1024u];
__device__ __half g_W1h[1024u*2048u];   // mix_w^T [n][k]
__device__ __half g_W2h[1024u*1024u];   // out_w^T [n][k]

__device__ __forceinline__ float f2tff(float x) {
    uint32_t u; asm("cvt.rn.tf32.f32 %0, %1;" : "=r"(u) : "f"(x));
    return __uint_as_float(u);
}
__device__ __forceinline__ void mma8(float* c, const uint32_t* a, const uint32_t* b) {
    asm volatile("mma.sync.aligned.m16n8k8.row.col.f32.tf32.tf32.f32 "
        "{%0,%1,%2,%3}, {%4,%5,%6,%7}, {%8,%9}, {%0,%1,%2,%3};"
        : "+f"(c[0]), "+f"(c[1]), "+f"(c[2]), "+f"(c[3])
        : "r"(a[0]), "r"(a[1]), "r"(a[2]), "r"(a[3]), "r"(b[0]), "r"(b[1]));
}
__device__ __forceinline__ void mma16h(float* c, const uint32_t* a, const uint32_t* b) {
    asm volatile("mma.sync.aligned.m16n8k16.row.col.f32.f16.f16.f32 "
        "{%0,%1,%2,%3}, {%4,%5,%6,%7}, {%8,%9}, {%0,%1,%2,%3};"
        : "+f"(c[0]), "+f"(c[1]), "+f"(c[2]), "+f"(c[3])
        : "r"(a[0]), "r"(a[1]), "r"(a[2]), "r"(a[3]), "r"(b[0]), "r"(b[1]));
}
#define LDSM_X2_TRANS(r0, r1, addr) \
    asm volatile("ldmatrix.sync.aligned.m8n8.x2.trans.shared.b16 {%0,%1}, [%2];" \
        : "=r"(r0), "=r"(r1) : "r"(addr))
__device__ __forceinline__ uint32_t smem_u32(const void* p) {
    uint32_t a;
    asm("{ .reg .u64 t; cvta.to.shared.u64 t, %1; cvt.u32.u64 %0, t; }" : "=r"(a) : "l"(p));
    return a;
}
#define CP16(dst, src) asm volatile("cp.async.cg.shared.global [%0], [%1], 16;" :: "r"(dst), "l"(src))
#define CPCOMMIT()     asm volatile("cp.async.commit_group;" ::: "memory")
#define CPWAIT1()      asm volatile("cp.async.wait_group 1;" ::: "memory")

__device__ __forceinline__ float invden(int s) {
    int n1 = s >> 8, i1 = s & 255;
    float d = 0.f;
    if (n1 <= 14) d += 0.5f + (float)i1 * (1.0f / 511.0f);
    if (n1 >= 1)  d += 0.5f + (float)(i1 + 256) * (1.0f / 511.0f);
    return 1.0f / d;
}

// ============ 0a) weight transpose -> half, [n][k] K-major ============
__global__ void wthalf(const float* __restrict__ W, __half* __restrict__ WT, int K) {
    __shared__ float tile[32][33];
    const int k0 = blockIdx.x << 5, n0 = blockIdx.y << 5;
    const int tx = threadIdx.x & 31, ty = threadIdx.x >> 5;
#pragma unroll
    for (int i = ty; i < 32; i += 8)
        tile[i][tx] = W[(size_t)(k0 + i) * 1024u + n0 + tx];
    __syncthreads();
#pragma unroll
    for (int i = ty; i < 32; i += 8)
        WT[(size_t)(n0 + i) * (size_t)K + k0 + tx] = __float2half_rn(tile[tx][i]);
}

// ============ 1) broadcast diffusion (conflict-free planes) ============
__global__ void bc_kernel(const float* __restrict__ x, float* __restrict__ bc) {
    extern __shared__ float sm[];
    const int tid = threadIdx.x, b = blockIdx.y, d0 = blockIdx.x << 2;
    float* bufA = sm; float* bufB = sm + 16384;
    const float* src = x + (size_t)b * 4194304u + d0;
    for (int s = tid; s < 4096; s += 512) {
        float4 v = *(const float4*)(src + (size_t)s * 1024u);
        bufA[s] = v.x; bufA[4096 + s] = v.y; bufA[8192 + s] = v.z; bufA[12288 + s] = v.w;
    }
    __syncthreads();
    float acc[32];
#pragma unroll
    for (int e = 0; e < 32; ++e) acc[e] = 0.f;
    float* cur = bufA; float* nxt = bufB;
    for (int st = 1; st < 4096; st <<= 1) {
#pragma unroll
        for (int q = 0; q < 8; ++q) {
            int s = tid + (q << 9);
            int sm1 = (s - st) & 4095, sp1 = (s + st) & 4095;
#pragma unroll
            for (int j = 0; j < 4; ++j) {
                const float* cj = cur + (j << 12);
                float v = cj[s] + 0.5f * (cj[sm1] + cj[sp1]);
                nxt[(j << 12) + s] = v;
                acc[(q << 2) + j] += v;
            }
        }
        __syncthreads();
        float* t = cur; cur = nxt; nxt = t;
    }
    const float inv = 1.0f / 13.0f;
    float* dst = bc + (size_t)b * 4194304u + d0;
#pragma unroll
    for (int q = 0; q < 8; ++q) {
        int s = tid + (q << 9);
        *(float4*)(dst + (size_t)s * 1024u) =
            make_float4(acc[q*4]*inv, acc[q*4+1]*inv, acc[q*4+2]*inv, acc[q*4+3]*inv);
    }
}

// ============ 2a) conv input gather ============
__global__ void xc_kernel(const float* __restrict__ x, float* __restrict__ Xc) {
    const int s = blockIdx.x;
    const int b = blockIdx.y;
    const int t = s >> 2, j = s & 3;
    const int m = (b << 6) + t;
    const float* src = x + (size_t)b * 4194304u + (size_t)s * 1024u;
    float* dst = Xc + (size_t)m * 4096u + j;
#pragma unroll
    for (int k = 0; k < 4; ++k) {
        int d = threadIdx.x + (k << 8);
        dst[d << 2] = src[d];
    }
}

// ============ 2b) conv GEMM (split-K x4, tf32) ============
__global__ void __launch_bounds__(256) conv_gemm(
        const float* __restrict__ Xc, const float* __restrict__ cwf,
        float* __restrict__ CP) {
    extern __shared__ float gsm[];
    const int tid = threadIdx.x;
    const int n0 = blockIdx.x << 7;
    const int kq = blockIdx.y;
    const int kbase = kq << 10;
    const int wid = tid >> 5, lane = tid & 31;
    const int quad = lane >> 2, tq = lane & 3;
    const int wm = wid >> 2, wn = wid & 3;
    const int am = tid >> 1, ak = (tid & 1) << 4;
    const uint32_t sbase = smem_u32(gsm);

    auto issue = [&](int kt, int slot) {
        uint32_t aoff = sbase + (uint32_t)(slot * 9216 + am * 36 + ak) * 4u;
        const float* asrc = Xc + (size_t)am * 4096u + kbase + kt + ak;
        CP16(aoff, asrc); CP16(aoff + 16, asrc + 4);
        CP16(aoff + 32, asrc + 8); CP16(aoff + 48, asrc + 12);
        uint32_t boff = aoff + 4608u * 4u;
        const float* bsrc = cwf + (size_t)(n0 + am) * 4096u + kbase + kt + ak;
        CP16(boff, bsrc); CP16(boff + 16, bsrc + 4);
        CP16(boff + 32, bsrc + 8); CP16(boff + 48, bsrc + 12);
        CPCOMMIT();
    };

    float acc[4][4][4];
#pragma unroll
    for (int i = 0; i < 4; ++i)
#pragma unroll
        for (int j = 0; j < 4; ++j)
#pragma unroll
            for (int e = 0; e < 4; ++e) acc[i][j][e] = 0.f;

    issue(0, 0);
    issue(32, 1);

    for (int kt = 0; kt < 1024; kt += 32) {
        CPWAIT1();
        __syncthreads();
        int nk = kt + 64;
        if (nk < 1024) issue(nk, ((kt >> 5) + 2) % 3);
        else           CPCOMMIT();

        const float* Asb = gsm + ((kt >> 5) % 3) * 9216;
        const float* Bsb = Asb + 4608;
#pragma unroll
        for (int ks = 0; ks < 4; ++ks) {
            const int k0 = ks << 3;
            uint32_t af[4][4], bf[4][2];
#pragma unroll
            for (int i = 0; i < 4; ++i) {
                int r = (wm << 6) + (i << 4) + quad;
                af[i][0] = __float_as_uint(Asb[r * 36 + k0 + tq]);
                af[i][1] = __float_as_uint(Asb[(r + 8) * 36 + k0 + tq]);
                af[i][2] = __float_as_uint(Asb[r * 36 + k0 + tq + 4]);
                af[i][3] = __float_as_uint(Asb[(r + 8) * 36 + k0 + tq + 4]);
            }
#pragma unroll
            for (int j = 0; j < 4; ++j) {
                int cidx = (wn << 5) + (j << 3) + quad;
                bf[j][0] = __float_as_uint(Bsb[cidx * 36 + k0 + tq]);
                bf[j][1] = __float_as_uint(Bsb[cidx * 36 + k0 + tq + 4]);
            }
#pragma unroll
            for (int i = 0; i < 4; ++i)
#pragma unroll
                for (int j = 0; j < 4; ++j) mma8(acc[i][j], af[i], bf[j]);
        }
    }
    float* cp = CP + (size_t)kq * 131072u;
#pragma unroll
    for (int i = 0; i < 4; ++i)
#pragma unroll
        for (int j = 0; j < 4; ++j) {
            int mr = (wm << 6) + (i << 4) + quad;
            int nc = n0 + (wn << 5) + (j << 3) + (tq << 1);
#pragma unroll
            for (int hf = 0; hf < 2; ++hf) {
                int m = mr + (hf << 3);
                *(float2*)(cp + (size_t)m * 1024u + nc) =
                    make_float2(acc[i][j][(hf << 1)], acc[i][j][(hf << 1) + 1]);
            }
        }
}

// ============ 2c) conv reduce ============
__global__ void conv_reduce(const float* __restrict__ CP, const float* __restrict__ cb,
                            float* __restrict__ comp) {
    int i = (blockIdx.x << 8) + threadIdx.x;
    int o4 = (i & 255) << 2;
    float4 a = *(const float4*)(CP + ((size_t)i << 2));
    float4 b = *(const float4*)(CP + 131072u + ((size_t)i << 2));
    float4 c = *(const float4*)(CP + 262144u + ((size_t)i << 2));
    float4 d = *(const float4*)(CP + 393216u + ((size_t)i << 2));
    float4 e = *(const float4*)(cb + o4);
    *(float4*)(comp + ((size_t)i << 2)) = make_float4(
        a.x + b.x + c.x + d.x + e.x, a.y + b.y + c.y + d.y + e.y,
        a.z + b.z + c.z + d.z + e.z, a.w + b.w + c.w + d.w + e.w);
}

// ============ 3) sliding-window attention (fp16 MMA + ldmatrix; writes L & Lh) ============
__global__ void __launch_bounds__(256) win_attn(
        const float* __restrict__ x, float* __restrict__ L,
        __half* __restrict__ Lh, int parity) {
    extern __shared__ float sm[];
    float* Ss = sm;                       // 4352 floats
    float* Al = sm + 4352;                // 64
    __half* Qh  = (__half*)(sm + 4416);   // 8704 halves
    __half* Ksh = Qh + 8704;              // 8704 halves
    __half* Ph  = Ksh + 8704;             // 4608 halves
    const uint32_t ksh_u32 = smem_u32(Ksh);

    const int tid = threadIdx.x;
    const int lane = tid & 31, wid = tid >> 5;
    const int g = lane >> 2, tq = lane & 3;
    const int qt = blockIdx.x;
    const int n = (blockIdx.y << 1) + parity;
    const int b = blockIdx.z >> 3, h = blockIdx.z & 7;
    const int base = n << 8, q0 = base + (qt << 6);
    const float* xb = x + (size_t)b * 4194304u + (h << 7);

#pragma unroll
    for (int it = 0; it < 8; ++it) {
        int i = tid + (it << 8);
        int r = i >> 5, c4 = (i & 31) << 2;
        float4 v = *(const float4*)(xb + (size_t)(q0 + r) * 1024u + c4);
        __half2 h0 = __floats2half2_rn(v.x, v.y);
        __half2 h1 = __floats2half2_rn(v.z, v.w);
        uint2 w; w.x = *(uint32_t*)&h0; w.y = *(uint32_t*)&h1;
        *(uint2*)&Qh[r * 136 + c4] = w;
    }

    const int wm = wid >> 1, wn = wid & 1;
    const int m0 = wm << 4;
    const int sn0 = wn << 5;
    const int on0 = wn << 6;
    const int srow = tid >> 2, seg = tid & 3;
    const int lrow = (lane & 15) * 136;
    const float scale = 0.08838834764831845f;

    float oacc[8][4];
#pragma unroll
    for (int nt = 0; nt < 8; ++nt)
#pragma unroll
        for (int e = 0; e < 4; ++e) oacc[nt][e] = 0.f;
    float m_i = -1e30f, l_i = 0.f;

    for (int kt = 0; kt < 8; ++kt) {
        __syncthreads();
        const int ktok = base + (kt << 6);
#pragma unroll
        for (int it = 0; it < 8; ++it) {
            int i = tid + (it << 8);
            int r = i >> 5, c4 = (i & 31) << 2;
            float4 v = *(const float4*)(xb + (size_t)(ktok + r) * 1024u + c4);
            __half2 h0 = __floats2half2_rn(v.x, v.y);
            __half2 h1 = __floats2half2_rn(v.z, v.w);
            uint2 w; w.x = *(uint32_t*)&h0; w.y = *(uint32_t*)&h1;
            *(uint2*)&Ksh[r * 136 + c4] = w;
        }
        __syncthreads();

        float sacc[4][4];
#pragma unroll
        for (int nt = 0; nt < 4; ++nt)
#pragma unroll
            for (int e = 0; e < 4; ++e) sacc[nt][e] = 0.f;
#pragma unroll
        for (int kd = 0; kd < 128; kd += 16) {
            uint32_t a[4];
            a[0] = *(const uint32_t*)&Qh[(m0 + g) * 136 + kd + (tq << 1)];
            a[1] = *(const uint32_t*)&Qh[(m0 + g + 8) * 136 + kd + (tq << 1)];
            a[2] = *(const uint32_t*)&Qh[(m0 + g) * 136 + kd + (tq << 1) + 8];
            a[3] = *(const uint32_t*)&Qh[(m0 + g + 8) * 136 + kd + (tq << 1) + 8];
#pragma unroll
            for (int nt = 0; nt < 4; ++nt) {
                int tcol = sn0 + (nt << 3) + g;
                uint32_t bb[2];
                bb[0] = *(const uint32_t*)&Ksh[tcol * 136 + kd + (tq << 1)];
                bb[1] = *(const uint32_t*)&Ksh[tcol * 136 + kd + (tq << 1) + 8];
                mma16h(sacc[nt], a, bb);
            }
        }
#pragma unroll
        for (int nt = 0; nt < 4; ++nt) {
            int nc = sn0 + (nt << 3) + (tq << 1);
            *(float2*)&Ss[(m0 + g) * 68 + nc] =
                make_float2(sacc[nt][0] * scale, sacc[nt][1] * scale);
            *(float2*)&Ss[(m0 + g + 8) * 68 + nc] =
                make_float2(sacc[nt][2] * scale, sacc[nt][3] * scale);
        }
        __syncthreads();

        {
            float* sr = &Ss[srow * 68 + (seg << 4)];
            float mt = -1e30f;
            float pv[16];
#pragma unroll
            for (int jj = 0; jj < 16; ++jj) { pv[jj] = sr[jj]; mt = fmaxf(mt, pv[jj]); }
            mt = fmaxf(mt, __shfl_xor_sync(0xffffffffu, mt, 1));
            mt = fmaxf(mt, __shfl_xor_sync(0xffffffffu, mt, 2));
            float m_new = fmaxf(m_i, mt);
            float alpha = __expf(m_i - m_new);
            float ls = 0.f;
#pragma unroll
            for (int jj = 0; jj < 16; ++jj) {
                pv[jj] = __expf(pv[jj] - m_new);
                ls += pv[jj];
            }
            __half* pr = &Ph[srow * 72 + (seg << 4)];
#pragma unroll
            for (int j2 = 0; j2 < 8; ++j2) {
                __half2 hp = __floats2half2_rn(pv[j2 << 1], pv[(j2 << 1) + 1]);
                *(__half2*)&pr[j2 << 1] = hp;
            }
            ls += __shfl_xor_sync(0xffffffffu, ls, 1);
            ls += __shfl_xor_sync(0xffffffffu, ls, 2);
            l_i = l_i * alpha + ls;
            m_i = m_new;
            if (seg == 0) Al[srow] = alpha;
        }
        __syncthreads();

        float aLo = Al[m0 + g], aHi = Al[m0 + g + 8];
#pragma unroll
        for (int nt = 0; nt < 8; ++nt) {
            oacc[nt][0] *= aLo; oacc[nt][1] *= aLo;
            oacc[nt][2] *= aHi; oacc[nt][3] *= aHi;
        }
#pragma unroll
        for (int kd = 0; kd < 64; kd += 16) {
            uint32_t a[4];
            a[0] = *(const uint32_t*)&Ph[(m0 + g) * 72 + kd + (tq << 1)];
            a[1] = *(const uint32_t*)&Ph[(m0 + g + 8) * 72 + kd + (tq << 1)];
            a[2] = *(const uint32_t*)&Ph[(m0 + g) * 72 + kd + (tq << 1) + 8];
            a[3] = *(const uint32_t*)&Ph[(m0 + g + 8) * 72 + kd + (tq << 1) + 8];
            uint32_t rowa = ksh_u32 + (uint32_t)(((kd * 136) + lrow) << 1);
#pragma unroll
            for (int nt = 0; nt < 8; ++nt) {
                uint32_t bb[2];
                uint32_t addr = rowa + (uint32_t)((on0 + (nt << 3)) << 1);
                LDSM_X2_TRANS(bb[0], bb[1], addr);
                mma16h(oacc[nt], a, bb);
            }
        }
    }
    __syncthreads();
    if (seg == 0) Al[srow] = 1.0f / l_i;
    __syncthreads();

    const int iwLo = (qt << 6) + m0 + g;
    const int iwHi = iwLo + 8;
    const int sLo = base + iwLo, sHi = base + iwHi;
    const float triLo = 0.5f + (float)iwLo * (1.0f / 511.0f);
    const float triHi = 0.5f + (float)iwHi * (1.0f / 511.0f);
    const size_t offLo = ((size_t)b * 4096u + sLo) * 1024u + (h << 7);
    const size_t offHi = offLo + (size_t)8 * 1024u;
    float* dLo = L + offLo;
    float* dHi = L + offHi;
    __half* eLo = Lh + offLo;
    __half* eHi = Lh + offHi;
    if (parity == 0) {
        const bool snLo = (sLo < 256) || (sLo >= 3840);
        const bool snHi = (sHi < 256) || (sHi >= 3840);
        const float twLo = (snLo ? 1.0f : triLo) * Al[m0 + g];
        const float twHi = (snHi ? 1.0f : triHi) * Al[m0 + g + 8];
#pragma unroll
        for (int nt = 0; nt < 8; ++nt) {
            int dc = on0 + (nt << 3) + (tq << 1);
            float2 o = make_float2(oacc[nt][0] * twLo, oacc[nt][1] * twLo);
            float2 p = make_float2(oacc[nt][2] * twHi, oacc[nt][3] * twHi);
            *(float2*)(dLo + dc) = o;
            *(float2*)(dHi + dc) = p;
            if (snLo) { __half2 hh = __floats2half2_rn(o.x, o.y); *(__half2*)(eLo + dc) = hh; }
            if (snHi) { __half2 hh = __floats2half2_rn(p.x, p.y); *(__half2*)(eHi + dc) = hh; }
        }
    } else {
        const float twLo = triLo * Al[m0 + g];
        const float twHi = triHi * Al[m0 + g + 8];
        const float ivLo = invden(sLo), ivHi = invden(sHi);
#pragma unroll
        for (int nt = 0; nt < 8; ++nt) {
            int dc = on0 + (nt << 3) + (tq << 1);
            float2 o = *(float2*)(dLo + dc);
            o.x = (o.x + oacc[nt][0] * twLo) * ivLo;
            o.y = (o.y + oacc[nt][1] * twLo) * ivLo;
            *(float2*)(dLo + dc) = o;
            __half2 ho = __floats2half2_rn(o.x, o.y);
            *(__half2*)(eLo + dc) = ho;
            float2 p = *(float2*)(dHi + dc);
            p.x = (p.x + oacc[nt][2] * twHi) * ivHi;
            p.y = (p.y + oacc[nt][3] * twHi) * ivHi;
            *(float2*)(dHi + dc) = p;
            __half2 hp = __floats2half2_rn(p.x, p.y);
            *(__half2*)(eHi + dc) = hp;
        }
    }
}

// ============ 4) compressed-global attention (fp16 MMA; writes G & Gh) ============
// smem: Ps float[32*132] (4224) | KVh half[128*136] | Qh half[32*136] | Ph half[32*136]
__global__ void __launch_bounds__(256) gattn(
        const float* __restrict__ x, const float* __restrict__ gmem,
        const float* __restrict__ comp, float* __restrict__ G,
        __half* __restrict__ Gh) {
    extern __shared__ float sm[];
    float* Ps = sm;                        // 4224 floats
    __half* KVh = (__half*)(sm + 4224);    // 17408 halves
    __half* Qh  = KVh + 17408;             // 4352 halves
    __half* Ph  = Qh + 4352;               // 4352 halves
    const uint32_t kvh_u32 = smem_u32(KVh);

    const int tid = threadIdx.x;
    const int lane = tid & 31, wid = tid >> 5;
    const int g = lane >> 2, tq = lane & 3;
    const int s0 = blockIdx.x << 5, h = blockIdx.y, b = blockIdx.z;

#pragma unroll
    for (int it = 0; it < 16; ++it) {
        int i = tid + (it << 8);
        int r = i >> 5, c4 = (i & 31) << 2;
        float4 v;
        if (r < 64) v = *(const float4*)(comp + (size_t)((b << 6) + r) * 1024u + (h << 7) + c4);
        else        v = *(const float4*)(gmem + (size_t)((h << 6) + (r - 64)) * 128u + c4);
        __half2 h0 = __floats2half2_rn(v.x, v.y);
        __half2 h1 = __floats2half2_rn(v.z, v.w);
        uint2 w; w.x = *(uint32_t*)&h0; w.y = *(uint32_t*)&h1;
        *(uint2*)&KVh[r * 136 + c4] = w;
    }
#pragma unroll
    for (int it = 0; it < 4; ++it) {
        int i = tid + (it << 8);
        int r = i >> 5, c4 = (i & 31) << 2;
        float4 v = *(const float4*)(x + (size_t)b * 4194304u + (size_t)(s0 + r) * 1024u + (h << 7) + c4);
        __half2 h0 = __floats2half2_rn(v.x, v.y);
        __half2 h1 = __floats2half2_rn(v.z, v.w);
        uint2 w; w.x = *(uint32_t*)&h0; w.y = *(uint32_t*)&h1;
        *(uint2*)&Qh[r * 136 + c4] = w;
    }
    __syncthreads();

    const int wm = wid & 1, wn = wid >> 1;
    const int m0 = wm << 4;
    const int tn0 = wn << 5;
    const int lrow = (lane & 15) * 136;
    const float scale = 0.08838834764831845f;

    // scores S[32][128] = Q @ KV^T (fp16)
    {
        float sacc[4][4];
#pragma unroll
        for (int nt = 0; nt < 4; ++nt)
#pragma unroll
            for (int e = 0; e < 4; ++e) sacc[nt][e] = 0.f;
#pragma unroll
        for (int kd = 0; kd < 128; kd += 16) {
            uint32_t a[4];
            a[0] = *(const uint32_t*)&Qh[(m0 + g) * 136 + kd + (tq << 1)];
            a[1] = *(const uint32_t*)&Qh[(m0 + g + 8) * 136 + kd + (tq << 1)];
            a[2] = *(const uint32_t*)&Qh[(m0 + g) * 136 + kd + (tq << 1) + 8];
            a[3] = *(const uint32_t*)&Qh[(m0 + g + 8) * 136 + kd + (tq << 1) + 8];
#pragma unroll
            for (int nt = 0; nt < 4; ++nt) {
                int tcol = tn0 + (nt << 3) + g;
                uint32_t bb[2];
                bb[0] = *(const uint32_t*)&KVh[tcol * 136 + kd + (tq << 1)];
                bb[1] = *(const uint32_t*)&KVh[tcol * 136 + kd + (tq << 1) + 8];
                mma16h(sacc[nt], a, bb);
            }
        }
#pragma unroll
        for (int nt = 0; nt < 4; ++nt) {
            int nc = tn0 + (nt << 3) + (tq << 1);
            *(float2*)&Ps[(m0 + g) * 132 + nc] =
                make_float2(sacc[nt][0] * scale, sacc[nt][1] * scale);
            *(float2*)&Ps[(m0 + g + 8) * 132 + nc] =
                make_float2(sacc[nt][2] * scale, sacc[nt][3] * scale);
        }
    }
    __syncthreads();

    // single-pass softmax -> Ph (half)
    {
        int row = tid >> 3, seg8 = tid & 7;
        float* pr = &Ps[row * 132 + (seg8 << 4)];
        float mt = -1e30f;
        float pv[16];
#pragma unroll
        for (int jj = 0; jj < 16; ++jj) { pv[jj] = pr[jj]; mt = fmaxf(mt, pv[jj]); }
        mt = fmaxf(mt, __shfl_xor_sync(0xffffffffu, mt, 1));
        mt = fmaxf(mt, __shfl_xor_sync(0xffffffffu, mt, 2));
        mt = fmaxf(mt, __shfl_xor_sync(0xffffffffu, mt, 4));
        float ssum = 0.f;
#pragma unroll
        for (int jj = 0; jj < 16; ++jj) { pv[jj] = __expf(pv[jj] - mt); ssum += pv[jj]; }
        ssum += __shfl_xor_sync(0xffffffffu, ssum, 1);
        ssum += __shfl_xor_sync(0xffffffffu, ssum, 2);
        ssum += __shfl_xor_sync(0xffffffffu, ssum, 4);
        float invs = 1.0f / ssum;
        __half* ph = &Ph[row * 136 + (seg8 << 4)];
#pragma unroll
        for (int j2 = 0; j2 < 8; ++j2) {
            __half2 hp = __floats2half2_rn(pv[j2 << 1] * invs, pv[(j2 << 1) + 1] * invs);
            *(__half2*)&ph[j2 << 1] = hp;
        }
    }
    __syncthreads();

    // O[32][128] = P @ KV (fp16, B via ldmatrix.trans)
    {
        float oacc[4][4];
#pragma unroll
        for (int nt = 0; nt < 4; ++nt)
#pragma unroll
            for (int e = 0; e < 4; ++e) oacc[nt][e] = 0.f;
#pragma unroll
        for (int kd = 0; kd < 128; kd += 16) {
            uint32_t a[4];
            a[0] = *(const uint32_t*)&Ph[(m0 + g) * 136 + kd + (tq << 1)];
            a[1] = *(const uint32_t*)&Ph[(m0 + g + 8) * 136 + kd + (tq << 1)];
            a[2] = *(const uint32_t*)&Ph[(m0 + g) * 136 + kd + (tq << 1) + 8];
            a[3] = *(const uint32_t*)&Ph[(m0 + g + 8) * 136 + kd + (tq << 1) + 8];
            uint32_t rowa = kvh_u32 + (uint32_t)(((kd * 136) + lrow) << 1);
#pragma unroll
            for (int nt = 0; nt < 4; ++nt) {
                uint32_t bb[2];
                uint32_t addr = rowa + (uint32_t)((tn0 + (nt << 3)) << 1);
                LDSM_X2_TRANS(bb[0], bb[1], addr);
                mma16h(oacc[nt], a, bb);
            }
        }
        const size_t offLo = ((size_t)b * 4096u + s0 + m0 + g) * 1024u + (h << 7);
        const size_t offHi = offLo + (size_t)8 * 1024u;
#pragma unroll
        for (int nt = 0; nt < 4; ++nt) {
            int nc = tn0 + (nt << 3) + (tq << 1);
            float2 o = make_float2(oacc[nt][0], oacc[nt][1]);
            float2 p = make_float2(oacc[nt][2], oacc[nt][3]);
            *(float2*)(G + offLo + nc) = o;
            *(float2*)(G + offHi + nc) = p;
            __half2 ho = __floats2half2_rn(o.x, o.y);
            __half2 hp = __floats2half2_rn(p.x, p.y);
            *(__half2*)(Gh + offLo + nc) = ho;
            *(__half2*)(Gh + offHi + nc) = hp;
        }
    }
}

// ============ 5+6) fp16 GEMM: 128x128 tile, m16n8k16, 3-stage cp.async ============
__global__ void __launch_bounds__(256) gemm_fp16(
        int mode, const __half* __restrict__ Ah0, const __half* __restrict__ Ah1,
        const float* __restrict__ Lf, const float* __restrict__ Gf,
        const float* __restrict__ BCp, const __half* __restrict__ WT,
        const float* __restrict__ bias, float* __restrict__ Cf,
        __half* __restrict__ Ch, int K) {
    extern __shared__ __half hsm[];
    const int tid = threadIdx.x;
    const int m0 = blockIdx.x << 7, n0 = blockIdx.y << 7;
    const int wid = tid >> 5, lane = tid & 31;
    const int quad = lane >> 2, tq = lane & 3;
    const int wm = wid >> 2, wn = wid & 3;
    const int arow = tid >> 1, aseg = (tid & 1) << 4;
    const uint32_t sbase = smem_u32(hsm);

    auto issue = [&](int kt, int slot) {
        uint32_t aoff = sbase + (uint32_t)(slot * 10240 + arow * 40 + aseg) * 2u;
        const __half* asrc = (mode == 1 && kt >= 1024)
            ? (Ah1 + (size_t)(m0 + arow) * 1024u + (kt - 1024) + aseg)
            : (Ah0 + (size_t)(m0 + arow) * 1024u + kt + aseg);
        CP16(aoff, asrc); CP16(aoff + 16, asrc + 8);
        uint32_t boff = sbase + (uint32_t)(slot * 10240 + 5120 + arow * 40 + aseg) * 2u;
        const __half* bsrc = WT + (size_t)(n0 + arow) * (size_t)K + kt + aseg;
        CP16(boff, bsrc); CP16(boff + 16, bsrc + 8);
        CPCOMMIT();
    };

    float acc[4][4][4];
#pragma unroll
    for (int i = 0; i < 4; ++i)
#pragma unroll
        for (int j = 0; j < 4; ++j)
#pragma unroll
            for (int e = 0; e < 4; ++e) acc[i][j][e] = 0.f;

    issue(0, 0);
    issue(32, 1);

    for (int kt = 0; kt < K; kt += 32) {
        CPWAIT1();
        __syncthreads();
        int nk = kt + 64;
        if (nk < K) issue(nk, ((kt >> 5) + 2) % 3);
        else        CPCOMMIT();

        const __half* Asb = hsm + ((kt >> 5) % 3) * 10240;
        const __half* Bsb = Asb + 5120;
#pragma unroll
        for (int ks = 0; ks < 2; ++ks) {
            const int k0 = ks << 4;
            uint32_t af[4][4], bf[4][2];
#pragma unroll
            for (int i = 0; i < 4; ++i) {
                int r = (wm << 6) + (i << 4) + quad;
                af[i][0] = *(const uint32_t*)&Asb[r * 40 + k0 + (tq << 1)];
                af[i][1] = *(const uint32_t*)&Asb[(r + 8) * 40 + k0 + (tq << 1)];
                af[i][2] = *(const uint32_t*)&Asb[r * 40 + k0 + (tq << 1) + 8];
                af[i][3] = *(const uint32_t*)&Asb[(r + 8) * 40 + k0 + (tq << 1) + 8];
            }
#pragma unroll
            for (int j = 0; j < 4; ++j) {
                int cidx = (wn << 5) + (j << 3) + quad;
                bf[j][0] = *(const uint32_t*)&Bsb[cidx * 40 + k0 + (tq << 1)];
                bf[j][1] = *(const uint32_t*)&Bsb[cidx * 40 + k0 + (tq << 1) + 8];
            }
#pragma unroll
            for (int i = 0; i < 4; ++i)
#pragma unroll
                for (int j = 0; j < 4; ++j) mma16h(acc[i][j], af[i], bf[j]);
        }
    }

#pragma unroll
    for (int i = 0; i < 4; ++i)
#pragma unroll
        for (int j = 0; j < 4; ++j) {
            int mr = m0 + (wm << 6) + (i << 4) + quad;
            int nc = n0 + (wn << 5) + (j << 3) + (tq << 1);
#pragma unroll
            for (int hf = 0; hf < 2; ++hf) {
                int m = mr + (hf << 3);
                size_t bix = (size_t)m * 1024u + nc;
#pragma unroll
                for (int e = 0; e < 2; ++e) {
                    float z = acc[i][j][(hf << 1) + e] + bias[nc + e];
                    if (mode == 1) {
                        float gg = 1.0f / (1.0f + __expf(-z));
                        float mval = gg * Lf[bix + e] + (1.0f - gg) * Gf[bix + e] + BCp[bix + e];
                        Ch[bix + e] = __float2half_rn(mval);
                    } else {
                        Cf[bix + e] = z;
                    }
                }
            }
        }
}

// =====================================================================
extern "C" void kernel_launch(void* const* d_in, const int* in_sizes, int n_in,
                              void* d_out, int out_size) {
    const float* x    = (const float*)d_in[0];
    const float* gmem = (const float*)d_in[1];
    const float* cw   = (const float*)d_in[2];
    const float* cb   = (const float*)d_in[3];
    const float* mw   = (const float*)d_in[4];
    const float* mb   = (const float*)d_in[5];
    const float* ow   = (const float*)d_in[6];
    const float* ob   = (const float*)d_in[7];
    float* out = (float*)d_out;

    float *pL, *pG, *pBC, *pCOMP, *pXC, *pCP;
    __half *pLh, *pGh, *pMh, *pW1h, *pW2h;
    cudaGetSymbolAddress((void**)&pL,    g_L);
    cudaGetSymbolAddress((void**)&pG,    g_G);
    cudaGetSymbolAddress((void**)&pBC,   g_BC);
    cudaGetSymbolAddress((void**)&pCOMP, g_COMP);
    cudaGetSymbolAddress((void**)&pXC,   g_XC);
    cudaGetSymbolAddress((void**)&pCP,   g_CP);
    cudaGetSymbolAddress((void**)&pLh,   g_Lh);
    cudaGetSymbolAddress((void**)&pGh,   g_Gh);
    cudaGetSymbolAddress((void**)&pMh,   g_Mh);
    cudaGetSymbolAddress((void**)&pW1h,  g_W1h);
    cudaGetSymbolAddress((void**)&pW2h,  g_W2h);

    static cudaStream_t s1 = nullptr, s2 = nullptr, s3 = nullptr;
    static cudaEvent_t evR = nullptr, ev1 = nullptr, ev2 = nullptr, ev3 = nullptr;
    if (s1 == nullptr) {
        cudaStreamCreateWithFlags(&s1, cudaStreamNonBlocking);
        cudaStreamCreateWithFlags(&s2, cudaStreamNonBlocking);
        cudaStreamCreateWithFlags(&s3, cudaStreamNonBlocking);
        cudaEventCreateWithFlags(&evR, cudaEventDisableTiming);
        cudaEventCreateWithFlags(&ev1, cudaEventDisableTiming);
        cudaEventCreateWithFlags(&ev2, cudaEventDisableTiming);
        cudaEventCreateWithFlags(&ev3, cudaEventDisableTiming);
    }

    const int BC_SMEM = 2 * 16384 * 4;
    const int WA_SMEM = 61696;
    const int GA_SMEM = 4224 * 4 + (17408 + 4352 + 4352) * 2;   // 69120 B
    const int GH_SMEM = 3 * 10240 * 2;
    const int CV_SMEM = 3 * 9216 * 4;
    cudaFuncSetAttribute(bc_kernel, cudaFuncAttributeMaxDynamicSharedMemorySize, BC_SMEM);
    cudaFuncSetAttribute(win_attn,  cudaFuncAttributeMaxDynamicSharedMemorySize, WA_SMEM);
    cudaFuncSetAttribute(gattn,     cudaFuncAttributeMaxDynamicSharedMemorySize, GA_SMEM);
    cudaFuncSetAttribute(gemm_fp16, cudaFuncAttributeMaxDynamicSharedMemorySize, GH_SMEM);
    cudaFuncSetAttribute(conv_gemm, cudaFuncAttributeMaxDynamicSharedMemorySize, CV_SMEM);

    cudaEventRecord(evR, 0);
    cudaStreamWaitEvent(s1, evR, 0);
    cudaStreamWaitEvent(s2, evR, 0);
    cudaStreamWaitEvent(s3, evR, 0);

    wthalf     <<<dim3(64, 32), 256, 0, s1>>>(mw, pW1h, 2048);
    wthalf     <<<dim3(32, 32), 256, 0, s1>>>(ow, pW2h, 1024);
    bc_kernel  <<<dim3(256, 2), 512, BC_SMEM, s1>>>(x, pBC);

    xc_kernel  <<<dim3(256, 2), 256, 0, s2>>>(x, pXC);
    conv_gemm  <<<dim3(8, 4), 256, CV_SMEM, s2>>>(pXC, cw, pCP);
    conv_reduce<<<128, 256, 0, s2>>>(pCP, cb, pCOMP);
    gattn      <<<dim3(128, 8, 2), 256, GA_SMEM, s2>>>(x, gmem, pCOMP, pG, pGh);

    win_attn   <<<dim3(8, 8, 16), 256, WA_SMEM, s3>>>(x, pL, pLh, 0);
    win_attn   <<<dim3(8, 7, 16), 256, WA_SMEM, s3>>>(x, pL, pLh, 1);

    cudaEventRecord(ev1, s1);
    cudaEventRecord(ev2, s2);
    cudaEventRecord(ev3, s3);
    cudaStreamWaitEvent(0, ev1, 0);
    cudaStreamWaitEvent(0, ev2, 0);
    cudaStreamWaitEvent(0, ev3, 0);

    gemm_fp16<<<dim3(64, 8), 256, GH_SMEM>>>(
        1, pLh, pGh, pL, pG, pBC, pW1h, mb, out, pMh, 2048);
    gemm_fp16<<<dim3(64, 8), 256, GH_SMEM>>>(
        0, pMh, pMh, pL, pG, pBC, pW2h, ob, out, pMh, 1024);
}

// round 16
// speedup vs baseline: 1.9890x; 1.0965x over previous
#include <cuda_runtime.h>
#include <cuda_fp16.h>
#include <math.h>
#include <stdint.h>

__device__ float g_L [2u*4096u*1024u];
__device__ float g_G [2u*4096u*1024u];
__device__ float g_BC[2u*4096u*1024u];
__device__ float g_COMP[2u*64u*1024u];
__device__ float g_CP[4u*128u*1024u];
__device__ __half g_XCh[128u*4096u];
__device__ __half g_CWh[1024u*4096u];
__device__ __half g_Lh[2u*4096u*1024u];
__device__ __half g_Gh[2u*4096u*1024u];
__device__ __half g_Mh[2u*4096u*1024u];
__device__ __half g_W1h[1024u*2048u];   // mix_w^T [n][k]
__device__ __half g_W2h[1024u*1024u];   // out_w^T [n][k]

__device__ __forceinline__ void mma16h(float* c, const uint32_t* a, const uint32_t* b) {
    asm volatile("mma.sync.aligned.m16n8k16.row.col.f32.f16.f16.f32 "
        "{%0,%1,%2,%3}, {%4,%5,%6,%7}, {%8,%9}, {%0,%1,%2,%3};"
        : "+f"(c[0]), "+f"(c[1]), "+f"(c[2]), "+f"(c[3])
        : "r"(a[0]), "r"(a[1]), "r"(a[2]), "r"(a[3]), "r"(b[0]), "r"(b[1]));
}
#define LDSM_X2_TRANS(r0, r1, addr) \
    asm volatile("ldmatrix.sync.aligned.m8n8.x2.trans.shared.b16 {%0,%1}, [%2];" \
        : "=r"(r0), "=r"(r1) : "r"(addr))
__device__ __forceinline__ uint32_t smem_u32(const void* p) {
    uint32_t a;
    asm("{ .reg .u64 t; cvta.to.shared.u64 t, %1; cvt.u32.u64 %0, t; }" : "=r"(a) : "l"(p));
    return a;
}
#define CP16(dst, src) asm volatile("cp.async.cg.shared.global [%0], [%1], 16;" :: "r"(dst), "l"(src))
#define CPCOMMIT()     asm volatile("cp.async.commit_group;" ::: "memory")
#define CPWAIT1()      asm volatile("cp.async.wait_group 1;" ::: "memory")

__device__ __forceinline__ float invden(int s) {
    int n1 = s >> 8, i1 = s & 255;
    float d = 0.f;
    if (n1 <= 14) d += 0.5f + (float)i1 * (1.0f / 511.0f);
    if (n1 >= 1)  d += 0.5f + (float)(i1 + 256) * (1.0f / 511.0f);
    return 1.0f / d;
}

// ============ 0a) weight transpose -> half, [n][k] K-major ============
__global__ void wthalf(const float* __restrict__ W, __half* __restrict__ WT, int K) {
    __shared__ float tile[32][33];
    const int k0 = blockIdx.x << 5, n0 = blockIdx.y << 5;
    const int tx = threadIdx.x & 31, ty = threadIdx.x >> 5;
#pragma unroll
    for (int i = ty; i < 32; i += 8)
        tile[i][tx] = W[(size_t)(k0 + i) * 1024u + n0 + tx];
    __syncthreads();
#pragma unroll
    for (int i = ty; i < 32; i += 8)
        WT[(size_t)(n0 + i) * (size_t)K + k0 + tx] = __float2half_rn(tile[tx][i]);
}

// ============ 0b) fp32 -> fp16 convert (8 elems/thread) ============
__global__ void tohalf(const float* __restrict__ S, __half* __restrict__ D) {
    size_t i = ((size_t)blockIdx.x * blockDim.x + threadIdx.x) << 3;
    float4 a = *(const float4*)(S + i);
    float4 b = *(const float4*)(S + i + 4);
    __half2 h0 = __floats2half2_rn(a.x, a.y);
    __half2 h1 = __floats2half2_rn(a.z, a.w);
    __half2 h2 = __floats2half2_rn(b.x, b.y);
    __half2 h3 = __floats2half2_rn(b.z, b.w);
    uint4 o;
    o.x = *(uint32_t*)&h0; o.y = *(uint32_t*)&h1;
    o.z = *(uint32_t*)&h2; o.w = *(uint32_t*)&h3;
    *(uint4*)(D + i) = o;
}

// ============ 1) broadcast diffusion (planes + register self-value) ============
__global__ void bc_kernel(const float* __restrict__ x, float* __restrict__ bc) {
    extern __shared__ float sm[];
    const int tid = threadIdx.x, b = blockIdx.y, d0 = blockIdx.x << 2;
    float* bufA = sm; float* bufB = sm + 16384;
    const float* src = x + (size_t)b * 4194304u + d0;
    float reg[8][4];
#pragma unroll
    for (int q = 0; q < 8; ++q) {
        int s = tid + (q << 9);
        float4 v = *(const float4*)(src + (size_t)s * 1024u);
        bufA[s] = v.x; bufA[4096 + s] = v.y; bufA[8192 + s] = v.z; bufA[12288 + s] = v.w;
        reg[q][0] = v.x; reg[q][1] = v.y; reg[q][2] = v.z; reg[q][3] = v.w;
    }
    __syncthreads();
    float acc[32];
#pragma unroll
    for (int e = 0; e < 32; ++e) acc[e] = 0.f;
    float* cur = bufA; float* nxt = bufB;
    for (int st = 1; st < 4096; st <<= 1) {
#pragma unroll
        for (int q = 0; q < 8; ++q) {
            int s = tid + (q << 9);
            int sm1 = (s - st) & 4095, sp1 = (s + st) & 4095;
#pragma unroll
            for (int j = 0; j < 4; ++j) {
                const float* cj = cur + (j << 12);
                float v = reg[q][j] + 0.5f * (cj[sm1] + cj[sp1]);
                nxt[(j << 12) + s] = v;
                reg[q][j] = v;
                acc[(q << 2) + j] += v;
            }
        }
        __syncthreads();
        float* t = cur; cur = nxt; nxt = t;
    }
    const float inv = 1.0f / 13.0f;
    float* dst = bc + (size_t)b * 4194304u + d0;
#pragma unroll
    for (int q = 0; q < 8; ++q) {
        int s = tid + (q << 9);
        *(float4*)(dst + (size_t)s * 1024u) =
            make_float4(acc[q*4]*inv, acc[q*4+1]*inv, acc[q*4+2]*inv, acc[q*4+3]*inv);
    }
}

// ============ 2a) conv input gather -> half ============
__global__ void xch_kernel(const float* __restrict__ x, __half* __restrict__ Xch) {
    const int s = blockIdx.x;
    const int b = blockIdx.y;
    const int t = s >> 2, j = s & 3;
    const int m = (b << 6) + t;
    const float* src = x + (size_t)b * 4194304u + (size_t)s * 1024u;
    __half* dst = Xch + (size_t)m * 4096u + j;
#pragma unroll
    for (int k = 0; k < 4; ++k) {
        int d = threadIdx.x + (k << 8);
        dst[d << 2] = __float2half_rn(src[d]);
    }
}

// ============ 2b) conv GEMM fp16 (split-K x4): CP[kq] partials ============
// A = Xch[m][4096], B = CWh[o][4096], both K-major. Tile 128x128, K=1024/CTA.
__global__ void __launch_bounds__(256) conv_gemm_h(
        const __half* __restrict__ Xch, const __half* __restrict__ CWh,
        float* __restrict__ CP) {
    extern __shared__ __half hsm[];
    const int tid = threadIdx.x;
    const int n0 = blockIdx.x << 7;
    const int kq = blockIdx.y;
    const int kbase = kq << 10;
    const int wid = tid >> 5, lane = tid & 31;
    const int quad = lane >> 2, tq = lane & 3;
    const int wm = wid >> 2, wn = wid & 3;
    const int arow = tid >> 1, aseg = (tid & 1) << 4;
    const uint32_t sbase = smem_u32(hsm);

    auto issue = [&](int kt, int slot) {
        uint32_t aoff = sbase + (uint32_t)(slot * 10240 + arow * 40 + aseg) * 2u;
        const __half* asrc = Xch + (size_t)arow * 4096u + kbase + kt + aseg;
        CP16(aoff, asrc); CP16(aoff + 16, asrc + 8);
        uint32_t boff = sbase + (uint32_t)(slot * 10240 + 5120 + arow * 40 + aseg) * 2u;
        const __half* bsrc = CWh + (size_t)(n0 + arow) * 4096u + kbase + kt + aseg;
        CP16(boff, bsrc); CP16(boff + 16, bsrc + 8);
        CPCOMMIT();
    };

    float acc[4][4][4];
#pragma unroll
    for (int i = 0; i < 4; ++i)
#pragma unroll
        for (int j = 0; j < 4; ++j)
#pragma unroll
            for (int e = 0; e < 4; ++e) acc[i][j][e] = 0.f;

    issue(0, 0);
    issue(32, 1);

    for (int kt = 0; kt < 1024; kt += 32) {
        CPWAIT1();
        __syncthreads();
        int nk = kt + 64;
        if (nk < 1024) issue(nk, ((kt >> 5) + 2) % 3);
        else           CPCOMMIT();

        const __half* Asb = hsm + ((kt >> 5) % 3) * 10240;
        const __half* Bsb = Asb + 5120;
#pragma unroll
        for (int ks = 0; ks < 2; ++ks) {
            const int k0 = ks << 4;
            uint32_t af[4][4], bf[4][2];
#pragma unroll
            for (int i = 0; i < 4; ++i) {
                int r = (wm << 6) + (i << 4) + quad;
                af[i][0] = *(const uint32_t*)&Asb[r * 40 + k0 + (tq << 1)];
                af[i][1] = *(const uint32_t*)&Asb[(r + 8) * 40 + k0 + (tq << 1)];
                af[i][2] = *(const uint32_t*)&Asb[r * 40 + k0 + (tq << 1) + 8];
                af[i][3] = *(const uint32_t*)&Asb[(r + 8) * 40 + k0 + (tq << 1) + 8];
            }
#pragma unroll
            for (int j = 0; j < 4; ++j) {
                int cidx = (wn << 5) + (j << 3) + quad;
                bf[j][0] = *(const uint32_t*)&Bsb[cidx * 40 + k0 + (tq << 1)];
                bf[j][1] = *(const uint32_t*)&Bsb[cidx * 40 + k0 + (tq << 1) + 8];
            }
#pragma unroll
            for (int i = 0; i < 4; ++i)
#pragma unroll
                for (int j = 0; j < 4; ++j) mma16h(acc[i][j], af[i], bf[j]);
        }
    }
    float* cp = CP + (size_t)kq * 131072u;
#pragma unroll
    for (int i = 0; i < 4; ++i)
#pragma unroll
        for (int j = 0; j < 4; ++j) {
            int mr = (wm << 6) + (i << 4) + quad;
            int nc = n0 + (wn << 5) + (j << 3) + (tq << 1);
#pragma unroll
            for (int hf = 0; hf < 2; ++hf) {
                int m = mr + (hf << 3);
                *(float2*)(cp + (size_t)m * 1024u + nc) =
                    make_float2(acc[i][j][(hf << 1)], acc[i][j][(hf << 1) + 1]);
            }
        }
}

// ============ 2c) conv reduce ============
__global__ void conv_reduce(const float* __restrict__ CP, const float* __restrict__ cb,
                            float* __restrict__ comp) {
    int i = (blockIdx.x << 8) + threadIdx.x;
    int o4 = (i & 255) << 2;
    float4 a = *(const float4*)(CP + ((size_t)i << 2));
    float4 b = *(const float4*)(CP + 131072u + ((size_t)i << 2));
    float4 c = *(const float4*)(CP + 262144u + ((size_t)i << 2));
    float4 d = *(const float4*)(CP + 393216u + ((size_t)i << 2));
    float4 e = *(const float4*)(cb + o4);
    *(float4*)(comp + ((size_t)i << 2)) = make_float4(
        a.x + b.x + c.x + d.x + e.x, a.y + b.y + c.y + d.y + e.y,
        a.z + b.z + c.z + d.z + e.z, a.w + b.w + c.w + d.w + e.w);
}

// ============ 3) sliding-window attention (fp16 MMA + ldmatrix; writes L & Lh) ============
__global__ void __launch_bounds__(256) win_attn(
        const float* __restrict__ x, float* __restrict__ L,
        __half* __restrict__ Lh, int parity) {
    extern __shared__ float sm[];
    float* Ss = sm;                       // 4352 floats
    float* Al = sm + 4352;                // 64
    __half* Qh  = (__half*)(sm + 4416);   // 8704 halves
    __half* Ksh = Qh + 8704;              // 8704 halves
    __half* Ph  = Ksh + 8704;             // 4608 halves
    const uint32_t ksh_u32 = smem_u32(Ksh);

    const int tid = threadIdx.x;
    const int lane = tid & 31, wid = tid >> 5;
    const int g = lane >> 2, tq = lane & 3;
    const int qt = blockIdx.x;
    const int n = (blockIdx.y << 1) + parity;
    const int b = blockIdx.z >> 3, h = blockIdx.z & 7;
    const int base = n << 8, q0 = base + (qt << 6);
    const float* xb = x + (size_t)b * 4194304u + (h << 7);

#pragma unroll
    for (int it = 0; it < 8; ++it) {
        int i = tid + (it << 8);
        int r = i >> 5, c4 = (i & 31) << 2;
        float4 v = *(const float4*)(xb + (size_t)(q0 + r) * 1024u + c4);
        __half2 h0 = __floats2half2_rn(v.x, v.y);
        __half2 h1 = __floats2half2_rn(v.z, v.w);
        uint2 w; w.x = *(uint32_t*)&h0; w.y = *(uint32_t*)&h1;
        *(uint2*)&Qh[r * 136 + c4] = w;
    }

    const int wm = wid >> 1, wn = wid & 1;
    const int m0 = wm << 4;
    const int sn0 = wn << 5;
    const int on0 = wn << 6;
    const int srow = tid >> 2, seg = tid & 3;
    const int lrow = (lane & 15) * 136;
    const float scale = 0.08838834764831845f;

    float oacc[8][4];
#pragma unroll
    for (int nt = 0; nt < 8; ++nt)
#pragma unroll
        for (int e = 0; e < 4; ++e) oacc[nt][e] = 0.f;
    float m_i = -1e30f, l_i = 0.f;

    for (int kt = 0; kt < 8; ++kt) {
        __syncthreads();
        const int ktok = base + (kt << 6);
#pragma unroll
        for (int it = 0; it < 8; ++it) {
            int i = tid + (it << 8);
            int r = i >> 5, c4 = (i & 31) << 2;
            float4 v = *(const float4*)(xb + (size_t)(ktok + r) * 1024u + c4);
            __half2 h0 = __floats2half2_rn(v.x, v.y);
            __half2 h1 = __floats2half2_rn(v.z, v.w);
            uint2 w; w.x = *(uint32_t*)&h0; w.y = *(uint32_t*)&h1;
            *(uint2*)&Ksh[r * 136 + c4] = w;
        }
        __syncthreads();

        float sacc[4][4];
#pragma unroll
        for (int nt = 0; nt < 4; ++nt)
#pragma unroll
            for (int e = 0; e < 4; ++e) sacc[nt][e] = 0.f;
#pragma unroll
        for (int kd = 0; kd < 128; kd += 16) {
            uint32_t a[4];
            a[0] = *(const uint32_t*)&Qh[(m0 + g) * 136 + kd + (tq << 1)];
            a[1] = *(const uint32_t*)&Qh[(m0 + g + 8) * 136 + kd + (tq << 1)];
            a[2] = *(const uint32_t*)&Qh[(m0 + g) * 136 + kd + (tq << 1) + 8];
            a[3] = *(const uint32_t*)&Qh[(m0 + g + 8) * 136 + kd + (tq << 1) + 8];
#pragma unroll
            for (int nt = 0; nt < 4; ++nt) {
                int tcol = sn0 + (nt << 3) + g;
                uint32_t bb[2];
                bb[0] = *(const uint32_t*)&Ksh[tcol * 136 + kd + (tq << 1)];
                bb[1] = *(const uint32_t*)&Ksh[tcol * 136 + kd + (tq << 1) + 8];
                mma16h(sacc[nt], a, bb);
            }
        }
#pragma unroll
        for (int nt = 0; nt < 4; ++nt) {
            int nc = sn0 + (nt << 3) + (tq << 1);
            *(float2*)&Ss[(m0 + g) * 68 + nc] =
                make_float2(sacc[nt][0] * scale, sacc[nt][1] * scale);
            *(float2*)&Ss[(m0 + g + 8) * 68 + nc] =
                make_float2(sacc[nt][2] * scale, sacc[nt][3] * scale);
        }
        __syncthreads();

        {
            float* sr = &Ss[srow * 68 + (seg << 4)];
            float mt = -1e30f;
            float pv[16];
#pragma unroll
            for (int jj = 0; jj < 16; ++jj) { pv[jj] = sr[jj]; mt = fmaxf(mt, pv[jj]); }
            mt = fmaxf(mt, __shfl_xor_sync(0xffffffffu, mt, 1));
            mt = fmaxf(mt, __shfl_xor_sync(0xffffffffu, mt, 2));
            float m_new = fmaxf(m_i, mt);
            float alpha = __expf(m_i - m_new);
            float ls = 0.f;
#pragma unroll
            for (int jj = 0; jj < 16; ++jj) {
                pv[jj] = __expf(pv[jj] - m_new);
                ls += pv[jj];
            }
            __half* pr = &Ph[srow * 72 + (seg << 4)];
#pragma unroll
            for (int j2 = 0; j2 < 8; ++j2) {
                __half2 hp = __floats2half2_rn(pv[j2 << 1], pv[(j2 << 1) + 1]);
                *(__half2*)&pr[j2 << 1] = hp;
            }
            ls += __shfl_xor_sync(0xffffffffu, ls, 1);
            ls += __shfl_xor_sync(0xffffffffu, ls, 2);
            l_i = l_i * alpha + ls;
            m_i = m_new;
            if (seg == 0) Al[srow] = alpha;
        }
        __syncthreads();

        float aLo = Al[m0 + g], aHi = Al[m0 + g + 8];
#pragma unroll
        for (int nt = 0; nt < 8; ++nt) {
            oacc[nt][0] *= aLo; oacc[nt][1] *= aLo;
            oacc[nt][2] *= aHi; oacc[nt][3] *= aHi;
        }
#pragma unroll
        for (int kd = 0; kd < 64; kd += 16) {
            uint32_t a[4];
            a[0] = *(const uint32_t*)&Ph[(m0 + g) * 72 + kd + (tq << 1)];
            a[1] = *(const uint32_t*)&Ph[(m0 + g + 8) * 72 + kd + (tq << 1)];
            a[2] = *(const uint32_t*)&Ph[(m0 + g) * 72 + kd + (tq << 1) + 8];
            a[3] = *(const uint32_t*)&Ph[(m0 + g + 8) * 72 + kd + (tq << 1) + 8];
            uint32_t rowa = ksh_u32 + (uint32_t)(((kd * 136) + lrow) << 1);
#pragma unroll
            for (int nt = 0; nt < 8; ++nt) {
                uint32_t bb[2];
                uint32_t addr = rowa + (uint32_t)((on0 + (nt << 3)) << 1);
                LDSM_X2_TRANS(bb[0], bb[1], addr);
                mma16h(oacc[nt], a, bb);
            }
        }
    }
    __syncthreads();
    if (seg == 0) Al[srow] = 1.0f / l_i;
    __syncthreads();

    const int iwLo = (qt << 6) + m0 + g;
    const int iwHi = iwLo + 8;
    const int sLo = base + iwLo, sHi = base + iwHi;
    const float triLo = 0.5f + (float)iwLo * (1.0f / 511.0f);
    const float triHi = 0.5f + (float)iwHi * (1.0f / 511.0f);
    const size_t offLo = ((size_t)b * 4096u + sLo) * 1024u + (h << 7);
    const size_t offHi = offLo + (size_t)8 * 1024u;
    float* dLo = L + offLo;
    float* dHi = L + offHi;
    __half* eLo = Lh + offLo;
    __half* eHi = Lh + offHi;
    if (parity == 0) {
        const bool snLo = (sLo < 256) || (sLo >= 3840);
        const bool snHi = (sHi < 256) || (sHi >= 3840);
        const float twLo = (snLo ? 1.0f : triLo) * Al[m0 + g];
        const float twHi = (snHi ? 1.0f : triHi) * Al[m0 + g + 8];
#pragma unroll
        for (int nt = 0; nt < 8; ++nt) {
            int dc = on0 + (nt << 3) + (tq << 1);
            float2 o = make_float2(oacc[nt][0] * twLo, oacc[nt][1] * twLo);
            float2 p = make_float2(oacc[nt][2] * twHi, oacc[nt][3] * twHi);
            *(float2*)(dLo + dc) = o;
            *(float2*)(dHi + dc) = p;
            if (snLo) { __half2 hh = __floats2half2_rn(o.x, o.y); *(__half2*)(eLo + dc) = hh; }
            if (snHi) { __half2 hh = __floats2half2_rn(p.x, p.y); *(__half2*)(eHi + dc) = hh; }
        }
    } else {
        const float twLo = triLo * Al[m0 + g];
        const float twHi = triHi * Al[m0 + g + 8];
        const float ivLo = invden(sLo), ivHi = invden(sHi);
#pragma unroll
        for (int nt = 0; nt < 8; ++nt) {
            int dc = on0 + (nt << 3) + (tq << 1);
            float2 o = *(float2*)(dLo + dc);
            o.x = (o.x + oacc[nt][0] * twLo) * ivLo;
            o.y = (o.y + oacc[nt][1] * twLo) * ivLo;
            *(float2*)(dLo + dc) = o;
            __half2 ho = __floats2half2_rn(o.x, o.y);
            *(__half2*)(eLo + dc) = ho;
            float2 p = *(float2*)(dHi + dc);
            p.x = (p.x + oacc[nt][2] * twHi) * ivHi;
            p.y = (p.y + oacc[nt][3] * twHi) * ivHi;
            *(float2*)(dHi + dc) = p;
            __half2 hp = __floats2half2_rn(p.x, p.y);
            *(__half2*)(eHi + dc) = hp;
        }
    }
}

// ============ 4) compressed-global attention (fp16 MMA; writes G & Gh) ============
__global__ void __launch_bounds__(256) gattn(
        const float* __restrict__ x, const float* __restrict__ gmem,
        const float* __restrict__ comp, float* __restrict__ G,
        __half* __restrict__ Gh) {
    extern __shared__ float sm[];
    float* Ps = sm;                        // 4224 floats
    __half* KVh = (__half*)(sm + 4224);    // 17408 halves
    __half* Qh  = KVh + 17408;             // 4352 halves
    __half* Ph  = Qh + 4352;               // 4352 halves
    const uint32_t kvh_u32 = smem_u32(KVh);

    const int tid = threadIdx.x;
    const int lane = tid & 31, wid = tid >> 5;
    const int g = lane >> 2, tq = lane & 3;
    const int s0 = blockIdx.x << 5, h = blockIdx.y, b = blockIdx.z;

#pragma unroll
    for (int it = 0; it < 16; ++it) {
        int i = tid + (it << 8);
        int r = i >> 5, c4 = (i & 31) << 2;
        float4 v;
        if (r < 64) v = *(const float4*)(comp + (size_t)((b << 6) + r) * 1024u + (h << 7) + c4);
        else        v = *(const float4*)(gmem + (size_t)((h << 6) + (r - 64)) * 128u + c4);
        __half2 h0 = __floats2half2_rn(v.x, v.y);
        __half2 h1 = __floats2half2_rn(v.z, v.w);
        uint2 w; w.x = *(uint32_t*)&h0; w.y = *(uint32_t*)&h1;
        *(uint2*)&KVh[r * 136 + c4] = w;
    }
#pragma unroll
    for (int it = 0; it < 4; ++it) {
        int i = tid + (it << 8);
        int r = i >> 5, c4 = (i & 31) << 2;
        float4 v = *(const float4*)(x + (size_t)b * 4194304u + (size_t)(s0 + r) * 1024u + (h << 7) + c4);
        __half2 h0 = __floats2half2_rn(v.x, v.y);
        __half2 h1 = __floats2half2_rn(v.z, v.w);
        uint2 w; w.x = *(uint32_t*)&h0; w.y = *(uint32_t*)&h1;
        *(uint2*)&Qh[r * 136 + c4] = w;
    }
    __syncthreads();

    const int wm = wid & 1, wn = wid >> 1;
    const int m0 = wm << 4;
    const int tn0 = wn << 5;
    const int lrow = (lane & 15) * 136;
    const float scale = 0.08838834764831845f;

    {
        float sacc[4][4];
#pragma unroll
        for (int nt = 0; nt < 4; ++nt)
#pragma unroll
            for (int e = 0; e < 4; ++e) sacc[nt][e] = 0.f;
#pragma unroll
        for (int kd = 0; kd < 128; kd += 16) {
            uint32_t a[4];
            a[0] = *(const uint32_t*)&Qh[(m0 + g) * 136 + kd + (tq << 1)];
            a[1] = *(const uint32_t*)&Qh[(m0 + g + 8) * 136 + kd + (tq << 1)];
            a[2] = *(const uint32_t*)&Qh[(m0 + g) * 136 + kd + (tq << 1) + 8];
            a[3] = *(const uint32_t*)&Qh[(m0 + g + 8) * 136 + kd + (tq << 1) + 8];
#pragma unroll
            for (int nt = 0; nt < 4; ++nt) {
                int tcol = tn0 + (nt << 3) + g;
                uint32_t bb[2];
                bb[0] = *(const uint32_t*)&KVh[tcol * 136 + kd + (tq << 1)];
                bb[1] = *(const uint32_t*)&KVh[tcol * 136 + kd + (tq << 1) + 8];
                mma16h(sacc[nt], a, bb);
            }
        }
#pragma unroll
        for (int nt = 0; nt < 4; ++nt) {
            int nc = tn0 + (nt << 3) + (tq << 1);
            *(float2*)&Ps[(m0 + g) * 132 + nc] =
                make_float2(sacc[nt][0] * scale, sacc[nt][1] * scale);
            *(float2*)&Ps[(m0 + g + 8) * 132 + nc] =
                make_float2(sacc[nt][2] * scale, sacc[nt][3] * scale);
        }
    }
    __syncthreads();

    {
        int row = tid >> 3, seg8 = tid & 7;
        float* pr = &Ps[row * 132 + (seg8 << 4)];
        float mt = -1e30f;
        float pv[16];
#pragma unroll
        for (int jj = 0; jj < 16; ++jj) { pv[jj] = pr[jj]; mt = fmaxf(mt, pv[jj]); }
        mt = fmaxf(mt, __shfl_xor_sync(0xffffffffu, mt, 1));
        mt = fmaxf(mt, __shfl_xor_sync(0xffffffffu, mt, 2));
        mt = fmaxf(mt, __shfl_xor_sync(0xffffffffu, mt, 4));
        float ssum = 0.f;
#pragma unroll
        for (int jj = 0; jj < 16; ++jj) { pv[jj] = __expf(pv[jj] - mt); ssum += pv[jj]; }
        ssum += __shfl_xor_sync(0xffffffffu, ssum, 1);
        ssum += __shfl_xor_sync(0xffffffffu, ssum, 2);
        ssum += __shfl_xor_sync(0xffffffffu, ssum, 4);
        float invs = 1.0f / ssum;
        __half* ph = &Ph[row * 136 + (seg8 << 4)];
#pragma unroll
        for (int j2 = 0; j2 < 8; ++j2) {
            __half2 hp = __floats2half2_rn(pv[j2 << 1] * invs, pv[(j2 << 1) + 1] * invs);
            *(__half2*)&ph[j2 << 1] = hp;
        }
    }
    __syncthreads();

    {
        float oacc[4][4];
#pragma unroll
        for (int nt = 0; nt < 4; ++nt)
#pragma unroll
            for (int e = 0; e < 4; ++e) oacc[nt][e] = 0.f;
#pragma unroll
        for (int kd = 0; kd < 128; kd += 16) {
            uint32_t a[4];
            a[0] = *(const uint32_t*)&Ph[(m0 + g) * 136 + kd + (tq << 1)];
            a[1] = *(const uint32_t*)&Ph[(m0 + g + 8) * 136 + kd + (tq << 1)];
            a[2] = *(const uint32_t*)&Ph[(m0 + g) * 136 + kd + (tq << 1) + 8];
            a[3] = *(const uint32_t*)&Ph[(m0 + g + 8) * 136 + kd + (tq << 1) + 8];
            uint32_t rowa = kvh_u32 + (uint32_t)(((kd * 136) + lrow) << 1);
#pragma unroll
            for (int nt = 0; nt < 4; ++nt) {
                uint32_t bb[2];
                uint32_t addr = rowa + (uint32_t)((tn0 + (nt << 3)) << 1);
                LDSM_X2_TRANS(bb[0], bb[1], addr);
                mma16h(oacc[nt], a, bb);
            }
        }
        const size_t offLo = ((size_t)b * 4096u + s0 + m0 + g) * 1024u + (h << 7);
        const size_t offHi = offLo + (size_t)8 * 1024u;
#pragma unroll
        for (int nt = 0; nt < 4; ++nt) {
            int nc = tn0 + (nt << 3) + (tq << 1);
            float2 o = make_float2(oacc[nt][0], oacc[nt][1]);
            float2 p = make_float2(oacc[nt][2], oacc[nt][3]);
            *(float2*)(G + offLo + nc) = o;
            *(float2*)(G + offHi + nc) = p;
            __half2 ho = __floats2half2_rn(o.x, o.y);
            __half2 hp = __floats2half2_rn(p.x, p.y);
            *(__half2*)(Gh + offLo + nc) = ho;
            *(__half2*)(Gh + offHi + nc) = hp;
        }
    }
}

// ============ 5+6) fp16 GEMM: 128x128 tile, m16n8k16, 3-stage cp.async ============
__global__ void __launch_bounds__(256) gemm_fp16(
        int mode, const __half* __restrict__ Ah0, const __half* __restrict__ Ah1,
        const float* __restrict__ Lf, const float* __restrict__ Gf,
        const float* __restrict__ BCp, const __half* __restrict__ WT,
        const float* __restrict__ bias, float* __restrict__ Cf,
        __half* __restrict__ Ch, int K) {
    extern __shared__ __half hsm[];
    const int tid = threadIdx.x;
    const int m0 = blockIdx.x << 7, n0 = blockIdx.y << 7;
    const int wid = tid >> 5, lane = tid & 31;
    const int quad = lane >> 2, tq = lane & 3;
    const int wm = wid >> 2, wn = wid & 3;
    const int arow = tid >> 1, aseg = (tid & 1) << 4;
    const uint32_t sbase = smem_u32(hsm);

    auto issue = [&](int kt, int slot) {
        uint32_t aoff = sbase + (uint32_t)(slot * 10240 + arow * 40 + aseg) * 2u;
        const __half* asrc = (mode == 1 && kt >= 1024)
            ? (Ah1 + (size_t)(m0 + arow) * 1024u + (kt - 1024) + aseg)
            : (Ah0 + (size_t)(m0 + arow) * 1024u + kt + aseg);
        CP16(aoff, asrc); CP16(aoff + 16, asrc + 8);
        uint32_t boff = sbase + (uint32_t)(slot * 10240 + 5120 + arow * 40 + aseg) * 2u;
        const __half* bsrc = WT + (size_t)(n0 + arow) * (size_t)K + kt + aseg;
        CP16(boff, bsrc); CP16(boff + 16, bsrc + 8);
        CPCOMMIT();
    };

    float acc[4][4][4];
#pragma unroll
    for (int i = 0; i < 4; ++i)
#pragma unroll
        for (int j = 0; j < 4; ++j)
#pragma unroll
            for (int e = 0; e < 4; ++e) acc[i][j][e] = 0.f;

    issue(0, 0);
    issue(32, 1);

    for (int kt = 0; kt < K; kt += 32) {
        CPWAIT1();
        __syncthreads();
        int nk = kt + 64;
        if (nk < K) issue(nk, ((kt >> 5) + 2) % 3);
        else        CPCOMMIT();

        const __half* Asb = hsm + ((kt >> 5) % 3) * 10240;
        const __half* Bsb = Asb + 5120;
#pragma unroll
        for (int ks = 0; ks < 2; ++ks) {
            const int k0 = ks << 4;
            uint32_t af[4][4], bf[4][2];
#pragma unroll
            for (int i = 0; i < 4; ++i) {
                int r = (wm << 6) + (i << 4) + quad;
                af[i][0] = *(const uint32_t*)&Asb[r * 40 + k0 + (tq << 1)];
                af[i][1] = *(const uint32_t*)&Asb[(r + 8) * 40 + k0 + (tq << 1)];
                af[i][2] = *(const uint32_t*)&Asb[r * 40 + k0 + (tq << 1) + 8];
                af[i][3] = *(const uint32_t*)&Asb[(r + 8) * 40 + k0 + (tq << 1) + 8];
            }
#pragma unroll
            for (int j = 0; j < 4; ++j) {
                int cidx = (wn << 5) + (j << 3) + quad;
                bf[j][0] = *(const uint32_t*)&Bsb[cidx * 40 + k0 + (tq << 1)];
                bf[j][1] = *(const uint32_t*)&Bsb[cidx * 40 + k0 + (tq << 1) + 8];
            }
#pragma unroll
            for (int i = 0; i < 4; ++i)
#pragma unroll
                for (int j = 0; j < 4; ++j) mma16h(acc[i][j], af[i], bf[j]);
        }
    }

#pragma unroll
    for (int i = 0; i < 4; ++i)
#pragma unroll
        for (int j = 0; j < 4; ++j) {
            int mr = m0 + (wm << 6) + (i << 4) + quad;
            int nc = n0 + (wn << 5) + (j << 3) + (tq << 1);
#pragma unroll
            for (int hf = 0; hf < 2; ++hf) {
                int m = mr + (hf << 3);
                size_t bix = (size_t)m * 1024u + nc;
#pragma unroll
                for (int e = 0; e < 2; ++e) {
                    float z = acc[i][j][(hf << 1) + e] + bias[nc + e];
                    if (mode == 1) {
                        float gg = 1.0f / (1.0f + __expf(-z));
                        float mval = gg * Lf[bix + e] + (1.0f - gg) * Gf[bix + e] + BCp[bix + e];
                        Ch[bix + e] = __float2half_rn(mval);
                    } else {
                        Cf[bix + e] = z;
                    }
                }
            }
        }
}

// =====================================================================
extern "C" void kernel_launch(void* const* d_in, const int* in_sizes, int n_in,
                              void* d_out, int out_size) {
    const float* x    = (const float*)d_in[0];
    const float* gmem = (const float*)d_in[1];
    const float* cw   = (const float*)d_in[2];
    const float* cb   = (const float*)d_in[3];
    const float* mw   = (const float*)d_in[4];
    const float* mb   = (const float*)d_in[5];
    const float* ow   = (const float*)d_in[6];
    const float* ob   = (const float*)d_in[7];
    float* out = (float*)d_out;

    float *pL, *pG, *pBC, *pCOMP, *pCP;
    __half *pXCh, *pCWh, *pLh, *pGh, *pMh, *pW1h, *pW2h;
    cudaGetSymbolAddress((void**)&pL,    g_L);
    cudaGetSymbolAddress((void**)&pG,    g_G);
    cudaGetSymbolAddress((void**)&pBC,   g_BC);
    cudaGetSymbolAddress((void**)&pCOMP, g_COMP);
    cudaGetSymbolAddress((void**)&pCP,   g_CP);
    cudaGetSymbolAddress((void**)&pXCh,  g_XCh);
    cudaGetSymbolAddress((void**)&pCWh,  g_CWh);
    cudaGetSymbolAddress((void**)&pLh,   g_Lh);
    cudaGetSymbolAddress((void**)&pGh,   g_Gh);
    cudaGetSymbolAddress((void**)&pMh,   g_Mh);
    cudaGetSymbolAddress((void**)&pW1h,  g_W1h);
    cudaGetSymbolAddress((void**)&pW2h,  g_W2h);

    static cudaStream_t s1 = nullptr, s2 = nullptr, s3 = nullptr;
    static cudaEvent_t evR = nullptr, ev1 = nullptr, ev2 = nullptr, ev3 = nullptr, evF = nullptr;
    if (s1 == nullptr) {
        cudaStreamCreateWithFlags(&s1, cudaStreamNonBlocking);
        cudaStreamCreateWithFlags(&s2, cudaStreamNonBlocking);
        cudaStreamCreateWithFlags(&s3, cudaStreamNonBlocking);
        cudaEventCreateWithFlags(&evR, cudaEventDisableTiming);
        cudaEventCreateWithFlags(&ev1, cudaEventDisableTiming);
        cudaEventCreateWithFlags(&ev2, cudaEventDisableTiming);
        cudaEventCreateWithFlags(&ev3, cudaEventDisableTiming);
        cudaEventCreateWithFlags(&evF, cudaEventDisableTiming);
    }

    const int BC_SMEM = 2 * 16384 * 4;
    const int WA_SMEM = 61696;
    const int GA_SMEM = 4224 * 4 + (17408 + 4352 + 4352) * 2;
    const int GH_SMEM = 3 * 10240 * 2;
    cudaFuncSetAttribute(bc_kernel,   cudaFuncAttributeMaxDynamicSharedMemorySize, BC_SMEM);
    cudaFuncSetAttribute(win_attn,    cudaFuncAttributeMaxDynamicSharedMemorySize, WA_SMEM);
    cudaFuncSetAttribute(gattn,       cudaFuncAttributeMaxDynamicSharedMemorySize, GA_SMEM);
    cudaFuncSetAttribute(gemm_fp16,   cudaFuncAttributeMaxDynamicSharedMemorySize, GH_SMEM);
    cudaFuncSetAttribute(conv_gemm_h, cudaFuncAttributeMaxDynamicSharedMemorySize, GH_SMEM);

    cudaEventRecord(evR, 0);
    cudaStreamWaitEvent(s1, evR, 0);
    cudaStreamWaitEvent(s2, evR, 0);
    cudaStreamWaitEvent(s3, evR, 0);

    wthalf      <<<dim3(64, 32), 256, 0, s1>>>(mw, pW1h, 2048);
    wthalf      <<<dim3(32, 32), 256, 0, s1>>>(ow, pW2h, 1024);
    bc_kernel   <<<dim3(256, 2), 512, BC_SMEM, s1>>>(x, pBC);

    tohalf      <<<2048, 256, 0, s2>>>(cw, pCWh);
    xch_kernel  <<<dim3(256, 2), 256, 0, s2>>>(x, pXCh);
    conv_gemm_h <<<dim3(8, 4), 256, GH_SMEM, s2>>>(pXCh, pCWh, pCP);
    conv_reduce <<<128, 256, 0, s2>>>(pCP, cb, pCOMP);
    gattn       <<<dim3(128, 8, 2), 256, GA_SMEM, s2>>>(x, gmem, pCOMP, pG, pGh);

    win_attn    <<<dim3(8, 8, 16), 256, WA_SMEM, s3>>>(x, pL, pLh, 0);
    win_attn    <<<dim3(8, 7, 16), 256, WA_SMEM, s3>>>(x, pL, pLh, 1);

    cudaEventRecord(ev1, s1);
    cudaEventRecord(ev2, s2);
    cudaEventRecord(ev3, s3);
    // join for both GEMM chains
    cudaStreamWaitEvent(0, ev1, 0);
    cudaStreamWaitEvent(0, ev2, 0);
    cudaStreamWaitEvent(0, ev3, 0);
    cudaStreamWaitEvent(s3, ev1, 0);
    cudaStreamWaitEvent(s3, ev2, 0);

    // chain A: m rows [0, 4096) on stream 0; chain B: [4096, 8192) on s3
    const size_t HO = (size_t)4096u * 1024u;
    gemm_fp16<<<dim3(32, 8), 256, GH_SMEM, 0>>>(
        1, pLh, pGh, pL, pG, pBC, pW1h, mb, out, pMh, 2048);
    gemm_fp16<<<dim3(32, 8), 256, GH_SMEM, 0>>>(
        0, pMh, pMh, pL, pG, pBC, pW2h, ob, out, pMh, 1024);

    gemm_fp16<<<dim3(32, 8), 256, GH_SMEM, s3>>>(
        1, pLh + HO, pGh + HO, pL + HO, pG + HO, pBC + HO, pW1h, mb, out + HO, pMh + HO, 2048);
    gemm_fp16<<<dim3(32, 8), 256, GH_SMEM, s3>>>(
        0, pMh + HO, pMh + HO, pL + HO, pG + HO, pBC + HO, pW2h, ob, out + HO, pMh + HO, 1024);

    cudaEventRecord(evF, s3);
    cudaStreamWaitEvent(0, evF, 0);
}

// round 17
// speedup vs baseline: 2.0315x; 1.0214x over previous
#include <cuda_runtime.h>
#include <cuda_fp16.h>
#include <math.h>
#include <stdint.h>

__device__ float g_L [2u*4096u*1024u];
__device__ float g_G [2u*4096u*1024u];
__device__ float g_BC[2u*4096u*1024u];
__device__ float g_COMP[2u*64u*1024u];
__device__ float g_CP[4u*128u*1024u];
__device__ __half g_XCh[128u*4096u];
__device__ __half g_CWh[1024u*4096u];
__device__ __half g_Lh[2u*4096u*1024u];
__device__ __half g_Gh[2u*4096u*1024u];
__device__ __half g_Mh[2u*4096u*1024u];
__device__ __half g_W1h[1024u*2048u];
__device__ __half g_W2h[1024u*1024u];

__device__ __forceinline__ void mma16h(float* c, const uint32_t* a, const uint32_t* b) {
    asm volatile("mma.sync.aligned.m16n8k16.row.col.f32.f16.f16.f32 "
        "{%0,%1,%2,%3}, {%4,%5,%6,%7}, {%8,%9}, {%0,%1,%2,%3};"
        : "+f"(c[0]), "+f"(c[1]), "+f"(c[2]), "+f"(c[3])
        : "r"(a[0]), "r"(a[1]), "r"(a[2]), "r"(a[3]), "r"(b[0]), "r"(b[1]));
}
#define LDSM_X2_TRANS(r0, r1, addr) \
    asm volatile("ldmatrix.sync.aligned.m8n8.x2.trans.shared.b16 {%0,%1}, [%2];" \
        : "=r"(r0), "=r"(r1) : "r"(addr))
__device__ __forceinline__ uint32_t smem_u32(const void* p) {
    uint32_t a;
    asm("{ .reg .u64 t; cvta.to.shared.u64 t, %1; cvt.u32.u64 %0, t; }" : "=r"(a) : "l"(p));
    return a;
}
#define CP16(dst, src) asm volatile("cp.async.cg.shared.global [%0], [%1], 16;" :: "r"(dst), "l"(src))
#define CPCOMMIT()     asm volatile("cp.async.commit_group;" ::: "memory")
#define CPWAIT1()      asm volatile("cp.async.wait_group 1;" ::: "memory")

// ============ 0a) weight transpose -> half ============
__global__ void wthalf(const float* __restrict__ W, __half* __restrict__ WT, int K) {
    __shared__ float tile[32][33];
    const int k0 = blockIdx.x << 5, n0 = blockIdx.y << 5;
    const int tx = threadIdx.x & 31, ty = threadIdx.x >> 5;
#pragma unroll
    for (int i = ty; i < 32; i += 8)
        tile[i][tx] = W[(size_t)(k0 + i) * 1024u + n0 + tx];
    __syncthreads();
#pragma unroll
    for (int i = ty; i < 32; i += 8)
        WT[(size_t)(n0 + i) * (size_t)K + k0 + tx] = __float2half_rn(tile[tx][i]);
}

// ============ 0b) fp32 -> fp16 convert ============
__global__ void tohalf(const float* __restrict__ S, __half* __restrict__ D) {
    size_t i = ((size_t)blockIdx.x * blockDim.x + threadIdx.x) << 3;
    float4 a = *(const float4*)(S + i);
    float4 b = *(const float4*)(S + i + 4);
    __half2 h0 = __floats2half2_rn(a.x, a.y);
    __half2 h1 = __floats2half2_rn(a.z, a.w);
    __half2 h2 = __floats2half2_rn(b.x, b.y);
    __half2 h3 = __floats2half2_rn(b.z, b.w);
    uint4 o;
    o.x = *(uint32_t*)&h0; o.y = *(uint32_t*)&h1;
    o.z = *(uint32_t*)&h2; o.w = *(uint32_t*)&h3;
    *(uint4*)(D + i) = o;
}

// ============ 1) broadcast diffusion ============
__global__ void bc_kernel(const float* __restrict__ x, float* __restrict__ bc) {
    extern __shared__ float sm[];
    const int tid = threadIdx.x, b = blockIdx.y, d0 = blockIdx.x << 2;
    float* bufA = sm; float* bufB = sm + 16384;
    const float* src = x + (size_t)b * 4194304u + d0;
    float reg[8][4];
#pragma unroll
    for (int q = 0; q < 8; ++q) {
        int s = tid + (q << 9);
        float4 v = *(const float4*)(src + (size_t)s * 1024u);
        bufA[s] = v.x; bufA[4096 + s] = v.y; bufA[8192 + s] = v.z; bufA[12288 + s] = v.w;
        reg[q][0] = v.x; reg[q][1] = v.y; reg[q][2] = v.z; reg[q][3] = v.w;
    }
    __syncthreads();
    float acc[32];
#pragma unroll
    for (int e = 0; e < 32; ++e) acc[e] = 0.f;
    float* cur = bufA; float* nxt = bufB;
    for (int st = 1; st < 4096; st <<= 1) {
#pragma unroll
        for (int q = 0; q < 8; ++q) {
            int s = tid + (q << 9);
            int sm1 = (s - st) & 4095, sp1 = (s + st) & 4095;
#pragma unroll
            for (int j = 0; j < 4; ++j) {
                const float* cj = cur + (j << 12);
                float v = reg[q][j] + 0.5f * (cj[sm1] + cj[sp1]);
                nxt[(j << 12) + s] = v;
                reg[q][j] = v;
                acc[(q << 2) + j] += v;
            }
        }
        __syncthreads();
        float* t = cur; cur = nxt; nxt = t;
    }
    const float inv = 1.0f / 13.0f;
    float* dst = bc + (size_t)b * 4194304u + d0;
#pragma unroll
    for (int q = 0; q < 8; ++q) {
        int s = tid + (q << 9);
        *(float4*)(dst + (size_t)s * 1024u) =
            make_float4(acc[q*4]*inv, acc[q*4+1]*inv, acc[q*4+2]*inv, acc[q*4+3]*inv);
    }
}

// ============ 2a) conv input gather -> half ============
__global__ void xch_kernel(const float* __restrict__ x, __half* __restrict__ Xch) {
    const int s = blockIdx.x;
    const int b = blockIdx.y;
    const int t = s >> 2, j = s & 3;
    const int m = (b << 6) + t;
    const float* src = x + (size_t)b * 4194304u + (size_t)s * 1024u;
    __half* dst = Xch + (size_t)m * 4096u + j;
#pragma unroll
    for (int k = 0; k < 4; ++k) {
        int d = threadIdx.x + (k << 8);
        dst[d << 2] = __float2half_rn(src[d]);
    }
}

// ============ 2b) conv GEMM fp16 (split-K x4) ============
__global__ void __launch_bounds__(256) conv_gemm_h(
        const __half* __restrict__ Xch, const __half* __restrict__ CWh,
        float* __restrict__ CP) {
    extern __shared__ __half hsm[];
    const int tid = threadIdx.x;
    const int n0 = blockIdx.x << 7;
    const int kq = blockIdx.y;
    const int kbase = kq << 10;
    const int wid = tid >> 5, lane = tid & 31;
    const int quad = lane >> 2, tq = lane & 3;
    const int wm = wid >> 2, wn = wid & 3;
    const int arow = tid >> 1, aseg = (tid & 1) << 4;
    const uint32_t sbase = smem_u32(hsm);

    auto issue = [&](int kt, int slot) {
        uint32_t aoff = sbase + (uint32_t)(slot * 10240 + arow * 40 + aseg) * 2u;
        const __half* asrc = Xch + (size_t)arow * 4096u + kbase + kt + aseg;
        CP16(aoff, asrc); CP16(aoff + 16, asrc + 8);
        uint32_t boff = sbase + (uint32_t)(slot * 10240 + 5120 + arow * 40 + aseg) * 2u;
        const __half* bsrc = CWh + (size_t)(n0 + arow) * 4096u + kbase + kt + aseg;
        CP16(boff, bsrc); CP16(boff + 16, bsrc + 8);
        CPCOMMIT();
    };

    float acc[4][4][4];
#pragma unroll
    for (int i = 0; i < 4; ++i)
#pragma unroll
        for (int j = 0; j < 4; ++j)
#pragma unroll
            for (int e = 0; e < 4; ++e) acc[i][j][e] = 0.f;

    issue(0, 0);
    issue(32, 1);

    for (int kt = 0; kt < 1024; kt += 32) {
        CPWAIT1();
        __syncthreads();
        int nk = kt + 64;
        if (nk < 1024) issue(nk, ((kt >> 5) + 2) % 3);
        else           CPCOMMIT();

        const __half* Asb = hsm + ((kt >> 5) % 3) * 10240;
        const __half* Bsb = Asb + 5120;
#pragma unroll
        for (int ks = 0; ks < 2; ++ks) {
            const int k0 = ks << 4;
            uint32_t af[4][4], bf[4][2];
#pragma unroll
            for (int i = 0; i < 4; ++i) {
                int r = (wm << 6) + (i << 4) + quad;
                af[i][0] = *(const uint32_t*)&Asb[r * 40 + k0 + (tq << 1)];
                af[i][1] = *(const uint32_t*)&Asb[(r + 8) * 40 + k0 + (tq << 1)];
                af[i][2] = *(const uint32_t*)&Asb[r * 40 + k0 + (tq << 1) + 8];
                af[i][3] = *(const uint32_t*)&Asb[(r + 8) * 40 + k0 + (tq << 1) + 8];
            }
#pragma unroll
            for (int j = 0; j < 4; ++j) {
                int cidx = (wn << 5) + (j << 3) + quad;
                bf[j][0] = *(const uint32_t*)&Bsb[cidx * 40 + k0 + (tq << 1)];
                bf[j][1] = *(const uint32_t*)&Bsb[cidx * 40 + k0 + (tq << 1) + 8];
            }
#pragma unroll
            for (int i = 0; i < 4; ++i)
#pragma unroll
                for (int j = 0; j < 4; ++j) mma16h(acc[i][j], af[i], bf[j]);
        }
    }
    float* cp = CP + (size_t)kq * 131072u;
#pragma unroll
    for (int i = 0; i < 4; ++i)
#pragma unroll
        for (int j = 0; j < 4; ++j) {
            int mr = (wm << 6) + (i << 4) + quad;
            int nc = n0 + (wn << 5) + (j << 3) + (tq << 1);
#pragma unroll
            for (int hf = 0; hf < 2; ++hf) {
                int m = mr + (hf << 3);
                *(float2*)(cp + (size_t)m * 1024u + nc) =
                    make_float2(acc[i][j][(hf << 1)], acc[i][j][(hf << 1) + 1]);
            }
        }
}

// ============ 2c) conv reduce ============
__global__ void conv_reduce(const float* __restrict__ CP, const float* __restrict__ cb,
                            float* __restrict__ comp) {
    int i = (blockIdx.x << 8) + threadIdx.x;
    int o4 = (i & 255) << 2;
    float4 a = *(const float4*)(CP + ((size_t)i << 2));
    float4 b = *(const float4*)(CP + 131072u + ((size_t)i << 2));
    float4 c = *(const float4*)(CP + 262144u + ((size_t)i << 2));
    float4 d = *(const float4*)(CP + 393216u + ((size_t)i << 2));
    float4 e = *(const float4*)(cb + o4);
    *(float4*)(comp + ((size_t)i << 2)) = make_float4(
        a.x + b.x + c.x + d.x + e.x, a.y + b.y + c.y + d.y + e.y,
        a.z + b.z + c.z + d.z + e.z, a.w + b.w + c.w + d.w + e.w);
}

// ============ 3) dual-window sliding attention (fused, fp16 MMA) ============
// CTA = one 64-query tile; walks union KV of its <=2 covering windows with
// two flash states; scores+AV MMA done ONCE per KV tile.
__global__ void __launch_bounds__(256) win_attn2(
        const float* __restrict__ x, float* __restrict__ L,
        __half* __restrict__ Lh) {
    extern __shared__ float sm[];
    float* Ss  = sm;                      // 64*68 = 4352
    float* AlA = sm + 4352;               // 64
    float* AlB = sm + 4416;               // 64
    float* FBs = sm + 4480;               // 64
    float* LAs = sm + 4544;               // 64
    float* LBs = sm + 4608;               // 64
    __half* Qh  = (__half*)(sm + 4672);   // 8704 halves
    __half* Ksh = Qh + 8704;              // 8704 halves
    __half* Ph  = Ksh + 8704;             // 4608 halves
    const uint32_t ksh_u32 = smem_u32(Ksh);

    const int tid = threadIdx.x;
    const int lane = tid & 31, wid = tid >> 5;
    const int g = lane >> 2, tq = lane & 3;
    const int qt = blockIdx.x;            // 0..63
    const int h = blockIdx.y, b = blockIdx.z;
    const int p = qt >> 2;                // segment 0..15
    const bool hasA = (p >= 1), hasB = (p <= 14);
    const int q0 = qt << 6;
    const float* xb = x + (size_t)b * 4194304u + (h << 7);

    // load Q -> half
#pragma unroll
    for (int it = 0; it < 8; ++it) {
        int i = tid + (it << 8);
        int r = i >> 5, c4 = (i & 31) << 2;
        float4 v = *(const float4*)(xb + (size_t)(q0 + r) * 1024u + c4);
        __half2 h0 = __floats2half2_rn(v.x, v.y);
        __half2 h1 = __floats2half2_rn(v.z, v.w);
        uint2 w; w.x = *(uint32_t*)&h0; w.y = *(uint32_t*)&h1;
        *(uint2*)&Qh[r * 136 + c4] = w;
    }

    const int wm = wid >> 1, wn = wid & 1;
    const int m0 = wm << 4;
    const int sn0 = wn << 5;
    const int on0 = wn << 6;
    const int srow = tid >> 2, seg = tid & 3;
    const int lrow = (lane & 15) * 136;
    const float scale = 0.08838834764831845f;

    float accA[8][4], accB[8][4];
#pragma unroll
    for (int nt = 0; nt < 8; ++nt)
#pragma unroll
        for (int e = 0; e < 4; ++e) { accA[nt][e] = 0.f; accB[nt][e] = 0.f; }
    float mA = -1e30f, lA = 0.f, mB = -1e30f, lB = 0.f;

    const int t0 = (p == 0) ? 0 : ((p << 2) - 4);
    const int t1 = (p == 15) ? 64 : ((p << 2) + 8);

    for (int t = t0; t < t1; ++t) {
        const bool inA = hasA && (t < (p << 2) + 4);     // t >= 4p-4 by loop bound
        const bool inB = hasB && (t >= (p << 2));
        __syncthreads();
        const int ktok = t << 6;
#pragma unroll
        for (int it = 0; it < 8; ++it) {
            int i = tid + (it << 8);
            int r = i >> 5, c4 = (i & 31) << 2;
            float4 v = *(const float4*)(xb + (size_t)(ktok + r) * 1024u + c4);
            __half2 h0 = __floats2half2_rn(v.x, v.y);
            __half2 h1 = __floats2half2_rn(v.z, v.w);
            uint2 w; w.x = *(uint32_t*)&h0; w.y = *(uint32_t*)&h1;
            *(uint2*)&Ksh[r * 136 + c4] = w;
        }
        __syncthreads();

        // scores S(64x64) once
        float sacc[4][4];
#pragma unroll
        for (int nt = 0; nt < 4; ++nt)
#pragma unroll
            for (int e = 0; e < 4; ++e) sacc[nt][e] = 0.f;
#pragma unroll
        for (int kd = 0; kd < 128; kd += 16) {
            uint32_t a[4];
            a[0] = *(const uint32_t*)&Qh[(m0 + g) * 136 + kd + (tq << 1)];
            a[1] = *(const uint32_t*)&Qh[(m0 + g + 8) * 136 + kd + (tq << 1)];
            a[2] = *(const uint32_t*)&Qh[(m0 + g) * 136 + kd + (tq << 1) + 8];
            a[3] = *(const uint32_t*)&Qh[(m0 + g + 8) * 136 + kd + (tq << 1) + 8];
#pragma unroll
            for (int nt = 0; nt < 4; ++nt) {
                int tcol = sn0 + (nt << 3) + g;
                uint32_t bb[2];
                bb[0] = *(const uint32_t*)&Ksh[tcol * 136 + kd + (tq << 1)];
                bb[1] = *(const uint32_t*)&Ksh[tcol * 136 + kd + (tq << 1) + 8];
                mma16h(sacc[nt], a, bb);
            }
        }
#pragma unroll
        for (int nt = 0; nt < 4; ++nt) {
            int nc = sn0 + (nt << 3) + (tq << 1);
            *(float2*)&Ss[(m0 + g) * 68 + nc] =
                make_float2(sacc[nt][0] * scale, sacc[nt][1] * scale);
            *(float2*)&Ss[(m0 + g + 8) * 68 + nc] =
                make_float2(sacc[nt][2] * scale, sacc[nt][3] * scale);
        }
        __syncthreads();

        // dual-state online softmax; exp once, P referenced to (A if inA else B)
        {
            float* sr = &Ss[srow * 68 + (seg << 4)];
            float tmax = -1e30f;
            float pv[16];
#pragma unroll
            for (int jj = 0; jj < 16; ++jj) { pv[jj] = sr[jj]; tmax = fmaxf(tmax, pv[jj]); }
            tmax = fmaxf(tmax, __shfl_xor_sync(0xffffffffu, tmax, 1));
            tmax = fmaxf(tmax, __shfl_xor_sync(0xffffffffu, tmax, 2));
            float alphaA = 1.f, alphaB = 1.f;
            if (inA) { float mn = fmaxf(mA, tmax); alphaA = __expf(mA - mn); mA = mn; }
            if (inB) { float mn = fmaxf(mB, tmax); alphaB = __expf(mB - mn); mB = mn; }
            float mref = inA ? mA : mB;
            float ls = 0.f;
#pragma unroll
            for (int jj = 0; jj < 16; ++jj) {
                pv[jj] = __expf(pv[jj] - mref);
                ls += pv[jj];
            }
            __half* pr = &Ph[srow * 72 + (seg << 4)];
#pragma unroll
            for (int j2 = 0; j2 < 8; ++j2) {
                __half2 hp = __floats2half2_rn(pv[j2 << 1], pv[(j2 << 1) + 1]);
                *(__half2*)&pr[j2 << 1] = hp;
            }
            ls += __shfl_xor_sync(0xffffffffu, ls, 1);
            ls += __shfl_xor_sync(0xffffffffu, ls, 2);
            float fB = inB ? __expf(mref - mB) : 0.f;
            if (inA) lA = lA * alphaA + ls;
            lB = lB * alphaB + fB * ls;
            if (seg == 0) { AlA[srow] = alphaA; AlB[srow] = alphaB; FBs[srow] = fB; }
        }
        __syncthreads();

        // AV once into ot, merged into accA / accB
        float ot[8][4];
#pragma unroll
        for (int nt = 0; nt < 8; ++nt)
#pragma unroll
            for (int e = 0; e < 4; ++e) ot[nt][e] = 0.f;
#pragma unroll
        for (int kd = 0; kd < 64; kd += 16) {
            uint32_t a[4];
            a[0] = *(const uint32_t*)&Ph[(m0 + g) * 72 + kd + (tq << 1)];
            a[1] = *(const uint32_t*)&Ph[(m0 + g + 8) * 72 + kd + (tq << 1)];
            a[2] = *(const uint32_t*)&Ph[(m0 + g) * 72 + kd + (tq << 1) + 8];
            a[3] = *(const uint32_t*)&Ph[(m0 + g + 8) * 72 + kd + (tq << 1) + 8];
            uint32_t rowa = ksh_u32 + (uint32_t)(((kd * 136) + lrow) << 1);
#pragma unroll
            for (int nt = 0; nt < 8; ++nt) {
                uint32_t bb[2];
                uint32_t addr = rowa + (uint32_t)((on0 + (nt << 3)) << 1);
                LDSM_X2_TRANS(bb[0], bb[1], addr);
                mma16h(ot[nt], a, bb);
            }
        }
        float aAlo = AlA[m0 + g], aAhi = AlA[m0 + g + 8];
        float aBlo = AlB[m0 + g], aBhi = AlB[m0 + g + 8];
        float fblo = FBs[m0 + g], fbhi = FBs[m0 + g + 8];
        if (inA) {
#pragma unroll
            for (int nt = 0; nt < 8; ++nt) {
                accA[nt][0] = accA[nt][0] * aAlo + ot[nt][0];
                accA[nt][1] = accA[nt][1] * aAlo + ot[nt][1];
                accA[nt][2] = accA[nt][2] * aAhi + ot[nt][2];
                accA[nt][3] = accA[nt][3] * aAhi + ot[nt][3];
            }
        }
        if (inB) {
#pragma unroll
            for (int nt = 0; nt < 8; ++nt) {
                accB[nt][0] = accB[nt][0] * aBlo + fblo * ot[nt][0];
                accB[nt][1] = accB[nt][1] * aBlo + fblo * ot[nt][1];
                accB[nt][2] = accB[nt][2] * aBhi + fbhi * ot[nt][2];
                accB[nt][3] = accB[nt][3] * aBhi + fbhi * ot[nt][3];
            }
        }
    }
    __syncthreads();
    if (seg == 0) {
        LAs[srow] = hasA ? (1.0f / lA) : 0.f;
        LBs[srow] = hasB ? (1.0f / lB) : 0.f;
    }
    __syncthreads();

    // output: tri-weighted, invden-normalized
    const int rLo = m0 + g, rHi = rLo + 8;
    const int ibLo = (q0 + rLo) & 255, ibHi = ibLo + 8;
    const float triBLo = 0.5f + (float)ibLo * (1.0f / 511.0f);
    const float triBHi = 0.5f + (float)ibHi * (1.0f / 511.0f);
    const float triALo = 0.5f + (float)(ibLo + 256) * (1.0f / 511.0f);
    const float triAHi = 0.5f + (float)(ibHi + 256) * (1.0f / 511.0f);
    const float wALo = hasA ? triALo : 0.f, wBLo = hasB ? triBLo : 0.f;
    const float wAHi = hasA ? triAHi : 0.f, wBHi = hasB ? triBHi : 0.f;
    const float ivLo = 1.0f / (wALo + wBLo);
    const float ivHi = 1.0f / (wAHi + wBHi);
    const float cALo = wALo * ivLo * LAs[rLo];
    const float cBLo = wBLo * ivLo * LBs[rLo];
    const float cAHi = wAHi * ivHi * LAs[rHi];
    const float cBHi = wBHi * ivHi * LBs[rHi];

    const size_t offLo = ((size_t)b * 4096u + q0 + rLo) * 1024u + (h << 7);
    const size_t offHi = offLo + (size_t)8 * 1024u;
#pragma unroll
    for (int nt = 0; nt < 8; ++nt) {
        int dc = on0 + (nt << 3) + (tq << 1);
        float2 o = make_float2(accA[nt][0] * cALo + accB[nt][0] * cBLo,
                               accA[nt][1] * cALo + accB[nt][1] * cBLo);
        float2 q = make_float2(accA[nt][2] * cAHi + accB[nt][2] * cBHi,
                               accA[nt][3] * cAHi + accB[nt][3] * cBHi);
        *(float2*)(L + offLo + dc) = o;
        *(float2*)(L + offHi + dc) = q;
        __half2 ho = __floats2half2_rn(o.x, o.y);
        __half2 hq = __floats2half2_rn(q.x, q.y);
        *(__half2*)(Lh + offLo + dc) = ho;
        *(__half2*)(Lh + offHi + dc) = hq;
    }
}

// ============ 4) compressed-global attention (fp16 MMA; writes G & Gh) ============
__global__ void __launch_bounds__(256) gattn(
        const float* __restrict__ x, const float* __restrict__ gmem,
        const float* __restrict__ comp, float* __restrict__ G,
        __half* __restrict__ Gh) {
    extern __shared__ float sm[];
    float* Ps = sm;
    __half* KVh = (__half*)(sm + 4224);
    __half* Qh  = KVh + 17408;
    __half* Ph  = Qh + 4352;
    const uint32_t kvh_u32 = smem_u32(KVh);

    const int tid = threadIdx.x;
    const int lane = tid & 31, wid = tid >> 5;
    const int g = lane >> 2, tq = lane & 3;
    const int s0 = blockIdx.x << 5, h = blockIdx.y, b = blockIdx.z;

#pragma unroll
    for (int it = 0; it < 16; ++it) {
        int i = tid + (it << 8);
        int r = i >> 5, c4 = (i & 31) << 2;
        float4 v;
        if (r < 64) v = *(const float4*)(comp + (size_t)((b << 6) + r) * 1024u + (h << 7) + c4);
        else        v = *(const float4*)(gmem + (size_t)((h << 6) + (r - 64)) * 128u + c4);
        __half2 h0 = __floats2half2_rn(v.x, v.y);
        __half2 h1 = __floats2half2_rn(v.z, v.w);
        uint2 w; w.x = *(uint32_t*)&h0; w.y = *(uint32_t*)&h1;
        *(uint2*)&KVh[r * 136 + c4] = w;
    }
#pragma unroll
    for (int it = 0; it < 4; ++it) {
        int i = tid + (it << 8);
        int r = i >> 5, c4 = (i & 31) << 2;
        float4 v = *(const float4*)(x + (size_t)b * 4194304u + (size_t)(s0 + r) * 1024u + (h << 7) + c4);
        __half2 h0 = __floats2half2_rn(v.x, v.y);
        __half2 h1 = __floats2half2_rn(v.z, v.w);
        uint2 w; w.x = *(uint32_t*)&h0; w.y = *(uint32_t*)&h1;
        *(uint2*)&Qh[r * 136 + c4] = w;
    }
    __syncthreads();

    const int wm = wid & 1, wn = wid >> 1;
    const int m0 = wm << 4;
    const int tn0 = wn << 5;
    const int lrow = (lane & 15) * 136;
    const float scale = 0.08838834764831845f;

    {
        float sacc[4][4];
#pragma unroll
        for (int nt = 0; nt < 4; ++nt)
#pragma unroll
            for (int e = 0; e < 4; ++e) sacc[nt][e] = 0.f;
#pragma unroll
        for (int kd = 0; kd < 128; kd += 16) {
            uint32_t a[4];
            a[0] = *(const uint32_t*)&Qh[(m0 + g) * 136 + kd + (tq << 1)];
            a[1] = *(const uint32_t*)&Qh[(m0 + g + 8) * 136 + kd + (tq << 1)];
            a[2] = *(const uint32_t*)&Qh[(m0 + g) * 136 + kd + (tq << 1) + 8];
            a[3] = *(const uint32_t*)&Qh[(m0 + g + 8) * 136 + kd + (tq << 1) + 8];
#pragma unroll
            for (int nt = 0; nt < 4; ++nt) {
                int tcol = tn0 + (nt << 3) + g;
                uint32_t bb[2];
                bb[0] = *(const uint32_t*)&KVh[tcol * 136 + kd + (tq << 1)];
                bb[1] = *(const uint32_t*)&KVh[tcol * 136 + kd + (tq << 1) + 8];
                mma16h(sacc[nt], a, bb);
            }
        }
#pragma unroll
        for (int nt = 0; nt < 4; ++nt) {
            int nc = tn0 + (nt << 3) + (tq << 1);
            *(float2*)&Ps[(m0 + g) * 132 + nc] =
                make_float2(sacc[nt][0] * scale, sacc[nt][1] * scale);
            *(float2*)&Ps[(m0 + g + 8) * 132 + nc] =
                make_float2(sacc[nt][2] * scale, sacc[nt][3] * scale);
        }
    }
    __syncthreads();

    {
        int row = tid >> 3, seg8 = tid & 7;
        float* pr = &Ps[row * 132 + (seg8 << 4)];
        float mt = -1e30f;
        float pv[16];
#pragma unroll
        for (int jj = 0; jj < 16; ++jj) { pv[jj] = pr[jj]; mt = fmaxf(mt, pv[jj]); }
        mt = fmaxf(mt, __shfl_xor_sync(0xffffffffu, mt, 1));
        mt = fmaxf(mt, __shfl_xor_sync(0xffffffffu, mt, 2));
        mt = fmaxf(mt, __shfl_xor_sync(0xffffffffu, mt, 4));
        float ssum = 0.f;
#pragma unroll
        for (int jj = 0; jj < 16; ++jj) { pv[jj] = __expf(pv[jj] - mt); ssum += pv[jj]; }
        ssum += __shfl_xor_sync(0xffffffffu, ssum, 1);
        ssum += __shfl_xor_sync(0xffffffffu, ssum, 2);
        ssum += __shfl_xor_sync(0xffffffffu, ssum, 4);
        float invs = 1.0f / ssum;
        __half* ph = &Ph[row * 136 + (seg8 << 4)];
#pragma unroll
        for (int j2 = 0; j2 < 8; ++j2) {
            __half2 hp = __floats2half2_rn(pv[j2 << 1] * invs, pv[(j2 << 1) + 1] * invs);
            *(__half2*)&ph[j2 << 1] = hp;
        }
    }
    __syncthreads();

    {
        float oacc[4][4];
#pragma unroll
        for (int nt = 0; nt < 4; ++nt)
#pragma unroll
            for (int e = 0; e < 4; ++e) oacc[nt][e] = 0.f;
#pragma unroll
        for (int kd = 0; kd < 128; kd += 16) {
            uint32_t a[4];
            a[0] = *(const uint32_t*)&Ph[(m0 + g) * 136 + kd + (tq << 1)];
            a[1] = *(const uint32_t*)&Ph[(m0 + g + 8) * 136 + kd + (tq << 1)];
            a[2] = *(const uint32_t*)&Ph[(m0 + g) * 136 + kd + (tq << 1) + 8];
            a[3] = *(const uint32_t*)&Ph[(m0 + g + 8) * 136 + kd + (tq << 1) + 8];
            uint32_t rowa = kvh_u32 + (uint32_t)(((kd * 136) + lrow) << 1);
#pragma unroll
            for (int nt = 0; nt < 4; ++nt) {
                uint32_t bb[2];
                uint32_t addr = rowa + (uint32_t)((tn0 + (nt << 3)) << 1);
                LDSM_X2_TRANS(bb[0], bb[1], addr);
                mma16h(oacc[nt], a, bb);
            }
        }
        const size_t offLo = ((size_t)b * 4096u + s0 + m0 + g) * 1024u + (h << 7);
        const size_t offHi = offLo + (size_t)8 * 1024u;
#pragma unroll
        for (int nt = 0; nt < 4; ++nt) {
            int nc = tn0 + (nt << 3) + (tq << 1);
            float2 o = make_float2(oacc[nt][0], oacc[nt][1]);
            float2 p = make_float2(oacc[nt][2], oacc[nt][3]);
            *(float2*)(G + offLo + nc) = o;
            *(float2*)(G + offHi + nc) = p;
            __half2 ho = __floats2half2_rn(o.x, o.y);
            __half2 hp = __floats2half2_rn(p.x, p.y);
            *(__half2*)(Gh + offLo + nc) = ho;
            *(__half2*)(Gh + offHi + nc) = hp;
        }
    }
}

// ============ 5+6) fp16 GEMM: 128x128 tile, m16n8k16, 3-stage cp.async ============
__global__ void __launch_bounds__(256) gemm_fp16(
        int mode, const __half* __restrict__ Ah0, const __half* __restrict__ Ah1,
        const float* __restrict__ Lf, const float* __restrict__ Gf,
        const float* __restrict__ BCp, const __half* __restrict__ WT,
        const float* __restrict__ bias, float* __restrict__ Cf,
        __half* __restrict__ Ch, int K) {
    extern __shared__ __half hsm[];
    const int tid = threadIdx.x;
    const int m0 = blockIdx.x << 7, n0 = blockIdx.y << 7;
    const int wid = tid >> 5, lane = tid & 31;
    const int quad = lane >> 2, tq = lane & 3;
    const int wm = wid >> 2, wn = wid & 3;
    const int arow = tid >> 1, aseg = (tid & 1) << 4;
    const uint32_t sbase = smem_u32(hsm);

    auto issue = [&](int kt, int slot) {
        uint32_t aoff = sbase + (uint32_t)(slot * 10240 + arow * 40 + aseg) * 2u;
        const __half* asrc = (mode == 1 && kt >= 1024)
            ? (Ah1 + (size_t)(m0 + arow) * 1024u + (kt - 1024) + aseg)
            : (Ah0 + (size_t)(m0 + arow) * 1024u + kt + aseg);
        CP16(aoff, asrc); CP16(aoff + 16, asrc + 8);
        uint32_t boff = sbase + (uint32_t)(slot * 10240 + 5120 + arow * 40 + aseg) * 2u;
        const __half* bsrc = WT + (size_t)(n0 + arow) * (size_t)K + kt + aseg;
        CP16(boff, bsrc); CP16(boff + 16, bsrc + 8);
        CPCOMMIT();
    };

    float acc[4][4][4];
#pragma unroll
    for (int i = 0; i < 4; ++i)
#pragma unroll
        for (int j = 0; j < 4; ++j)
#pragma unroll
            for (int e = 0; e < 4; ++e) acc[i][j][e] = 0.f;

    issue(0, 0);
    issue(32, 1);

    for (int kt = 0; kt < K; kt += 32) {
        CPWAIT1();
        __syncthreads();
        int nk = kt + 64;
        if (nk < K) issue(nk, ((kt >> 5) + 2) % 3);
        else        CPCOMMIT();

        const __half* Asb = hsm + ((kt >> 5) % 3) * 10240;
        const __half* Bsb = Asb + 5120;
#pragma unroll
        for (int ks = 0; ks < 2; ++ks) {
            const int k0 = ks << 4;
            uint32_t af[4][4], bf[4][2];
#pragma unroll
            for (int i = 0; i < 4; ++i) {
                int r = (wm << 6) + (i << 4) + quad;
                af[i][0] = *(const uint32_t*)&Asb[r * 40 + k0 + (tq << 1)];
                af[i][1] = *(const uint32_t*)&Asb[(r + 8) * 40 + k0 + (tq << 1)];
                af[i][2] = *(const uint32_t*)&Asb[r * 40 + k0 + (tq << 1) + 8];
                af[i][3] = *(const uint32_t*)&Asb[(r + 8) * 40 + k0 + (tq << 1) + 8];
            }
#pragma unroll
            for (int j = 0; j < 4; ++j) {
                int cidx = (wn << 5) + (j << 3) + quad;
                bf[j][0] = *(const uint32_t*)&Bsb[cidx * 40 + k0 + (tq << 1)];
                bf[j][1] = *(const uint32_t*)&Bsb[cidx * 40 + k0 + (tq << 1) + 8];
            }
#pragma unroll
            for (int i = 0; i < 4; ++i)
#pragma unroll
                for (int j = 0; j < 4; ++j) mma16h(acc[i][j], af[i], bf[j]);
        }
    }

#pragma unroll
    for (int i = 0; i < 4; ++i)
#pragma unroll
        for (int j = 0; j < 4; ++j) {
            int mr = m0 + (wm << 6) + (i << 4) + quad;
            int nc = n0 + (wn << 5) + (j << 3) + (tq << 1);
#pragma unroll
            for (int hf = 0; hf < 2; ++hf) {
                int m = mr + (hf << 3);
                size_t bix = (size_t)m * 1024u + nc;
#pragma unroll
                for (int e = 0; e < 2; ++e) {
                    float z = acc[i][j][(hf << 1) + e] + bias[nc + e];
                    if (mode == 1) {
                        float gg = 1.0f / (1.0f + __expf(-z));
                        float mval = gg * Lf[bix + e] + (1.0f - gg) * Gf[bix + e] + BCp[bix + e];
                        Ch[bix + e] = __float2half_rn(mval);
                    } else {
                        Cf[bix + e] = z;
                    }
                }
            }
        }
}

// =====================================================================
extern "C" void kernel_launch(void* const* d_in, const int* in_sizes, int n_in,
                              void* d_out, int out_size) {
    const float* x    = (const float*)d_in[0];
    const float* gmem = (const float*)d_in[1];
    const float* cw   = (const float*)d_in[2];
    const float* cb   = (const float*)d_in[3];
    const float* mw   = (const float*)d_in[4];
    const float* mb   = (const float*)d_in[5];
    const float* ow   = (const float*)d_in[6];
    const float* ob   = (const float*)d_in[7];
    float* out = (float*)d_out;

    float *pL, *pG, *pBC, *pCOMP, *pCP;
    __half *pXCh, *pCWh, *pLh, *pGh, *pMh, *pW1h, *pW2h;
    cudaGetSymbolAddress((void**)&pL,    g_L);
    cudaGetSymbolAddress((void**)&pG,    g_G);
    cudaGetSymbolAddress((void**)&pBC,   g_BC);
    cudaGetSymbolAddress((void**)&pCOMP, g_COMP);
    cudaGetSymbolAddress((void**)&pCP,   g_CP);
    cudaGetSymbolAddress((void**)&pXCh,  g_XCh);
    cudaGetSymbolAddress((void**)&pCWh,  g_CWh);
    cudaGetSymbolAddress((void**)&pLh,   g_Lh);
    cudaGetSymbolAddress((void**)&pGh,   g_Gh);
    cudaGetSymbolAddress((void**)&pMh,   g_Mh);
    cudaGetSymbolAddress((void**)&pW1h,  g_W1h);
    cudaGetSymbolAddress((void**)&pW2h,  g_W2h);

    static cudaStream_t s1 = nullptr, s2 = nullptr, s3 = nullptr;
    static cudaEvent_t evR = nullptr, ev1 = nullptr, ev2 = nullptr, ev3 = nullptr, evF = nullptr;
    if (s1 == nullptr) {
        cudaStreamCreateWithFlags(&s1, cudaStreamNonBlocking);
        cudaStreamCreateWithFlags(&s2, cudaStreamNonBlocking);
        cudaStreamCreateWithFlags(&s3, cudaStreamNonBlocking);
        cudaEventCreateWithFlags(&evR, cudaEventDisableTiming);
        cudaEventCreateWithFlags(&ev1, cudaEventDisableTiming);
        cudaEventCreateWithFlags(&ev2, cudaEventDisableTiming);
        cudaEventCreateWithFlags(&ev3, cudaEventDisableTiming);
        cudaEventCreateWithFlags(&evF, cudaEventDisableTiming);
    }

    const int BC_SMEM = 2 * 16384 * 4;
    const int WA_SMEM = 4672 * 4 + (8704 + 8704 + 4608) * 2;   // 62720 B
    const int GA_SMEM = 4224 * 4 + (17408 + 4352 + 4352) * 2;
    const int GH_SMEM = 3 * 10240 * 2;
    cudaFuncSetAttribute(bc_kernel,   cudaFuncAttributeMaxDynamicSharedMemorySize, BC_SMEM);
    cudaFuncSetAttribute(win_attn2,   cudaFuncAttributeMaxDynamicSharedMemorySize, WA_SMEM);
    cudaFuncSetAttribute(gattn,       cudaFuncAttributeMaxDynamicSharedMemorySize, GA_SMEM);
    cudaFuncSetAttribute(gemm_fp16,   cudaFuncAttributeMaxDynamicSharedMemorySize, GH_SMEM);
    cudaFuncSetAttribute(conv_gemm_h, cudaFuncAttributeMaxDynamicSharedMemorySize, GH_SMEM);

    cudaEventRecord(evR, 0);
    cudaStreamWaitEvent(s1, evR, 0);
    cudaStreamWaitEvent(s2, evR, 0);
    cudaStreamWaitEvent(s3, evR, 0);

    wthalf      <<<dim3(64, 32), 256, 0, s1>>>(mw, pW1h, 2048);
    wthalf      <<<dim3(32, 32), 256, 0, s1>>>(ow, pW2h, 1024);
    bc_kernel   <<<dim3(256, 2), 512, BC_SMEM, s1>>>(x, pBC);

    tohalf      <<<2048, 256, 0, s2>>>(cw, pCWh);
    xch_kernel  <<<dim3(256, 2), 256, 0, s2>>>(x, pXCh);
    conv_gemm_h <<<dim3(8, 4), 256, GH_SMEM, s2>>>(pXCh, pCWh, pCP);
    conv_reduce <<<128, 256, 0, s2>>>(pCP, cb, pCOMP);
    gattn       <<<dim3(128, 8, 2), 256, GA_SMEM, s2>>>(x, gmem, pCOMP, pG, pGh);

    win_attn2   <<<dim3(64, 8, 2), 256, WA_SMEM, s3>>>(x, pL, pLh);

    cudaEventRecord(ev1, s1);
    cudaEventRecord(ev2, s2);
    cudaEventRecord(ev3, s3);
    cudaStreamWaitEvent(0, ev1, 0);
    cudaStreamWaitEvent(0, ev2, 0);
    cudaStreamWaitEvent(0, ev3, 0);
    cudaStreamWaitEvent(s3, ev1, 0);
    cudaStreamWaitEvent(s3, ev2, 0);

    const size_t HO = (size_t)4096u * 1024u;
    gemm_fp16<<<dim3(32, 8), 256, GH_SMEM, 0>>>(
        1, pLh, pGh, pL, pG, pBC, pW1h, mb, out, pMh, 2048);
    gemm_fp16<<<dim3(32, 8), 256, GH_SMEM, 0>>>(
        0, pMh, pMh, pL, pG, pBC, pW2h, ob, out, pMh, 1024);

    gemm_fp16<<<dim3(32, 8), 256, GH_SMEM, s3>>>(
        1, pLh + HO, pGh + HO, pL + HO, pG + HO, pBC + HO, pW1h, mb, out + HO, pMh + HO, 2048);
    gemm_fp16<<<dim3(32, 8), 256, GH_SMEM, s3>>>(
        0, pMh + HO, pMh + HO, pL + HO, pG + HO, pBC + HO, pW2h, ob, out + HO, pMh + HO, 1024);

    cudaEventRecord(evF, s3);
    cudaStreamWaitEvent(0, evF, 0);
}